// round 1
// baseline (speedup 1.0000x reference)
#include <cuda_runtime.h>
#include <math.h>

// Problem constants
#define VV   32000
#define DD   768
#define HH   12
#define KVH_ 4
#define LL   6
#define TT   1024
#define HD_  64
#define KVD_ 256
#define BB   2
#define BT   2048      // B*T
#define FF   3072      // 4*D

// ---------------- scratch (device globals: no allocation allowed) ------------
__device__ float g_x [BT*DD];
__device__ float g_x0[BT*DD];
__device__ float g_xn[BT*DD];
__device__ float g_q [BT*DD];
__device__ float g_k [BT*KVD_];
__device__ float g_v [BT*KVD_];
__device__ float g_y [BT*DD];
__device__ float g_h [BT*FF];

// ---------------- fused embedding + rmsnorm ---------------------------------
__global__ void embed_norm_kernel(const float* __restrict__ wte,
                                  const int* __restrict__ idx,
                                  float* __restrict__ x, float* __restrict__ x0) {
    int t = blockIdx.x;
    const float* row = wte + (long)idx[t] * DD;
    int tid = threadIdx.x;
    float s = 0.f;
    for (int i = tid; i < DD; i += 256) { float v = row[i]; s += v * v; }
    __shared__ float red[256];
    red[tid] = s; __syncthreads();
    for (int o = 128; o; o >>= 1) { if (tid < o) red[tid] += red[tid + o]; __syncthreads(); }
    float inv = rsqrtf(red[0] * (1.0f / DD) + 1e-6f);
    for (int i = tid; i < DD; i += 256) {
        float v = row[i] * inv;
        x[(long)t * DD + i]  = v;
        x0[(long)t * DD + i] = v;
    }
}

// ---------------- rmsnorm ----------------------------------------------------
__global__ void rmsnorm_kernel(const float* __restrict__ src, float* __restrict__ dst) {
    int t = blockIdx.x;
    const float* xp = src + (long)t * DD;
    int tid = threadIdx.x;
    float s = 0.f;
    for (int i = tid; i < DD; i += 256) { float v = xp[i]; s += v * v; }
    __shared__ float red[256];
    red[tid] = s; __syncthreads();
    for (int o = 128; o; o >>= 1) { if (tid < o) red[tid] += red[tid + o]; __syncthreads(); }
    float inv = rsqrtf(red[0] * (1.0f / DD) + 1e-6f);
    for (int i = tid; i < DD; i += 256) dst[(long)t * DD + i] = xp[i] * inv;
}

// ---------------- residual lambdas: x = rl*x + xl*x0 -------------------------
__global__ void resid_kernel(float* __restrict__ x, const float* __restrict__ x0,
                             const float* __restrict__ rl, const float* __restrict__ xl,
                             int layer) {
    long i = (long)blockIdx.x * blockDim.x + threadIdx.x;
    float a = rl[layer], b = xl[layer];
    x[i] = a * x[i] + b * x0[i];
}

// ---------------- value-embedding gate add ----------------------------------
__global__ void ve_kernel(const float* __restrict__ xn, float* __restrict__ v,
                          const int* __restrict__ idx,
                          const float* __restrict__ ve_table,
                          const float* __restrict__ ve_gate) {
    int tok  = blockIdx.x;
    int tid  = threadIdx.x;           // 128
    int warp = tid >> 5, lane = tid & 31;
    __shared__ float gates[KVH_];
    // warp w computes gate for kv-head w: 2*sigmoid( xn[tok,0:32] . gate[w,0:32] )
    float g = xn[(long)tok * DD + lane] * ve_gate[warp * 32 + lane];
    #pragma unroll
    for (int o = 16; o; o >>= 1) g += __shfl_down_sync(0xffffffffu, g, o);
    if (lane == 0) gates[warp] = 2.0f / (1.0f + expf(-g));
    __syncthreads();
    const float* vt = ve_table + (long)idx[tok] * KVD_;
    for (int i = tid; i < KVD_; i += 128)
        v[(long)tok * KVD_ + i] += gates[i >> 6] * vt[i];
}

// ---------------- fused rope + per-head rmsnorm (q and k) -------------------
__global__ void ropenorm_kernel(float* __restrict__ q, float* __restrict__ k) {
    int bid = blockIdx.x;
    int hh  = bid & 15;               // 0..11 -> q heads, 12..15 -> k heads
    int tok = bid >> 4;
    int t   = tok % TT;               // position
    float* ptr = (hh < HH) ? (q + (long)tok * DD + hh * HD_)
                           : (k + (long)tok * KVD_ + (hh - HH) * HD_);
    int d = threadIdx.x;              // 64
    __shared__ float sv[HD_];
    __shared__ float red[HD_];
    sv[d] = ptr[d];
    __syncthreads();
    int j = d & 31;
    float ex   = (float)(2 * j) * (1.0f / 64.0f);
    float invf = 1.0f / powf(10000.0f, ex);
    float ang  = (float)t * invf;
    float cv = cosf(ang), sn = sinf(ang);
    float x1 = sv[j], x2 = sv[j + 32];
    float r = (d < 32) ? (x1 * cv + x2 * sn) : (x2 * cv - x1 * sn);
    red[d] = r * r; __syncthreads();
    for (int o = 32; o; o >>= 1) { if (d < o) red[d] += red[d + o]; __syncthreads(); }
    float inv = rsqrtf(red[0] * (1.0f / HD_) + 1e-6f);
    ptr[d] = r * inv;
}

// ---------------- windowed attention: one block per (b,h,q) -----------------
__global__ void attn_kernel(const float* __restrict__ q, const float* __restrict__ k,
                            const float* __restrict__ v, float* __restrict__ y, int win) {
    int bid = blockIdx.x;
    int t = bid % TT;
    int h = (bid / TT) % HH;
    int b = bid / (TT * HH);
    int kh = h / (HH / KVH_);
    int kv0 = t - win + 1; if (kv0 < 0) kv0 = 0;
    int nk = t - kv0 + 1;
    int d = threadIdx.x;              // 64
    __shared__ float sq[HD_];
    __shared__ float sc[TT];
    __shared__ float red[HD_];
    long tok = (long)b * TT + t;
    sq[d] = q[tok * DD + h * HD_ + d];
    __syncthreads();
    long kbase = (long)b * TT * KVD_ + kh * HD_;
    for (int jj = d; jj < nk; jj += HD_) {
        const float* kp = k + kbase + (long)(kv0 + jj) * KVD_;
        float s = 0.f;
        #pragma unroll
        for (int e = 0; e < HD_; e += 4) {
            float4 k4 = *reinterpret_cast<const float4*>(kp + e);
            s += sq[e] * k4.x + sq[e + 1] * k4.y + sq[e + 2] * k4.z + sq[e + 3] * k4.w;
        }
        sc[jj] = s * 0.125f;          // 1/sqrt(64)
    }
    __syncthreads();
    float m = -INFINITY;
    for (int jj = d; jj < nk; jj += HD_) m = fmaxf(m, sc[jj]);
    red[d] = m; __syncthreads();
    for (int o = 32; o; o >>= 1) { if (d < o) red[d] = fmaxf(red[d], red[d + o]); __syncthreads(); }
    float M = red[0];
    __syncthreads();
    float se = 0.f;
    for (int jj = d; jj < nk; jj += HD_) { float p = expf(sc[jj] - M); sc[jj] = p; se += p; }
    red[d] = se; __syncthreads();
    for (int o = 32; o; o >>= 1) { if (d < o) red[d] += red[d + o]; __syncthreads(); }
    float inv = 1.0f / red[0];
    float acc = 0.f;
    const float* vp = v + kbase + (long)kv0 * KVD_ + d;
    for (int jj = 0; jj < nk; jj++) acc += sc[jj] * vp[(long)jj * KVD_];
    y[tok * DD + h * HD_ + d] = acc * inv;
}

// ---------------- generic NT GEMM: C[M,N] (+)= A[M,K] * B[N,K]^T ------------
// EPI: 0=store  1=accumulate  2=relu^2 store  3=softcap-tanh store
template <int EPI>
__global__ __launch_bounds__(256) void gemm_nt_kernel(
    const float* __restrict__ A, const float* __restrict__ Bm, float* __restrict__ C,
    int M, int N, int K) {
    __shared__ float As[16][65];
    __shared__ float Bs[16][65];
    int tid = threadIdx.x;
    int bm = blockIdx.y << 6, bn = blockIdx.x << 6;
    int tm = (tid >> 4) << 2, tn = (tid & 15) << 2;
    float acc[4][4] = {};
    const float* Ap = A + (long)bm * K;
    const float* Bp = Bm + (long)bn * K;
    for (int k0 = 0; k0 < K; k0 += 16) {
        #pragma unroll
        for (int jj = 0; jj < 4; jj++) {
            int id = tid + jj * 256;
            int r = id >> 4, c = id & 15;
            As[c][r] = Ap[(long)r * K + k0 + c];
            Bs[c][r] = Bp[(long)r * K + k0 + c];
        }
        __syncthreads();
        #pragma unroll
        for (int kk = 0; kk < 16; kk++) {
            float a0 = As[kk][tm], a1 = As[kk][tm + 1], a2 = As[kk][tm + 2], a3 = As[kk][tm + 3];
            float b0 = Bs[kk][tn], b1 = Bs[kk][tn + 1], b2 = Bs[kk][tn + 2], b3 = Bs[kk][tn + 3];
            acc[0][0] += a0 * b0; acc[0][1] += a0 * b1; acc[0][2] += a0 * b2; acc[0][3] += a0 * b3;
            acc[1][0] += a1 * b0; acc[1][1] += a1 * b1; acc[1][2] += a1 * b2; acc[1][3] += a1 * b3;
            acc[2][0] += a2 * b0; acc[2][1] += a2 * b1; acc[2][2] += a2 * b2; acc[2][3] += a2 * b3;
            acc[3][0] += a3 * b0; acc[3][1] += a3 * b1; acc[3][2] += a3 * b2; acc[3][3] += a3 * b3;
        }
        __syncthreads();
    }
    #pragma unroll
    for (int i = 0; i < 4; i++) {
        long crow = (long)(bm + tm + i) * N + bn + tn;
        #pragma unroll
        for (int j2 = 0; j2 < 4; j2++) {
            float val = acc[i][j2];
            if (EPI == 1)      C[crow + j2] += val;
            else if (EPI == 2) { float r = fmaxf(val, 0.f); C[crow + j2] = r * r; }
            else if (EPI == 3) C[crow + j2] = 15.0f * tanhf(val * (1.0f / 15.0f));
            else               C[crow + j2] = val;
        }
    }
}

// ---------------- orchestration ---------------------------------------------
extern "C" void kernel_launch(void* const* d_in, const int* in_sizes, int n_in,
                              void* d_out, int out_size) {
    const int*   idx  = (const int*)  d_in[0];
    const float* wte  = (const float*)d_in[1];
    const float* Wq   = (const float*)d_in[2];
    const float* Wk   = (const float*)d_in[3];
    const float* Wv   = (const float*)d_in[4];
    const float* Wo   = (const float*)d_in[5];
    const float* Wfc  = (const float*)d_in[6];
    const float* Wpr  = (const float*)d_in[7];
    const float* veT  = (const float*)d_in[8];
    const float* veG  = (const float*)d_in[9];
    const float* rl   = (const float*)d_in[10];
    const float* xl   = (const float*)d_in[11];
    const float* lm   = (const float*)d_in[12];
    float* out = (float*)d_out;

    float *x, *x0, *xn, *q, *k, *v, *y, *h;
    cudaGetSymbolAddress((void**)&x,  g_x);
    cudaGetSymbolAddress((void**)&x0, g_x0);
    cudaGetSymbolAddress((void**)&xn, g_xn);
    cudaGetSymbolAddress((void**)&q,  g_q);
    cudaGetSymbolAddress((void**)&k,  g_k);
    cudaGetSymbolAddress((void**)&v,  g_v);
    cudaGetSymbolAddress((void**)&y,  g_y);
    cudaGetSymbolAddress((void**)&h,  g_h);

    embed_norm_kernel<<<BT, 256>>>(wte, idx, x, x0);

    for (int i = 0; i < LL; i++) {
        resid_kernel<<<(BT * DD) / 1024, 1024>>>(x, x0, rl, xl, i);
        rmsnorm_kernel<<<BT, 256>>>(x, xn);

        gemm_nt_kernel<0><<<dim3(DD / 64,  BT / 64), 256>>>(xn, Wq + (long)i * DD * DD,   q, BT, DD,   DD);
        gemm_nt_kernel<0><<<dim3(KVD_ / 64, BT / 64), 256>>>(xn, Wk + (long)i * KVD_ * DD, k, BT, KVD_, DD);
        gemm_nt_kernel<0><<<dim3(KVD_ / 64, BT / 64), 256>>>(xn, Wv + (long)i * KVD_ * DD, v, BT, KVD_, DD);

        int j = (i == 1) ? 0 : (i == 3) ? 1 : (i == 5) ? 2 : -1;
        if (j >= 0)
            ve_kernel<<<BT, 128>>>(xn, v, idx, veT + (long)j * VV * KVD_, veG + j * KVH_ * 32);

        ropenorm_kernel<<<BT * 16, HD_>>>(q, k);

        int win = (i % 2 == 0) ? (TT / 2) : TT;
        attn_kernel<<<BB * HH * TT, HD_>>>(q, k, v, y, win);

        gemm_nt_kernel<1><<<dim3(DD / 64, BT / 64), 256>>>(y, Wo + (long)i * DD * DD, x, BT, DD, DD);

        rmsnorm_kernel<<<BT, 256>>>(x, xn);
        gemm_nt_kernel<2><<<dim3(FF / 64, BT / 64), 256>>>(xn, Wfc + (long)i * FF * DD, h, BT, FF, DD);
        gemm_nt_kernel<1><<<dim3(DD / 64, BT / 64), 256>>>(h,  Wpr + (long)i * DD * FF, x, BT, DD, FF);
    }

    rmsnorm_kernel<<<BT, 256>>>(x, xn);
    gemm_nt_kernel<3><<<dim3(VV / 64, BT / 64), 256>>>(xn, lm, out, BT, VV, DD);
}

// round 4
// speedup vs baseline: 2.1371x; 2.1371x over previous
#include <cuda_runtime.h>
#include <cuda_bf16.h>
#include <stdint.h>
#include <math.h>

#define VV   32000
#define DD   768
#define HH   12
#define KVH_ 4
#define LL   6
#define TT   1024
#define HD_  64
#define BB   2
#define BT   2048
#define FF   3072
#define QKVD 1280   // 768 q + 256 k + 256 v

typedef __nv_bfloat16 bf16;

// ---------------- device-global scratch -------------------------------------
__device__ float g_x  [BT*DD];
__device__ float g_x0 [BT*DD];
__device__ float g_qkv[BT*QKVD];

__device__ bf16 g_xn_h[BT*DD], g_xn_l[BT*DD];
__device__ bf16 g_y_h [BT*DD], g_y_l [BT*DD];
__device__ bf16 g_h_h [BT*FF], g_h_l [BT*FF];

__device__ bf16 g_wqkv_h[LL*QKVD*DD], g_wqkv_l[LL*QKVD*DD];
__device__ bf16 g_wo_h  [LL*DD*DD],   g_wo_l  [LL*DD*DD];
__device__ bf16 g_wfc_h [LL*FF*DD],   g_wfc_l [LL*FF*DD];
__device__ bf16 g_wpr_h [LL*DD*FF],   g_wpr_l [LL*DD*FF];
__device__ bf16 g_lm_h  [(long)VV*DD], g_lm_l [(long)VV*DD];

// ---------------- fp32 -> bf16 hi/lo conversion ------------------------------
__global__ void cvt_kernel(const float* __restrict__ in, bf16* __restrict__ h,
                           bf16* __restrict__ l, long n) {
    long i = (long)blockIdx.x * 256 + threadIdx.x;
    if (i >= n) return;
    float x = in[i];
    bf16 hi = __float2bfloat16(x);
    h[i] = hi;
    l[i] = __float2bfloat16(x - __bfloat162float(hi));
}

__global__ void cvt_qkv_kernel(const float* __restrict__ Wq, const float* __restrict__ Wk,
                               const float* __restrict__ Wv, bf16* __restrict__ h,
                               bf16* __restrict__ l) {
    long i = (long)blockIdx.x * 256 + threadIdx.x;
    long per = (long)QKVD * DD;
    if (i >= (long)LL * per) return;
    int layer = (int)(i / per);
    long rem = i % per;
    int row = (int)(rem / DD), col = (int)(rem % DD);
    float x;
    if (row < DD)            x = Wq[((long)layer*DD   + row)        * DD + col];
    else if (row < DD + 256) x = Wk[((long)layer*256  + row - DD)   * DD + col];
    else                     x = Wv[((long)layer*256  + row - 1024) * DD + col];
    bf16 hi = __float2bfloat16(x);
    h[i] = hi;
    l[i] = __float2bfloat16(x - __bfloat162float(hi));
}

// ---------------- fused embedding + rmsnorm ---------------------------------
__global__ void embed_norm_kernel(const float* __restrict__ wte,
                                  const int* __restrict__ idx,
                                  float* __restrict__ x, float* __restrict__ x0) {
    int t = blockIdx.x;
    const float* row = wte + (long)idx[t] * DD;
    int tid = threadIdx.x;
    float s = 0.f;
    for (int i = tid; i < DD; i += 256) { float v = row[i]; s += v * v; }
    __shared__ float red[256];
    red[tid] = s; __syncthreads();
    for (int o = 128; o; o >>= 1) { if (tid < o) red[tid] += red[tid + o]; __syncthreads(); }
    float inv = rsqrtf(red[0] * (1.0f / DD) + 1e-6f);
    for (int i = tid; i < DD; i += 256) {
        float v = row[i] * inv;
        x[(long)t * DD + i]  = v;
        x0[(long)t * DD + i] = v;
    }
}

// ---------------- rmsnorm (writes bf16 hi/lo) --------------------------------
__global__ void rmsnorm_kernel(const float* __restrict__ src,
                               bf16* __restrict__ oh, bf16* __restrict__ ol) {
    int t = blockIdx.x;
    const float* xp = src + (long)t * DD;
    int tid = threadIdx.x;
    float s = 0.f;
    for (int i = tid; i < DD; i += 256) { float v = xp[i]; s += v * v; }
    __shared__ float red[256];
    red[tid] = s; __syncthreads();
    for (int o = 128; o; o >>= 1) { if (tid < o) red[tid] += red[tid + o]; __syncthreads(); }
    float inv = rsqrtf(red[0] * (1.0f / DD) + 1e-6f);
    for (int i = tid; i < DD; i += 256) {
        float v = xp[i] * inv;
        bf16 hi = __float2bfloat16(v);
        oh[(long)t * DD + i] = hi;
        ol[(long)t * DD + i] = __float2bfloat16(v - __bfloat162float(hi));
    }
}

// ---------------- residual lambdas ------------------------------------------
__global__ void resid_kernel(float* __restrict__ x, const float* __restrict__ x0,
                             const float* __restrict__ rl, const float* __restrict__ xl,
                             int layer) {
    long i = (long)blockIdx.x * blockDim.x + threadIdx.x;
    float a = rl[layer], b = xl[layer];
    x[i] = a * x[i] + b * x0[i];
}

// ---------------- value-embedding gate add (v slice of qkv) ------------------
__global__ void ve_kernel(const bf16* __restrict__ xnh, const bf16* __restrict__ xnl,
                          float* __restrict__ qkv,
                          const int* __restrict__ idx,
                          const float* __restrict__ ve_table,
                          const float* __restrict__ ve_gate) {
    int tok  = blockIdx.x;
    int tid  = threadIdx.x;           // 128
    int warp = tid >> 5, lane = tid & 31;
    __shared__ float gates[KVH_];
    float xv = __bfloat162float(xnh[(long)tok * DD + lane]) +
               __bfloat162float(xnl[(long)tok * DD + lane]);
    float g = xv * ve_gate[warp * 32 + lane];
    #pragma unroll
    for (int o = 16; o; o >>= 1) g += __shfl_down_sync(0xffffffffu, g, o);
    if (lane == 0) gates[warp] = 2.0f / (1.0f + expf(-g));
    __syncthreads();
    const float* vt = ve_table + (long)idx[tok] * 256;
    float* v = qkv + (long)tok * QKVD + 1024;
    for (int i = tid; i < 256; i += 128)
        v[i] += gates[i >> 6] * vt[i];
}

// ---------------- fused rope + per-head rmsnorm (q and k in qkv) ------------
__global__ void ropenorm_kernel(float* __restrict__ qkv) {
    int bid = blockIdx.x;
    int hh  = bid & 15;               // 0..11 q heads, 12..15 k heads
    int tok = bid >> 4;
    int t   = tok % TT;
    float* ptr = qkv + (long)tok * QKVD + (hh < HH ? hh * HD_ : DD + (hh - HH) * HD_);
    int d = threadIdx.x;              // 64
    __shared__ float sv[HD_];
    __shared__ float red[HD_];
    sv[d] = ptr[d];
    __syncthreads();
    int j = d & 31;
    float invf = 1.0f / powf(10000.0f, (float)(2 * j) * (1.0f / 64.0f));
    float ang  = (float)t * invf;
    float cv = cosf(ang), sn = sinf(ang);
    float x1 = sv[j], x2 = sv[j + 32];
    float r = (d < 32) ? (x1 * cv + x2 * sn) : (x2 * cv - x1 * sn);
    red[d] = r * r; __syncthreads();
    for (int o = 32; o; o >>= 1) { if (d < o) red[d] += red[d + o]; __syncthreads(); }
    float inv = rsqrtf(red[0] * (1.0f / HD_) + 1e-6f);
    ptr[d] = r * inv;
}

// ---------------- tiled attention -------------------------------------------
// grid: (T/64, H, B), block 256. smem: Qs,Ks,Vs,Ss each [64][65] fp32 (dynamic).
__global__ __launch_bounds__(256) void attn_kernel(const float* __restrict__ qkv,
                                                   bf16* __restrict__ yh,
                                                   bf16* __restrict__ yl, int win) {
    extern __shared__ float asm_[];
    float* Qs = asm_;
    float* Ks = asm_ + 64 * 65;
    float* Vs = asm_ + 2 * 64 * 65;
    float* Ss = asm_ + 3 * 64 * 65;
    int qt = blockIdx.x, h = blockIdx.y, b = blockIdx.z;
    int kh = h / (HH / KVH_);
    int tid = threadIdx.x;
    int qrow = tid >> 2;
    int dseg = tid & 3;
    int q0 = qt * 64;

    for (int it = 0; it < 16; it++) {
        int id = tid + it * 256;
        int r = id >> 6, c = id & 63;
        Qs[r * 65 + c] = qkv[((long)(b * TT + q0 + r)) * QKVD + h * HD_ + c] * 0.125f;
    }

    float m = -1e30f, lsum = 0.f;
    float o[16];
    #pragma unroll
    for (int j2 = 0; j2 < 16; j2++) o[j2] = 0.f;

    int lo = q0 - win + 1;
    int kt0 = lo > 0 ? (lo >> 6) : 0;
    for (int kt = kt0; kt <= qt; kt++) {
        __syncthreads();
        for (int it = 0; it < 16; it++) {
            int id = tid + it * 256;
            int r = id >> 6, c = id & 63;
            long base = ((long)(b * TT + kt * 64 + r)) * QKVD;
            Ks[r * 65 + c] = qkv[base + DD   + kh * HD_ + c];
            Vs[r * 65 + c] = qkv[base + 1024 + kh * HD_ + c];
        }
        __syncthreads();

        float sv[16];
        #pragma unroll
        for (int j2 = 0; j2 < 16; j2++) {
            int k = dseg * 16 + j2;
            float s = 0.f;
            #pragma unroll
            for (int e = 0; e < 64; e++) s += Qs[qrow * 65 + e] * Ks[k * 65 + e];
            int diff = (q0 + qrow) - (kt * 64 + k);
            sv[j2] = (diff >= 0 && diff < win) ? s : -1e30f;
        }
        float mx = sv[0];
        #pragma unroll
        for (int j2 = 1; j2 < 16; j2++) mx = fmaxf(mx, sv[j2]);
        mx = fmaxf(mx, __shfl_xor_sync(0xffffffffu, mx, 1));
        mx = fmaxf(mx, __shfl_xor_sync(0xffffffffu, mx, 2));
        float mnew = fmaxf(m, mx);
        float f = __expf(m - mnew);
        float rs = 0.f;
        #pragma unroll
        for (int j2 = 0; j2 < 16; j2++) {
            float p = __expf(sv[j2] - mnew);
            Ss[qrow * 65 + dseg * 16 + j2] = p;
            rs += p;
        }
        rs += __shfl_xor_sync(0xffffffffu, rs, 1);
        rs += __shfl_xor_sync(0xffffffffu, rs, 2);
        lsum = lsum * f + rs;
        #pragma unroll
        for (int j2 = 0; j2 < 16; j2++) o[j2] *= f;
        m = mnew;
        __syncwarp();
        for (int k = 0; k < 64; k++) {
            float p = Ss[qrow * 65 + k];
            #pragma unroll
            for (int j2 = 0; j2 < 16; j2++)
                o[j2] += p * Vs[k * 65 + dseg * 16 + j2];
        }
    }
    float inv = 1.0f / lsum;
    long tok = (long)(b * TT + q0 + qrow);
    #pragma unroll
    for (int j2 = 0; j2 < 16; j2++) {
        float val = o[j2] * inv;
        long id = tok * DD + h * HD_ + dseg * 16 + j2;
        bf16 hi = __float2bfloat16(val);
        yh[id] = hi;
        yl[id] = __float2bfloat16(val - __bfloat162float(hi));
    }
}

// ---------------- bf16-split tensor-core NT GEMM ----------------------------
// C[M,N] (+)= A[M,K] * B[N,K]^T  using hi/lo bf16 decomposition (3 mma passes)
// EPI: 0=store f32  1=accumulate f32  2=relu^2 -> bf16 hi/lo  3=softcap f32
#define MMA_BF16(d, a0,a1,a2,a3, b0,b1) \
  asm volatile("mma.sync.aligned.m16n8k16.row.col.f32.bf16.bf16.f32 " \
    "{%0,%1,%2,%3},{%4,%5,%6,%7},{%8,%9},{%0,%1,%2,%3};\n" \
    : "+f"(d[0]),"+f"(d[1]),"+f"(d[2]),"+f"(d[3]) \
    : "r"(a0),"r"(a1),"r"(a2),"r"(a3),"r"(b0),"r"(b1))

template <int EPI>
__global__ __launch_bounds__(256, 1) void gemm_bb(
    const bf16* __restrict__ Ah, const bf16* __restrict__ Al,
    const bf16* __restrict__ Bh, const bf16* __restrict__ Bl,
    float* __restrict__ C, bf16* __restrict__ Ch, bf16* __restrict__ Cl,
    int M, int N, int K) {
    extern __shared__ bf16 sm[];
    // stage s (stride 20480 elems): A[hl][128][40] then B[hl][128][40]
    const int tid = threadIdx.x;
    const int wid = tid >> 5, lane = tid & 31;
    const int wm = wid & 3, wn = wid >> 2;
    const int bm = blockIdx.y << 7, bn = blockIdx.x << 7;

    float acc[2][8][4];
    #pragma unroll
    for (int i = 0; i < 2; i++)
        #pragma unroll
        for (int j = 0; j < 8; j++)
            #pragma unroll
            for (int e = 0; e < 4; e++) acc[i][j][e] = 0.f;

    const int nc = K >> 5;

    auto issue = [&](int c, int s) {
        int k0 = c << 5;
        #pragma unroll
        for (int it = 0; it < 4; it++) {
            int t = tid + it * 256;
            int hl = t >> 9, rem = t & 511, row = rem >> 2, seg = rem & 3;
            const bf16* g = (hl ? Al : Ah) + (long)(bm + row) * K + k0 + seg * 8;
            uint32_t sa = (uint32_t)__cvta_generic_to_shared(sm + s * 20480 + hl * 5120 + row * 40 + seg * 8);
            asm volatile("cp.async.cg.shared.global [%0],[%1],16;\n" :: "r"(sa), "l"(g));
        }
        #pragma unroll
        for (int it = 0; it < 4; it++) {
            int t = tid + it * 256;
            int hl = t >> 9, rem = t & 511, row = rem >> 2, seg = rem & 3;
            const bf16* g = (hl ? Bl : Bh) + (long)(bn + row) * K + k0 + seg * 8;
            uint32_t sa = (uint32_t)__cvta_generic_to_shared(sm + s * 20480 + 10240 + hl * 5120 + row * 40 + seg * 8);
            asm volatile("cp.async.cg.shared.global [%0],[%1],16;\n" :: "r"(sa), "l"(g));
        }
        asm volatile("cp.async.commit_group;\n");
    };

    issue(0, 0);
    for (int c = 0; c < nc; c++) {
        int s = c & 1;
        if (c + 1 < nc) {
            issue(c + 1, s ^ 1);
            asm volatile("cp.async.wait_group 1;\n");
        } else {
            asm volatile("cp.async.wait_group 0;\n");
        }
        __syncthreads();

        const bf16* As = sm + s * 20480;
        const bf16* Bs = sm + s * 20480 + 10240;
        #pragma unroll
        for (int kk = 0; kk < 2; kk++) {
            uint32_t a[2][2][4];
            #pragma unroll
            for (int i = 0; i < 2; i++)
                #pragma unroll
                for (int hl = 0; hl < 2; hl++) {
                    uint32_t addr = (uint32_t)__cvta_generic_to_shared(
                        As + hl * 5120 + (wm * 32 + i * 16 + (lane & 15)) * 40 + kk * 16 + (lane >> 4) * 8);
                    asm volatile("ldmatrix.sync.aligned.m8n8.x4.shared.b16 {%0,%1,%2,%3},[%4];\n"
                        : "=r"(a[i][hl][0]), "=r"(a[i][hl][1]), "=r"(a[i][hl][2]), "=r"(a[i][hl][3])
                        : "r"(addr));
                }
            uint32_t bfr[4][2][4];
            #pragma unroll
            for (int p2 = 0; p2 < 4; p2++)
                #pragma unroll
                for (int hl = 0; hl < 2; hl++) {
                    int row = wn * 64 + p2 * 16 + (lane & 7) + ((lane >> 4) & 1) * 8;
                    int col = kk * 16 + ((lane >> 3) & 1) * 8;
                    uint32_t addr = (uint32_t)__cvta_generic_to_shared(Bs + hl * 5120 + row * 40 + col);
                    asm volatile("ldmatrix.sync.aligned.m8n8.x4.shared.b16 {%0,%1,%2,%3},[%4];\n"
                        : "=r"(bfr[p2][hl][0]), "=r"(bfr[p2][hl][1]), "=r"(bfr[p2][hl][2]), "=r"(bfr[p2][hl][3])
                        : "r"(addr));
                }
            #pragma unroll
            for (int i = 0; i < 2; i++)
                #pragma unroll
                for (int j = 0; j < 8; j++) {
                    int p2 = j >> 1, half = j & 1;
                    uint32_t bh0 = bfr[p2][0][half * 2], bh1 = bfr[p2][0][half * 2 + 1];
                    uint32_t bl0 = bfr[p2][1][half * 2], bl1 = bfr[p2][1][half * 2 + 1];
                    MMA_BF16(acc[i][j], a[i][0][0], a[i][0][1], a[i][0][2], a[i][0][3], bh0, bh1);
                    MMA_BF16(acc[i][j], a[i][0][0], a[i][0][1], a[i][0][2], a[i][0][3], bl0, bl1);
                    MMA_BF16(acc[i][j], a[i][1][0], a[i][1][1], a[i][1][2], a[i][1][3], bh0, bh1);
                }
        }
        __syncthreads();
    }

    // epilogue
    #pragma unroll
    for (int i = 0; i < 2; i++) {
        int r0 = bm + wm * 32 + i * 16 + (lane >> 2);
        #pragma unroll
        for (int j = 0; j < 8; j++) {
            int col = bn + wn * 64 + j * 8 + (lane & 3) * 2;
            #pragma unroll
            for (int e = 0; e < 4; e++) {
                int rr = r0 + (e >> 1) * 8;
                int cc = col + (e & 1);
                long id = (long)rr * N + cc;
                float val = acc[i][j][e];
                if (EPI == 0)      C[id] = val;
                else if (EPI == 1) C[id] += val;
                else if (EPI == 2) {
                    float r = fmaxf(val, 0.f); r = r * r;
                    bf16 hi = __float2bfloat16(r);
                    Ch[id] = hi;
                    Cl[id] = __float2bfloat16(r - __bfloat162float(hi));
                }
                else C[id] = 15.0f * tanhf(val * (1.0f / 15.0f));
            }
        }
    }
}

// ---------------- orchestration ---------------------------------------------
extern "C" void kernel_launch(void* const* d_in, const int* in_sizes, int n_in,
                              void* d_out, int out_size) {
    const int*   idx  = (const int*)  d_in[0];
    const float* wte  = (const float*)d_in[1];
    const float* Wq   = (const float*)d_in[2];
    const float* Wk   = (const float*)d_in[3];
    const float* Wv   = (const float*)d_in[4];
    const float* Wo   = (const float*)d_in[5];
    const float* Wfc  = (const float*)d_in[6];
    const float* Wpr  = (const float*)d_in[7];
    const float* veT  = (const float*)d_in[8];
    const float* veG  = (const float*)d_in[9];
    const float* rl   = (const float*)d_in[10];
    const float* xl   = (const float*)d_in[11];
    const float* lm   = (const float*)d_in[12];
    float* out = (float*)d_out;

    float *x, *x0, *qkv;
    bf16 *xnh, *xnl, *yh, *yl, *hh, *hl;
    bf16 *wqkvh, *wqkvl, *woh, *wol, *wfch, *wfcl, *wprh, *wprl, *lmh, *lml;
    cudaGetSymbolAddress((void**)&x,   g_x);
    cudaGetSymbolAddress((void**)&x0,  g_x0);
    cudaGetSymbolAddress((void**)&qkv, g_qkv);
    cudaGetSymbolAddress((void**)&xnh, g_xn_h);  cudaGetSymbolAddress((void**)&xnl, g_xn_l);
    cudaGetSymbolAddress((void**)&yh,  g_y_h);   cudaGetSymbolAddress((void**)&yl,  g_y_l);
    cudaGetSymbolAddress((void**)&hh,  g_h_h);   cudaGetSymbolAddress((void**)&hl,  g_h_l);
    cudaGetSymbolAddress((void**)&wqkvh, g_wqkv_h); cudaGetSymbolAddress((void**)&wqkvl, g_wqkv_l);
    cudaGetSymbolAddress((void**)&woh, g_wo_h);  cudaGetSymbolAddress((void**)&wol, g_wo_l);
    cudaGetSymbolAddress((void**)&wfch, g_wfc_h); cudaGetSymbolAddress((void**)&wfcl, g_wfc_l);
    cudaGetSymbolAddress((void**)&wprh, g_wpr_h); cudaGetSymbolAddress((void**)&wprl, g_wpr_l);
    cudaGetSymbolAddress((void**)&lmh, g_lm_h);  cudaGetSymbolAddress((void**)&lml, g_lm_l);

    const int GEMM_SMEM = 81920;
    cudaFuncSetAttribute(gemm_bb<0>, cudaFuncAttributeMaxDynamicSharedMemorySize, GEMM_SMEM);
    cudaFuncSetAttribute(gemm_bb<1>, cudaFuncAttributeMaxDynamicSharedMemorySize, GEMM_SMEM);
    cudaFuncSetAttribute(gemm_bb<2>, cudaFuncAttributeMaxDynamicSharedMemorySize, GEMM_SMEM);
    cudaFuncSetAttribute(gemm_bb<3>, cudaFuncAttributeMaxDynamicSharedMemorySize, GEMM_SMEM);
    const int ATTN_SMEM = 4 * 64 * 65 * 4;
    cudaFuncSetAttribute(attn_kernel, cudaFuncAttributeMaxDynamicSharedMemorySize, ATTN_SMEM);

    // weight conversions
    {
        long n = (long)LL * QKVD * DD;
        cvt_qkv_kernel<<<(int)((n + 255) / 256), 256>>>(Wq, Wk, Wv, wqkvh, wqkvl);
        n = (long)LL * DD * DD;
        cvt_kernel<<<(int)((n + 255) / 256), 256>>>(Wo, woh, wol, n);
        n = (long)LL * FF * DD;
        cvt_kernel<<<(int)((n + 255) / 256), 256>>>(Wfc, wfch, wfcl, n);
        cvt_kernel<<<(int)((n + 255) / 256), 256>>>(Wpr, wprh, wprl, n);
        n = (long)VV * DD;
        cvt_kernel<<<(int)((n + 255) / 256), 256>>>(lm, lmh, lml, n);
    }

    embed_norm_kernel<<<BT, 256>>>(wte, idx, x, x0);

    for (int i = 0; i < LL; i++) {
        resid_kernel<<<(BT * DD) / 1024, 1024>>>(x, x0, rl, xl, i);
        rmsnorm_kernel<<<BT, 256>>>(x, xnh, xnl);

        gemm_bb<0><<<dim3(QKVD / 128, BT / 128), 256, GEMM_SMEM>>>(
            xnh, xnl, wqkvh + (long)i * QKVD * DD, wqkvl + (long)i * QKVD * DD,
            qkv, nullptr, nullptr, BT, QKVD, DD);

        int j = (i == 1) ? 0 : (i == 3) ? 1 : (i == 5) ? 2 : -1;
        if (j >= 0)
            ve_kernel<<<BT, 128>>>(xnh, xnl, qkv, idx,
                                   veT + (long)j * VV * 256, veG + j * KVH_ * 32);

        ropenorm_kernel<<<BT * 16, HD_>>>(qkv);

        int win = (i % 2 == 0) ? (TT / 2) : TT;
        attn_kernel<<<dim3(TT / 64, HH, BB), 256, ATTN_SMEM>>>(qkv, yh, yl, win);

        gemm_bb<1><<<dim3(DD / 128, BT / 128), 256, GEMM_SMEM>>>(
            yh, yl, woh + (long)i * DD * DD, wol + (long)i * DD * DD,
            x, nullptr, nullptr, BT, DD, DD);

        rmsnorm_kernel<<<BT, 256>>>(x, xnh, xnl);
        gemm_bb<2><<<dim3(FF / 128, BT / 128), 256, GEMM_SMEM>>>(
            xnh, xnl, wfch + (long)i * FF * DD, wfcl + (long)i * FF * DD,
            nullptr, hh, hl, BT, FF, DD);
        gemm_bb<1><<<dim3(DD / 128, BT / 128), 256, GEMM_SMEM>>>(
            hh, hl, wprh + (long)i * DD * FF, wprl + (long)i * DD * FF,
            x, nullptr, nullptr, BT, DD, FF);
    }

    rmsnorm_kernel<<<BT, 256>>>(x, xnh, xnl);
    gemm_bb<3><<<dim3(VV / 128, BT / 128), 256, GEMM_SMEM>>>(
        xnh, xnl, lmh, lml, out, nullptr, nullptr, BT, VV, DD);
}

// round 6
// speedup vs baseline: 2.2715x; 1.0629x over previous
#include <cuda_runtime.h>
#include <cuda_bf16.h>
#include <cuda_fp16.h>
#include <stdint.h>
#include <math.h>

#define VV   32000
#define DD   768
#define HH   12
#define KVH_ 4
#define LL   6
#define TT   1024
#define HD_  64
#define BB   2
#define BT   2048
#define FF   3072
#define QKVD 1280   // 768 q + 256 k + 256 v

typedef __nv_bfloat16 bf16;

// ---------------- device-global scratch -------------------------------------
__device__ float g_x  [BT*DD];
__device__ float g_x0 [BT*DD];
__device__ float g_qkv[BT*QKVD];

__device__ bf16 g_xn_h[BT*DD], g_xn_l[BT*DD];
__device__ bf16 g_y_h [BT*DD], g_y_l [BT*DD];
__device__ bf16 g_h_h [BT*FF], g_h_l [BT*FF];
__device__ __half g_xn_fh[BT*DD], g_xn_fl[BT*DD];

__device__ bf16 g_wqkv_h[LL*QKVD*DD], g_wqkv_l[LL*QKVD*DD];
__device__ bf16 g_wo_h  [LL*DD*DD],   g_wo_l  [LL*DD*DD];
__device__ bf16 g_wfc_h [LL*FF*DD],   g_wfc_l [LL*FF*DD];
__device__ bf16 g_wpr_h [LL*DD*FF],   g_wpr_l [LL*DD*FF];
__device__ __half g_lm_f[(long)VV*DD];

// ---------------- fp32 -> bf16 hi/lo conversion (vectorized) -----------------
__global__ void cvt4_kernel(const float4* __restrict__ in, __nv_bfloat162* __restrict__ h2,
                            __nv_bfloat162* __restrict__ l2, long n4) {
    long i = (long)blockIdx.x * 256 + threadIdx.x;
    if (i >= n4) return;
    float4 v = in[i];
    bf16 h0 = __float2bfloat16(v.x), h1 = __float2bfloat16(v.y);
    bf16 h2v = __float2bfloat16(v.z), h3 = __float2bfloat16(v.w);
    __nv_bfloat162 ha; ha.x = h0; ha.y = h1;
    __nv_bfloat162 hb; hb.x = h2v; hb.y = h3;
    h2[i * 2]     = ha;
    h2[i * 2 + 1] = hb;
    __nv_bfloat162 la, lb;
    la.x = __float2bfloat16(v.x - __bfloat162float(h0));
    la.y = __float2bfloat16(v.y - __bfloat162float(h1));
    lb.x = __float2bfloat16(v.z - __bfloat162float(h2v));
    lb.y = __float2bfloat16(v.w - __bfloat162float(h3));
    l2[i * 2]     = la;
    l2[i * 2 + 1] = lb;
}

__global__ void cvt_half4_kernel(const float4* __restrict__ in, __half2* __restrict__ o2, long n4) {
    long i = (long)blockIdx.x * 256 + threadIdx.x;
    if (i >= n4) return;
    float4 v = in[i];
    __half2 a; a.x = __float2half_rn(v.x); a.y = __float2half_rn(v.y);
    __half2 b; b.x = __float2half_rn(v.z); b.y = __float2half_rn(v.w);
    o2[i * 2]     = a;
    o2[i * 2 + 1] = b;
}

__global__ void cvt_qkv_kernel(const float* __restrict__ Wq, const float* __restrict__ Wk,
                               const float* __restrict__ Wv, bf16* __restrict__ h,
                               bf16* __restrict__ l) {
    long i = (long)blockIdx.x * 256 + threadIdx.x;
    long per = (long)QKVD * DD;
    if (i >= (long)LL * per) return;
    int layer = (int)(i / per);
    long rem = i % per;
    int row = (int)(rem / DD), col = (int)(rem % DD);
    float x;
    if (row < DD)            x = Wq[((long)layer*DD   + row)        * DD + col];
    else if (row < DD + 256) x = Wk[((long)layer*256  + row - DD)   * DD + col];
    else                     x = Wv[((long)layer*256  + row - 1024) * DD + col];
    bf16 hi = __float2bfloat16(x);
    h[i] = hi;
    l[i] = __float2bfloat16(x - __bfloat162float(hi));
}

// ---------------- fused embedding + rmsnorm ---------------------------------
__global__ void embed_norm_kernel(const float* __restrict__ wte,
                                  const int* __restrict__ idx,
                                  float* __restrict__ x, float* __restrict__ x0) {
    int t = blockIdx.x;
    const float* row = wte + (long)idx[t] * DD;
    int tid = threadIdx.x;
    float v[3]; float s = 0.f;
    #pragma unroll
    for (int j = 0; j < 3; j++) { v[j] = row[tid + j * 256]; s += v[j] * v[j]; }
    __shared__ float red[256];
    red[tid] = s; __syncthreads();
    for (int o = 128; o; o >>= 1) { if (tid < o) red[tid] += red[tid + o]; __syncthreads(); }
    float inv = rsqrtf(red[0] * (1.0f / DD) + 1e-6f);
    #pragma unroll
    for (int j = 0; j < 3; j++) {
        float w = v[j] * inv;
        x[(long)t * DD + tid + j * 256]  = w;
        x0[(long)t * DD + tid + j * 256] = w;
    }
}

// ---------------- fused resid-lambda + rmsnorm (bf16 hi/lo out) -------------
__global__ void resid_norm_kernel(float* __restrict__ x, const float* __restrict__ x0,
                                  const float* __restrict__ rl, const float* __restrict__ xl,
                                  int layer, bf16* __restrict__ oh, bf16* __restrict__ ol) {
    int t = blockIdx.x;
    int tid = threadIdx.x;
    float a = rl[layer], b = xl[layer];
    float v[3]; float s = 0.f;
    #pragma unroll
    for (int j = 0; j < 3; j++) {
        long id = (long)t * DD + tid + j * 256;
        float xv = a * x[id] + b * x0[id];
        v[j] = xv; s += xv * xv;
    }
    __shared__ float red[256];
    red[tid] = s; __syncthreads();
    for (int o = 128; o; o >>= 1) { if (tid < o) red[tid] += red[tid + o]; __syncthreads(); }
    float inv = rsqrtf(red[0] * (1.0f / DD) + 1e-6f);
    #pragma unroll
    for (int j = 0; j < 3; j++) {
        long id = (long)t * DD + tid + j * 256;
        x[id] = v[j];
        float w = v[j] * inv;
        bf16 hi = __float2bfloat16(w);
        oh[id] = hi;
        ol[id] = __float2bfloat16(w - __bfloat162float(hi));
    }
}

// ---------------- rmsnorm (bf16 hi/lo out) ----------------------------------
__global__ void rmsnorm_kernel(const float* __restrict__ src,
                               bf16* __restrict__ oh, bf16* __restrict__ ol) {
    int t = blockIdx.x;
    const float* xp = src + (long)t * DD;
    int tid = threadIdx.x;
    float v[3]; float s = 0.f;
    #pragma unroll
    for (int j = 0; j < 3; j++) { v[j] = xp[tid + j * 256]; s += v[j] * v[j]; }
    __shared__ float red[256];
    red[tid] = s; __syncthreads();
    for (int o = 128; o; o >>= 1) { if (tid < o) red[tid] += red[tid + o]; __syncthreads(); }
    float inv = rsqrtf(red[0] * (1.0f / DD) + 1e-6f);
    #pragma unroll
    for (int j = 0; j < 3; j++) {
        float w = v[j] * inv;
        long id = (long)t * DD + tid + j * 256;
        bf16 hi = __float2bfloat16(w);
        oh[id] = hi;
        ol[id] = __float2bfloat16(w - __bfloat162float(hi));
    }
}

// ---------------- rmsnorm (fp16 hi/lo out, for lm_head) ---------------------
__global__ void rmsnorm_h_kernel(const float* __restrict__ src,
                                 __half* __restrict__ oh, __half* __restrict__ ol) {
    int t = blockIdx.x;
    const float* xp = src + (long)t * DD;
    int tid = threadIdx.x;
    float v[3]; float s = 0.f;
    #pragma unroll
    for (int j = 0; j < 3; j++) { v[j] = xp[tid + j * 256]; s += v[j] * v[j]; }
    __shared__ float red[256];
    red[tid] = s; __syncthreads();
    for (int o = 128; o; o >>= 1) { if (tid < o) red[tid] += red[tid + o]; __syncthreads(); }
    float inv = rsqrtf(red[0] * (1.0f / DD) + 1e-6f);
    #pragma unroll
    for (int j = 0; j < 3; j++) {
        float w = v[j] * inv;
        long id = (long)t * DD + tid + j * 256;
        __half hi = __float2half_rn(w);
        oh[id] = hi;
        ol[id] = __float2half_rn(w - __half2float(hi));
    }
}

// ---------------- value-embedding gate add (v slice of qkv) ------------------
__global__ void ve_kernel(const bf16* __restrict__ xnh, const bf16* __restrict__ xnl,
                          float* __restrict__ qkv,
                          const int* __restrict__ idx,
                          const float* __restrict__ ve_table,
                          const float* __restrict__ ve_gate) {
    int tok  = blockIdx.x;
    int tid  = threadIdx.x;           // 128
    int warp = tid >> 5, lane = tid & 31;
    __shared__ float gates[KVH_];
    float xv = __bfloat162float(xnh[(long)tok * DD + lane]) +
               __bfloat162float(xnl[(long)tok * DD + lane]);
    float g = xv * ve_gate[warp * 32 + lane];
    #pragma unroll
    for (int o = 16; o; o >>= 1) g += __shfl_down_sync(0xffffffffu, g, o);
    if (lane == 0) gates[warp] = 2.0f / (1.0f + expf(-g));
    __syncthreads();
    const float* vt = ve_table + (long)idx[tok] * 256;
    float* v = qkv + (long)tok * QKVD + 1024;
    for (int i = tid; i < 256; i += 128)
        v[i] += gates[i >> 6] * vt[i];
}

// ---------------- fused rope + per-head rmsnorm (q and k in qkv) ------------
__global__ void ropenorm_kernel(float* __restrict__ qkv) {
    int bid = blockIdx.x;
    int hh  = bid & 15;               // 0..11 q heads, 12..15 k heads
    int tok = bid >> 4;
    int t   = tok % TT;
    float* ptr = qkv + (long)tok * QKVD + (hh < HH ? hh * HD_ : DD + (hh - HH) * HD_);
    int d = threadIdx.x;              // 64
    __shared__ float sv[HD_];
    __shared__ float red[HD_];
    sv[d] = ptr[d];
    __syncthreads();
    int j = d & 31;
    float invf = 1.0f / powf(10000.0f, (float)(2 * j) * (1.0f / 64.0f));
    float ang  = (float)t * invf;
    float cv = cosf(ang), sn = sinf(ang);
    float x1 = sv[j], x2 = sv[j + 32];
    float r = (d < 32) ? (x1 * cv + x2 * sn) : (x2 * cv - x1 * sn);
    red[d] = r * r; __syncthreads();
    for (int o = 32; o; o >>= 1) { if (d < o) red[d] += red[d + o]; __syncthreads(); }
    float inv = rsqrtf(red[0] * (1.0f / HD_) + 1e-6f);
    ptr[d] = r * inv;
}

// ---------------- tiled attention -------------------------------------------
__global__ __launch_bounds__(256) void attn_kernel(const float* __restrict__ qkv,
                                                   bf16* __restrict__ yh,
                                                   bf16* __restrict__ yl, int win) {
    extern __shared__ float asm_[];
    float* Qs = asm_;
    float* Ks = asm_ + 64 * 65;
    float* Vs = asm_ + 2 * 64 * 65;
    float* Ss = asm_ + 3 * 64 * 65;
    int qt = blockIdx.x, h = blockIdx.y, b = blockIdx.z;
    int kh = h / (HH / KVH_);
    int tid = threadIdx.x;
    int qrow = tid >> 2;
    int dseg = tid & 3;
    int q0 = qt * 64;

    for (int it = 0; it < 16; it++) {
        int id = tid + it * 256;
        int r = id >> 6, c = id & 63;
        Qs[r * 65 + c] = qkv[((long)(b * TT + q0 + r)) * QKVD + h * HD_ + c] * 0.125f;
    }

    float m = -1e30f, lsum = 0.f;
    float o[16];
    #pragma unroll
    for (int j2 = 0; j2 < 16; j2++) o[j2] = 0.f;

    int lo = q0 - win + 1;
    int kt0 = lo > 0 ? (lo >> 6) : 0;
    for (int kt = kt0; kt <= qt; kt++) {
        __syncthreads();
        for (int it = 0; it < 16; it++) {
            int id = tid + it * 256;
            int r = id >> 6, c = id & 63;
            long base = ((long)(b * TT + kt * 64 + r)) * QKVD;
            Ks[r * 65 + c] = qkv[base + DD   + kh * HD_ + c];
            Vs[r * 65 + c] = qkv[base + 1024 + kh * HD_ + c];
        }
        __syncthreads();

        float sv[16];
        #pragma unroll
        for (int j2 = 0; j2 < 16; j2++) {
            int k = dseg * 16 + j2;
            float s = 0.f;
            #pragma unroll
            for (int e = 0; e < 64; e++) s += Qs[qrow * 65 + e] * Ks[k * 65 + e];
            int diff = (q0 + qrow) - (kt * 64 + k);
            sv[j2] = (diff >= 0 && diff < win) ? s : -1e30f;
        }
        float mx = sv[0];
        #pragma unroll
        for (int j2 = 1; j2 < 16; j2++) mx = fmaxf(mx, sv[j2]);
        mx = fmaxf(mx, __shfl_xor_sync(0xffffffffu, mx, 1));
        mx = fmaxf(mx, __shfl_xor_sync(0xffffffffu, mx, 2));
        float mnew = fmaxf(m, mx);
        float f = __expf(m - mnew);
        float rs = 0.f;
        #pragma unroll
        for (int j2 = 0; j2 < 16; j2++) {
            float p = __expf(sv[j2] - mnew);
            Ss[qrow * 65 + dseg * 16 + j2] = p;
            rs += p;
        }
        rs += __shfl_xor_sync(0xffffffffu, rs, 1);
        rs += __shfl_xor_sync(0xffffffffu, rs, 2);
        lsum = lsum * f + rs;
        #pragma unroll
        for (int j2 = 0; j2 < 16; j2++) o[j2] *= f;
        m = mnew;
        __syncwarp();
        for (int k = 0; k < 64; k++) {
            float p = Ss[qrow * 65 + k];
            #pragma unroll
            for (int j2 = 0; j2 < 16; j2++)
                o[j2] += p * Vs[k * 65 + dseg * 16 + j2];
        }
    }
    float inv = 1.0f / lsum;
    long tok = (long)(b * TT + q0 + qrow);
    #pragma unroll
    for (int j2 = 0; j2 < 16; j2++) {
        float val = o[j2] * inv;
        long id = tok * DD + h * HD_ + dseg * 16 + j2;
        bf16 hi = __float2bfloat16(val);
        yh[id] = hi;
        yl[id] = __float2bfloat16(val - __bfloat162float(hi));
    }
}

// ---------------- bf16-split tensor-core NT GEMM (3-pass) -------------------
#define MMA_BF16(d, a0,a1,a2,a3, b0,b1) \
  asm volatile("mma.sync.aligned.m16n8k16.row.col.f32.bf16.bf16.f32 " \
    "{%0,%1,%2,%3},{%4,%5,%6,%7},{%8,%9},{%0,%1,%2,%3};\n" \
    : "+f"(d[0]),"+f"(d[1]),"+f"(d[2]),"+f"(d[3]) \
    : "r"(a0),"r"(a1),"r"(a2),"r"(a3),"r"(b0),"r"(b1))

#define MMA_F16(d, a0,a1,a2,a3, b0,b1) \
  asm volatile("mma.sync.aligned.m16n8k16.row.col.f32.f16.f16.f32 " \
    "{%0,%1,%2,%3},{%4,%5,%6,%7},{%8,%9},{%0,%1,%2,%3};\n" \
    : "+f"(d[0]),"+f"(d[1]),"+f"(d[2]),"+f"(d[3]) \
    : "r"(a0),"r"(a1),"r"(a2),"r"(a3),"r"(b0),"r"(b1))

template <int EPI>
__global__ __launch_bounds__(256, 1) void gemm_bb(
    const bf16* __restrict__ Ah, const bf16* __restrict__ Al,
    const bf16* __restrict__ Bh, const bf16* __restrict__ Bl,
    float* __restrict__ C, bf16* __restrict__ Ch, bf16* __restrict__ Cl,
    int M, int N, int K) {
    extern __shared__ bf16 sm[];
    const int tid = threadIdx.x;
    const int wid = tid >> 5, lane = tid & 31;
    const int wm = wid & 3, wn = wid >> 2;
    const int bm = blockIdx.y << 7, bn = blockIdx.x << 7;

    float acc[2][8][4];
    #pragma unroll
    for (int i = 0; i < 2; i++)
        #pragma unroll
        for (int j = 0; j < 8; j++)
            #pragma unroll
            for (int e = 0; e < 4; e++) acc[i][j][e] = 0.f;

    const int nc = K >> 5;

    auto issue = [&](int c, int s) {
        int k0 = c << 5;
        #pragma unroll
        for (int it = 0; it < 4; it++) {
            int t = tid + it * 256;
            int hl = t >> 9, rem = t & 511, row = rem >> 2, seg = rem & 3;
            const bf16* g = (hl ? Al : Ah) + (long)(bm + row) * K + k0 + seg * 8;
            uint32_t sa = (uint32_t)__cvta_generic_to_shared(sm + s * 20480 + hl * 5120 + row * 40 + seg * 8);
            asm volatile("cp.async.cg.shared.global [%0],[%1],16;\n" :: "r"(sa), "l"(g));
        }
        #pragma unroll
        for (int it = 0; it < 4; it++) {
            int t = tid + it * 256;
            int hl = t >> 9, rem = t & 511, row = rem >> 2, seg = rem & 3;
            const bf16* g = (hl ? Bl : Bh) + (long)(bn + row) * K + k0 + seg * 8;
            uint32_t sa = (uint32_t)__cvta_generic_to_shared(sm + s * 20480 + 10240 + hl * 5120 + row * 40 + seg * 8);
            asm volatile("cp.async.cg.shared.global [%0],[%1],16;\n" :: "r"(sa), "l"(g));
        }
        asm volatile("cp.async.commit_group;\n");
    };

    issue(0, 0);
    for (int c = 0; c < nc; c++) {
        int s = c & 1;
        if (c + 1 < nc) {
            issue(c + 1, s ^ 1);
            asm volatile("cp.async.wait_group 1;\n");
        } else {
            asm volatile("cp.async.wait_group 0;\n");
        }
        __syncthreads();

        const bf16* As = sm + s * 20480;
        const bf16* Bs = sm + s * 20480 + 10240;
        #pragma unroll
        for (int kk = 0; kk < 2; kk++) {
            uint32_t a[2][2][4];
            #pragma unroll
            for (int i = 0; i < 2; i++)
                #pragma unroll
                for (int hl = 0; hl < 2; hl++) {
                    uint32_t addr = (uint32_t)__cvta_generic_to_shared(
                        As + hl * 5120 + (wm * 32 + i * 16 + (lane & 15)) * 40 + kk * 16 + (lane >> 4) * 8);
                    asm volatile("ldmatrix.sync.aligned.m8n8.x4.shared.b16 {%0,%1,%2,%3},[%4];\n"
                        : "=r"(a[i][hl][0]), "=r"(a[i][hl][1]), "=r"(a[i][hl][2]), "=r"(a[i][hl][3])
                        : "r"(addr));
                }
            uint32_t bfr[4][2][4];
            #pragma unroll
            for (int p2 = 0; p2 < 4; p2++)
                #pragma unroll
                for (int hl = 0; hl < 2; hl++) {
                    int row = wn * 64 + p2 * 16 + (lane & 7) + ((lane >> 4) & 1) * 8;
                    int col = kk * 16 + ((lane >> 3) & 1) * 8;
                    uint32_t addr = (uint32_t)__cvta_generic_to_shared(Bs + hl * 5120 + row * 40 + col);
                    asm volatile("ldmatrix.sync.aligned.m8n8.x4.shared.b16 {%0,%1,%2,%3},[%4];\n"
                        : "=r"(bfr[p2][hl][0]), "=r"(bfr[p2][hl][1]), "=r"(bfr[p2][hl][2]), "=r"(bfr[p2][hl][3])
                        : "r"(addr));
                }
            #pragma unroll
            for (int i = 0; i < 2; i++)
                #pragma unroll
                for (int j = 0; j < 8; j++) {
                    int p2 = j >> 1, half = j & 1;
                    uint32_t bh0 = bfr[p2][0][half * 2], bh1 = bfr[p2][0][half * 2 + 1];
                    uint32_t bl0 = bfr[p2][1][half * 2], bl1 = bfr[p2][1][half * 2 + 1];
                    MMA_BF16(acc[i][j], a[i][0][0], a[i][0][1], a[i][0][2], a[i][0][3], bh0, bh1);
                    MMA_BF16(acc[i][j], a[i][0][0], a[i][0][1], a[i][0][2], a[i][0][3], bl0, bl1);
                    MMA_BF16(acc[i][j], a[i][1][0], a[i][1][1], a[i][1][2], a[i][1][3], bh0, bh1);
                }
        }
        __syncthreads();
    }

    #pragma unroll
    for (int i = 0; i < 2; i++) {
        int r0 = bm + wm * 32 + i * 16 + (lane >> 2);
        #pragma unroll
        for (int j = 0; j < 8; j++) {
            int col = bn + wn * 64 + j * 8 + (lane & 3) * 2;
            #pragma unroll
            for (int e = 0; e < 4; e++) {
                int rr = r0 + (e >> 1) * 8;
                int cc = col + (e & 1);
                long id = (long)rr * N + cc;
                float val = acc[i][j][e];
                if (EPI == 0)      C[id] = val;
                else if (EPI == 1) C[id] += val;
                else if (EPI == 2) {
                    float r = fmaxf(val, 0.f); r = r * r;
                    bf16 hi = __float2bfloat16(r);
                    Ch[id] = hi;
                    Cl[id] = __float2bfloat16(r - __bfloat162float(hi));
                }
                else C[id] = 15.0f * tanhf(val * (1.0f / 15.0f));
            }
        }
    }
}

// ---------------- fp16 2-pass GEMM for lm_head ------------------------------
// C[M,N] = softcap( (Ah+Al)[M,K] * B[N,K]^T ), A split fp16, B single fp16.
// smem stage (halves): Ah[0,5120) Al[5120,10240) B[10240,15360); stride 15360.
__global__ __launch_bounds__(256, 1) void gemm_lm(
    const __half* __restrict__ Ah, const __half* __restrict__ Al,
    const __half* __restrict__ Bf,
    float* __restrict__ C, int M, int N, int K) {
    extern __shared__ __half smh[];
    const int tid = threadIdx.x;
    const int wid = tid >> 5, lane = tid & 31;
    const int wm = wid & 3, wn = wid >> 2;
    const int bm = blockIdx.y << 7, bn = blockIdx.x << 7;

    float acc[2][8][4];
    #pragma unroll
    for (int i = 0; i < 2; i++)
        #pragma unroll
        for (int j = 0; j < 8; j++)
            #pragma unroll
            for (int e = 0; e < 4; e++) acc[i][j][e] = 0.f;

    const int nc = K >> 5;

    auto issue = [&](int c, int s) {
        int k0 = c << 5;
        #pragma unroll
        for (int it = 0; it < 6; it++) {
            int t = tid + it * 256;
            uint32_t sa; const __half* g;
            if (t < 1024) {
                int hl = t >> 9, rem = t & 511, row = rem >> 2, seg = rem & 3;
                g = (hl ? Al : Ah) + (long)(bm + row) * K + k0 + seg * 8;
                sa = (uint32_t)__cvta_generic_to_shared(smh + s * 15360 + hl * 5120 + row * 40 + seg * 8);
            } else {
                int t2 = t - 1024;
                int row = t2 >> 2, seg = t2 & 3;
                g = Bf + (long)(bn + row) * K + k0 + seg * 8;
                sa = (uint32_t)__cvta_generic_to_shared(smh + s * 15360 + 10240 + row * 40 + seg * 8);
            }
            asm volatile("cp.async.cg.shared.global [%0],[%1],16;\n" :: "r"(sa), "l"(g));
        }
        asm volatile("cp.async.commit_group;\n");
    };

    issue(0, 0);
    for (int c = 0; c < nc; c++) {
        int s = c & 1;
        if (c + 1 < nc) {
            issue(c + 1, s ^ 1);
            asm volatile("cp.async.wait_group 1;\n");
        } else {
            asm volatile("cp.async.wait_group 0;\n");
        }
        __syncthreads();

        const __half* As = smh + s * 15360;
        const __half* Bs = smh + s * 15360 + 10240;
        #pragma unroll
        for (int kk = 0; kk < 2; kk++) {
            uint32_t a[2][2][4];
            #pragma unroll
            for (int i = 0; i < 2; i++)
                #pragma unroll
                for (int hl = 0; hl < 2; hl++) {
                    uint32_t addr = (uint32_t)__cvta_generic_to_shared(
                        As + hl * 5120 + (wm * 32 + i * 16 + (lane & 15)) * 40 + kk * 16 + (lane >> 4) * 8);
                    asm volatile("ldmatrix.sync.aligned.m8n8.x4.shared.b16 {%0,%1,%2,%3},[%4];\n"
                        : "=r"(a[i][hl][0]), "=r"(a[i][hl][1]), "=r"(a[i][hl][2]), "=r"(a[i][hl][3])
                        : "r"(addr));
                }
            uint32_t bfr[4][4];
            #pragma unroll
            for (int p2 = 0; p2 < 4; p2++) {
                int row = wn * 64 + p2 * 16 + (lane & 7) + ((lane >> 4) & 1) * 8;
                int col = kk * 16 + ((lane >> 3) & 1) * 8;
                uint32_t addr = (uint32_t)__cvta_generic_to_shared(Bs + row * 40 + col);
                asm volatile("ldmatrix.sync.aligned.m8n8.x4.shared.b16 {%0,%1,%2,%3},[%4];\n"
                    : "=r"(bfr[p2][0]), "=r"(bfr[p2][1]), "=r"(bfr[p2][2]), "=r"(bfr[p2][3])
                    : "r"(addr));
            }
            #pragma unroll
            for (int i = 0; i < 2; i++)
                #pragma unroll
                for (int j = 0; j < 8; j++) {
                    int p2 = j >> 1, half = j & 1;
                    uint32_t b0 = bfr[p2][half * 2], b1 = bfr[p2][half * 2 + 1];
                    MMA_F16(acc[i][j], a[i][0][0], a[i][0][1], a[i][0][2], a[i][0][3], b0, b1);
                    MMA_F16(acc[i][j], a[i][1][0], a[i][1][1], a[i][1][2], a[i][1][3], b0, b1);
                }
        }
        __syncthreads();
    }

    #pragma unroll
    for (int i = 0; i < 2; i++) {
        int r0 = bm + wm * 32 + i * 16 + (lane >> 2);
        #pragma unroll
        for (int j = 0; j < 8; j++) {
            int col = bn + wn * 64 + j * 8 + (lane & 3) * 2;
            #pragma unroll
            for (int e = 0; e < 4; e++) {
                int rr = r0 + (e >> 1) * 8;
                int cc = col + (e & 1);
                C[(long)rr * N + cc] = 15.0f * tanhf(acc[i][j][e] * (1.0f / 15.0f));
            }
        }
    }
}

// ---------------- orchestration ---------------------------------------------
extern "C" void kernel_launch(void* const* d_in, const int* in_sizes, int n_in,
                              void* d_out, int out_size) {
    const int*   idx  = (const int*)  d_in[0];
    const float* wte  = (const float*)d_in[1];
    const float* Wq   = (const float*)d_in[2];
    const float* Wk   = (const float*)d_in[3];
    const float* Wv   = (const float*)d_in[4];
    const float* Wo   = (const float*)d_in[5];
    const float* Wfc  = (const float*)d_in[6];
    const float* Wpr  = (const float*)d_in[7];
    const float* veT  = (const float*)d_in[8];
    const float* veG  = (const float*)d_in[9];
    const float* rl   = (const float*)d_in[10];
    const float* xl   = (const float*)d_in[11];
    const float* lm   = (const float*)d_in[12];
    float* out = (float*)d_out;

    float *x, *x0, *qkv;
    bf16 *xnh, *xnl, *yh, *yl, *hh, *hl;
    __half *xnfh, *xnfl, *lmf;
    bf16 *wqkvh, *wqkvl, *woh, *wol, *wfch, *wfcl, *wprh, *wprl;
    cudaGetSymbolAddress((void**)&x,   g_x);
    cudaGetSymbolAddress((void**)&x0,  g_x0);
    cudaGetSymbolAddress((void**)&qkv, g_qkv);
    cudaGetSymbolAddress((void**)&xnh, g_xn_h);  cudaGetSymbolAddress((void**)&xnl, g_xn_l);
    cudaGetSymbolAddress((void**)&yh,  g_y_h);   cudaGetSymbolAddress((void**)&yl,  g_y_l);
    cudaGetSymbolAddress((void**)&hh,  g_h_h);   cudaGetSymbolAddress((void**)&hl,  g_h_l);
    cudaGetSymbolAddress((void**)&xnfh, g_xn_fh); cudaGetSymbolAddress((void**)&xnfl, g_xn_fl);
    cudaGetSymbolAddress((void**)&wqkvh, g_wqkv_h); cudaGetSymbolAddress((void**)&wqkvl, g_wqkv_l);
    cudaGetSymbolAddress((void**)&woh, g_wo_h);  cudaGetSymbolAddress((void**)&wol, g_wo_l);
    cudaGetSymbolAddress((void**)&wfch, g_wfc_h); cudaGetSymbolAddress((void**)&wfcl, g_wfc_l);
    cudaGetSymbolAddress((void**)&wprh, g_wpr_h); cudaGetSymbolAddress((void**)&wprl, g_wpr_l);
    cudaGetSymbolAddress((void**)&lmf, g_lm_f);

    const int GEMM_SMEM = 81920;
    cudaFuncSetAttribute(gemm_bb<0>, cudaFuncAttributeMaxDynamicSharedMemorySize, GEMM_SMEM);
    cudaFuncSetAttribute(gemm_bb<1>, cudaFuncAttributeMaxDynamicSharedMemorySize, GEMM_SMEM);
    cudaFuncSetAttribute(gemm_bb<2>, cudaFuncAttributeMaxDynamicSharedMemorySize, GEMM_SMEM);
    const int LM_SMEM = 2 * 15360 * 2;  // 61440 bytes
    cudaFuncSetAttribute(gemm_lm, cudaFuncAttributeMaxDynamicSharedMemorySize, LM_SMEM);
    const int ATTN_SMEM = 4 * 64 * 65 * 4;
    cudaFuncSetAttribute(attn_kernel, cudaFuncAttributeMaxDynamicSharedMemorySize, ATTN_SMEM);

    // weight conversions
    {
        long n = (long)LL * QKVD * DD;
        cvt_qkv_kernel<<<(int)((n + 255) / 256), 256>>>(Wq, Wk, Wv, wqkvh, wqkvl);
        long n4 = (long)LL * DD * DD / 4;
        cvt4_kernel<<<(int)((n4 + 255) / 256), 256>>>((const float4*)Wo,
            (__nv_bfloat162*)woh, (__nv_bfloat162*)wol, n4);
        n4 = (long)LL * FF * DD / 4;
        cvt4_kernel<<<(int)((n4 + 255) / 256), 256>>>((const float4*)Wfc,
            (__nv_bfloat162*)wfch, (__nv_bfloat162*)wfcl, n4);
        cvt4_kernel<<<(int)((n4 + 255) / 256), 256>>>((const float4*)Wpr,
            (__nv_bfloat162*)wprh, (__nv_bfloat162*)wprl, n4);
        n4 = (long)VV * DD / 4;
        cvt_half4_kernel<<<(int)((n4 + 255) / 256), 256>>>((const float4*)lm, (__half2*)lmf, n4);
    }

    embed_norm_kernel<<<BT, 256>>>(wte, idx, x, x0);

    for (int i = 0; i < LL; i++) {
        resid_norm_kernel<<<BT, 256>>>(x, x0, rl, xl, i, xnh, xnl);

        gemm_bb<0><<<dim3(QKVD / 128, BT / 128), 256, GEMM_SMEM>>>(
            xnh, xnl, wqkvh + (long)i * QKVD * DD, wqkvl + (long)i * QKVD * DD,
            qkv, nullptr, nullptr, BT, QKVD, DD);

        int j = (i == 1) ? 0 : (i == 3) ? 1 : (i == 5) ? 2 : -1;
        if (j >= 0)
            ve_kernel<<<BT, 128>>>(xnh, xnl, qkv, idx,
                                   veT + (long)j * VV * 256, veG + j * KVH_ * 32);

        ropenorm_kernel<<<BT * 16, HD_>>>(qkv);

        int win = (i % 2 == 0) ? (TT / 2) : TT;
        attn_kernel<<<dim3(TT / 64, HH, BB), 256, ATTN_SMEM>>>(qkv, yh, yl, win);

        gemm_bb<1><<<dim3(DD / 128, BT / 128), 256, GEMM_SMEM>>>(
            yh, yl, woh + (long)i * DD * DD, wol + (long)i * DD * DD,
            x, nullptr, nullptr, BT, DD, DD);

        rmsnorm_kernel<<<BT, 256>>>(x, xnh, xnl);
        gemm_bb<2><<<dim3(FF / 128, BT / 128), 256, GEMM_SMEM>>>(
            xnh, xnl, wfch + (long)i * FF * DD, wfcl + (long)i * FF * DD,
            nullptr, hh, hl, BT, FF, DD);
        gemm_bb<1><<<dim3(DD / 128, BT / 128), 256, GEMM_SMEM>>>(
            hh, hl, wprh + (long)i * DD * FF, wprl + (long)i * DD * FF,
            x, nullptr, nullptr, BT, DD, FF);
    }

    rmsnorm_h_kernel<<<BT, 256>>>(x, xnfh, xnfl);
    gemm_lm<<<dim3(VV / 128, BT / 128), 256, LM_SMEM>>>(
        xnfh, xnfl, lmf, out, BT, VV, DD);
}

// round 8
// speedup vs baseline: 3.8756x; 1.7062x over previous
#include <cuda_runtime.h>
#include <cuda_bf16.h>
#include <cuda_fp16.h>
#include <stdint.h>
#include <math.h>

#define VV   32000
#define DD   768
#define HH   12
#define KVH_ 4
#define LL   6
#define TT   1024
#define HD_  64
#define BB   2
#define BT   2048
#define FF   3072
#define QKVD 1280   // 768 q + 256 k + 256 v

typedef __nv_bfloat16 bf16;

#define CP16(dst, src)    asm volatile("cp.async.cg.shared.global [%0],[%1],16;\n" :: "r"(dst), "l"(src))
#define CP_COMMIT()       asm volatile("cp.async.commit_group;\n")
#define LDM4(r, addr) \
    asm volatile("ldmatrix.sync.aligned.m8n8.x4.shared.b16 {%0,%1,%2,%3},[%4];\n" \
        : "=r"((r)[0]), "=r"((r)[1]), "=r"((r)[2]), "=r"((r)[3]) : "r"(addr))

#define MMA_BF16(d, a, b0,b1) \
  asm volatile("mma.sync.aligned.m16n8k16.row.col.f32.bf16.bf16.f32 " \
    "{%0,%1,%2,%3},{%4,%5,%6,%7},{%8,%9},{%0,%1,%2,%3};\n" \
    : "+f"((d)[0]),"+f"((d)[1]),"+f"((d)[2]),"+f"((d)[3]) \
    : "r"((a)[0]),"r"((a)[1]),"r"((a)[2]),"r"((a)[3]),"r"(b0),"r"(b1))

#define MMA_F16(d, a, b0,b1) \
  asm volatile("mma.sync.aligned.m16n8k16.row.col.f32.f16.f16.f32 " \
    "{%0,%1,%2,%3},{%4,%5,%6,%7},{%8,%9},{%0,%1,%2,%3};\n" \
    : "+f"((d)[0]),"+f"((d)[1]),"+f"((d)[2]),"+f"((d)[3]) \
    : "r"((a)[0]),"r"((a)[1]),"r"((a)[2]),"r"((a)[3]),"r"(b0),"r"(b1))

// ---------------- device-global scratch -------------------------------------
__device__ float g_x  [BT*DD];
__device__ float g_x0 [BT*DD];
__device__ float g_qkv[BT*QKVD];

__device__ bf16 g_xn_h[BT*DD], g_xn_l[BT*DD];
__device__ bf16 g_y_h [BT*DD], g_y_l [BT*DD];
__device__ bf16 g_h_h [BT*FF], g_h_l [BT*FF];
__device__ __half g_xn_fh[BT*DD], g_xn_fl[BT*DD];

__device__ bf16 g_qah[BB*HH*TT*HD_],  g_qal[BB*HH*TT*HD_];
__device__ bf16 g_kah[BB*KVH_*TT*HD_], g_kal[BB*KVH_*TT*HD_];
__device__ bf16 g_vth[BB*KVH_*HD_*TT], g_vtl[BB*KVH_*HD_*TT];

__device__ bf16 g_wqkv_h[LL*QKVD*DD], g_wqkv_l[LL*QKVD*DD];
__device__ bf16 g_wo_h  [LL*DD*DD],   g_wo_l  [LL*DD*DD];
__device__ bf16 g_wfc_h [LL*FF*DD],   g_wfc_l [LL*FF*DD];
__device__ bf16 g_wpr_h [LL*DD*FF],   g_wpr_l [LL*DD*FF];
__device__ __half g_lm_f[(long)VV*DD];

// ---------------- fp32 -> bf16 hi/lo conversion (vectorized) -----------------
__global__ void cvt4_kernel(const float4* __restrict__ in, __nv_bfloat162* __restrict__ h2,
                            __nv_bfloat162* __restrict__ l2, long n4) {
    long i = (long)blockIdx.x * 256 + threadIdx.x;
    if (i >= n4) return;
    float4 v = in[i];
    bf16 h0 = __float2bfloat16(v.x), h1 = __float2bfloat16(v.y);
    bf16 h2v = __float2bfloat16(v.z), h3 = __float2bfloat16(v.w);
    __nv_bfloat162 ha; ha.x = h0; ha.y = h1;
    __nv_bfloat162 hb; hb.x = h2v; hb.y = h3;
    h2[i * 2]     = ha;
    h2[i * 2 + 1] = hb;
    __nv_bfloat162 la, lb;
    la.x = __float2bfloat16(v.x - __bfloat162float(h0));
    la.y = __float2bfloat16(v.y - __bfloat162float(h1));
    lb.x = __float2bfloat16(v.z - __bfloat162float(h2v));
    lb.y = __float2bfloat16(v.w - __bfloat162float(h3));
    l2[i * 2]     = la;
    l2[i * 2 + 1] = lb;
}

__global__ void cvt_half4_kernel(const float4* __restrict__ in, __half2* __restrict__ o2, long n4) {
    long i = (long)blockIdx.x * 256 + threadIdx.x;
    if (i >= n4) return;
    float4 v = in[i];
    __half2 a; a.x = __float2half_rn(v.x); a.y = __float2half_rn(v.y);
    __half2 b; b.x = __float2half_rn(v.z); b.y = __float2half_rn(v.w);
    o2[i * 2]     = a;
    o2[i * 2 + 1] = b;
}

__global__ void cvt_qkv_kernel(const float* __restrict__ Wq, const float* __restrict__ Wk,
                               const float* __restrict__ Wv, bf16* __restrict__ h,
                               bf16* __restrict__ l) {
    long i = (long)blockIdx.x * 256 + threadIdx.x;
    long per = (long)QKVD * DD;
    if (i >= (long)LL * per) return;
    int layer = (int)(i / per);
    long rem = i % per;
    int row = (int)(rem / DD), col = (int)(rem % DD);
    float x;
    if (row < DD)            x = Wq[((long)layer*DD   + row)        * DD + col];
    else if (row < DD + 256) x = Wk[((long)layer*256  + row - DD)   * DD + col];
    else                     x = Wv[((long)layer*256  + row - 1024) * DD + col];
    bf16 hi = __float2bfloat16(x);
    h[i] = hi;
    l[i] = __float2bfloat16(x - __bfloat162float(hi));
}

// ---------------- fused embedding + rmsnorm ---------------------------------
__global__ void embed_norm_kernel(const float* __restrict__ wte,
                                  const int* __restrict__ idx,
                                  float* __restrict__ x, float* __restrict__ x0) {
    int t = blockIdx.x;
    const float* row = wte + (long)idx[t] * DD;
    int tid = threadIdx.x;
    float v[3]; float s = 0.f;
    #pragma unroll
    for (int j = 0; j < 3; j++) { v[j] = row[tid + j * 256]; s += v[j] * v[j]; }
    __shared__ float red[256];
    red[tid] = s; __syncthreads();
    for (int o = 128; o; o >>= 1) { if (tid < o) red[tid] += red[tid + o]; __syncthreads(); }
    float inv = rsqrtf(red[0] * (1.0f / DD) + 1e-6f);
    #pragma unroll
    for (int j = 0; j < 3; j++) {
        float w = v[j] * inv;
        x[(long)t * DD + tid + j * 256]  = w;
        x0[(long)t * DD + tid + j * 256] = w;
    }
}

// ---------------- fused resid-lambda + rmsnorm ------------------------------
__global__ void resid_norm_kernel(float* __restrict__ x, const float* __restrict__ x0,
                                  const float* __restrict__ rl, const float* __restrict__ xl,
                                  int layer, bf16* __restrict__ oh, bf16* __restrict__ ol) {
    int t = blockIdx.x;
    int tid = threadIdx.x;
    float a = rl[layer], b = xl[layer];
    float v[3]; float s = 0.f;
    #pragma unroll
    for (int j = 0; j < 3; j++) {
        long id = (long)t * DD + tid + j * 256;
        float xv = a * x[id] + b * x0[id];
        v[j] = xv; s += xv * xv;
    }
    __shared__ float red[256];
    red[tid] = s; __syncthreads();
    for (int o = 128; o; o >>= 1) { if (tid < o) red[tid] += red[tid + o]; __syncthreads(); }
    float inv = rsqrtf(red[0] * (1.0f / DD) + 1e-6f);
    #pragma unroll
    for (int j = 0; j < 3; j++) {
        long id = (long)t * DD + tid + j * 256;
        x[id] = v[j];
        float w = v[j] * inv;
        bf16 hi = __float2bfloat16(w);
        oh[id] = hi;
        ol[id] = __float2bfloat16(w - __bfloat162float(hi));
    }
}

// ---------------- rmsnorm (bf16 hi/lo out) ----------------------------------
__global__ void rmsnorm_kernel(const float* __restrict__ src,
                               bf16* __restrict__ oh, bf16* __restrict__ ol) {
    int t = blockIdx.x;
    const float* xp = src + (long)t * DD;
    int tid = threadIdx.x;
    float v[3]; float s = 0.f;
    #pragma unroll
    for (int j = 0; j < 3; j++) { v[j] = xp[tid + j * 256]; s += v[j] * v[j]; }
    __shared__ float red[256];
    red[tid] = s; __syncthreads();
    for (int o = 128; o; o >>= 1) { if (tid < o) red[tid] += red[tid + o]; __syncthreads(); }
    float inv = rsqrtf(red[0] * (1.0f / DD) + 1e-6f);
    #pragma unroll
    for (int j = 0; j < 3; j++) {
        float w = v[j] * inv;
        long id = (long)t * DD + tid + j * 256;
        bf16 hi = __float2bfloat16(w);
        oh[id] = hi;
        ol[id] = __float2bfloat16(w - __bfloat162float(hi));
    }
}

// ---------------- rmsnorm (fp16 hi/lo out, for lm_head) ---------------------
__global__ void rmsnorm_h_kernel(const float* __restrict__ src,
                                 __half* __restrict__ oh, __half* __restrict__ ol) {
    int t = blockIdx.x;
    const float* xp = src + (long)t * DD;
    int tid = threadIdx.x;
    float v[3]; float s = 0.f;
    #pragma unroll
    for (int j = 0; j < 3; j++) { v[j] = xp[tid + j * 256]; s += v[j] * v[j]; }
    __shared__ float red[256];
    red[tid] = s; __syncthreads();
    for (int o = 128; o; o >>= 1) { if (tid < o) red[tid] += red[tid + o]; __syncthreads(); }
    float inv = rsqrtf(red[0] * (1.0f / DD) + 1e-6f);
    #pragma unroll
    for (int j = 0; j < 3; j++) {
        float w = v[j] * inv;
        long id = (long)t * DD + tid + j * 256;
        __half hi = __float2half_rn(w);
        oh[id] = hi;
        ol[id] = __float2half_rn(w - __half2float(hi));
    }
}

// ---------------- value-embedding gate add (v slice of qkv) ------------------
__global__ void ve_kernel(const bf16* __restrict__ xnh, const bf16* __restrict__ xnl,
                          float* __restrict__ qkv,
                          const int* __restrict__ idx,
                          const float* __restrict__ ve_table,
                          const float* __restrict__ ve_gate) {
    int tok  = blockIdx.x;
    int tid  = threadIdx.x;           // 128
    int warp = tid >> 5, lane = tid & 31;
    __shared__ float gates[KVH_];
    float xv = __bfloat162float(xnh[(long)tok * DD + lane]) +
               __bfloat162float(xnl[(long)tok * DD + lane]);
    float g = xv * ve_gate[warp * 32 + lane];
    #pragma unroll
    for (int o = 16; o; o >>= 1) g += __shfl_down_sync(0xffffffffu, g, o);
    if (lane == 0) gates[warp] = 2.0f / (1.0f + expf(-g));
    __syncthreads();
    const float* vt = ve_table + (long)idx[tok] * 256;
    float* v = qkv + (long)tok * QKVD + 1024;
    for (int i = tid; i < 256; i += 128)
        v[i] += gates[i >> 6] * vt[i];
}

// ---------------- rope + per-head rmsnorm -> bf16 hi/lo q/k -----------------
__global__ void ropenorm_kernel(const float* __restrict__ qkv,
                                bf16* __restrict__ qah, bf16* __restrict__ qal,
                                bf16* __restrict__ kah, bf16* __restrict__ kal) {
    int bid = blockIdx.x;
    int hh  = bid & 15;               // 0..11 q heads, 12..15 k heads
    int tok = bid >> 4;
    int t   = tok % TT;
    int b   = tok / TT;
    const float* ptr = qkv + (long)tok * QKVD + (hh < HH ? hh * HD_ : DD + (hh - HH) * HD_);
    int d = threadIdx.x;              // 64
    __shared__ float sv[HD_];
    __shared__ float red[HD_];
    sv[d] = ptr[d];
    __syncthreads();
    int j = d & 31;
    float invf = 1.0f / powf(10000.0f, (float)(2 * j) * (1.0f / 64.0f));
    float ang  = (float)t * invf;
    float cv = cosf(ang), sn = sinf(ang);
    float x1 = sv[j], x2 = sv[j + 32];
    float r = (d < 32) ? (x1 * cv + x2 * sn) : (x2 * cv - x1 * sn);
    red[d] = r * r; __syncthreads();
    for (int o = 32; o; o >>= 1) { if (d < o) red[d] += red[d + o]; __syncthreads(); }
    float inv = rsqrtf(red[0] * (1.0f / HD_) + 1e-6f);
    float val = r * inv;
    if (hh < HH) {
        val *= 0.125f;  // fold 1/sqrt(hd) into q
        long id = (((long)b * HH + hh) * TT + t) * HD_ + d;
        bf16 hi = __float2bfloat16(val);
        qah[id] = hi;
        qal[id] = __float2bfloat16(val - __bfloat162float(hi));
    } else {
        long id = (((long)b * KVH_ + (hh - HH)) * TT + t) * HD_ + d;
        bf16 hi = __float2bfloat16(val);
        kah[id] = hi;
        kal[id] = __float2bfloat16(val - __bfloat162float(hi));
    }
}

// ---------------- v slice: convert + transpose to [b][kvh][hd][T] -----------
__global__ void vcvt_kernel(const float* __restrict__ qkv,
                            bf16* __restrict__ vth, bf16* __restrict__ vtl) {
    __shared__ float tile[32][33];
    int t0 = blockIdx.x * 32, d0 = blockIdx.y * 32;
    int bk = blockIdx.z; int b = bk / KVH_, kv = bk % KVH_;
    int tx = threadIdx.x, ty = threadIdx.y;    // (32, 8)
    #pragma unroll
    for (int j = 0; j < 4; j++) {
        int t = t0 + ty + j * 8;
        tile[ty + j * 8][tx] = qkv[(long)(b * TT + t) * QKVD + 1024 + kv * HD_ + d0 + tx];
    }
    __syncthreads();
    #pragma unroll
    for (int j = 0; j < 4; j++) {
        int d = d0 + ty + j * 8;
        float v = tile[tx][ty + j * 8];
        bf16 hi = __float2bfloat16(v);
        long o = (((long)b * KVH_ + kv) * HD_ + d) * TT + t0 + tx;
        vth[o] = hi;
        vtl[o] = __float2bfloat16(v - __bfloat162float(hi));
    }
}

// ---------------- mma flash attention ---------------------------------------
// grid (T/64, H, B), 128 threads (4 warps, warp w = q rows w*16..+16).
// smem elems: Qh[0,4608) Ql[4608,9216); stage s @9216+s*18432: Kh,Kl,Vh,Vl each 4608 (64x72).
#define ATT_SMEM (46080 * 2)
__device__ __forceinline__ void split_pack(float a, float b, uint32_t& hi, uint32_t& lo) {
    __nv_bfloat162 h2, l2;
    h2.x = __float2bfloat16(a); h2.y = __float2bfloat16(b);
    l2.x = __float2bfloat16(a - __bfloat162float(h2.x));
    l2.y = __float2bfloat16(b - __bfloat162float(h2.y));
    hi = *(uint32_t*)&h2; lo = *(uint32_t*)&l2;
}

__global__ __launch_bounds__(128) void attn_mma(
    const bf16* __restrict__ qah, const bf16* __restrict__ qal,
    const bf16* __restrict__ kah, const bf16* __restrict__ kal,
    const bf16* __restrict__ vth, const bf16* __restrict__ vtl,
    bf16* __restrict__ yh, bf16* __restrict__ yl, int win) {
    extern __shared__ bf16 smA[];
    const int qt = blockIdx.x, h = blockIdx.y, b = blockIdx.z;
    const int kvh = h / (HH / KVH_);
    const int tid = threadIdx.x, w = tid >> 5, lane = tid & 31;
    const int g = lane >> 2, cc = lane & 3;
    const int q0 = qt * 64;
    uint32_t sb = (uint32_t)__cvta_generic_to_shared(smA);

    // load Q (hi+lo), group 1
    const bf16* Qh_g = qah + (((long)b * HH + h) * TT + q0) * HD_;
    const bf16* Ql_g = qal + (((long)b * HH + h) * TT + q0) * HD_;
    #pragma unroll
    for (int it = 0; it < 8; it++) {
        int id = tid + it * 128;
        int mat = id >> 9, rem = id & 511, row = rem >> 3, seg = rem & 7;
        const bf16* src = (mat ? Ql_g : Qh_g) + row * HD_ + seg * 8;
        CP16(sb + (mat * 4608 + row * 72 + seg * 8) * 2, src);
    }
    CP_COMMIT();

    int lo_ = q0 - win + 1;
    int kt0 = lo_ > 0 ? (lo_ >> 6) : 0;
    int nkt = qt - kt0 + 1;

    const bf16* Kh_g = kah + (((long)b * KVH_ + kvh) * TT) * HD_;
    const bf16* Kl_g = kal + (((long)b * KVH_ + kvh) * TT) * HD_;
    const bf16* Vh_g = vth + ((long)b * KVH_ + kvh) * HD_ * TT;
    const bf16* Vl_g = vtl + ((long)b * KVH_ + kvh) * HD_ * TT;

    auto issue_kv = [&](int i) {
        int kt = kt0 + i, s = i & 1;
        uint32_t st = sb + (9216 + s * 18432) * 2;
        #pragma unroll
        for (int it = 0; it < 16; it++) {
            int id = tid + it * 128;
            int mat = id >> 9, rem = id & 511, row = rem >> 3, seg = rem & 7;
            const bf16* src;
            if (mat == 0)      src = Kh_g + (long)(kt * 64 + row) * HD_ + seg * 8;
            else if (mat == 1) src = Kl_g + (long)(kt * 64 + row) * HD_ + seg * 8;
            else if (mat == 2) src = Vh_g + (long)row * TT + kt * 64 + seg * 8;
            else               src = Vl_g + (long)row * TT + kt * 64 + seg * 8;
            CP16(st + (mat * 4608 + row * 72 + seg * 8) * 2, src);
        }
        CP_COMMIT();
    };

    issue_kv(0);
    if (nkt > 1) {
        issue_kv(1);
        // groups: Q, kv0, kv1 — allow only kv1 pending so Q AND kv0 are complete
        asm volatile("cp.async.wait_group 1;\n");
    } else {
        // groups: Q, kv0 — everything must be complete
        asm volatile("cp.async.wait_group 0;\n");
    }
    __syncthreads();

    // Q fragments (resident for whole block)
    uint32_t qA[4][2][4];
    #pragma unroll
    for (int ks = 0; ks < 4; ks++)
        #pragma unroll
        for (int hl = 0; hl < 2; hl++) {
            uint32_t addr = sb + (hl * 4608 + (w * 16 + (lane & 15)) * 72 + ks * 16 + (lane >> 4) * 8) * 2;
            LDM4(qA[ks][hl], addr);
        }

    float oacc[8][4];
    #pragma unroll
    for (int t2 = 0; t2 < 8; t2++)
        #pragma unroll
        for (int e = 0; e < 4; e++) oacc[t2][e] = 0.f;
    float m0 = -1e30f, m1 = -1e30f, l0 = 0.f, l1 = 0.f;

    for (int i = 0; i < nkt; i++) {
        int kt = kt0 + i, s = i & 1;
        if (i > 0) {
            if (i + 1 < nkt) asm volatile("cp.async.wait_group 1;\n");
            else             asm volatile("cp.async.wait_group 0;\n");
            __syncthreads();
        }
        uint32_t stK = sb + (9216 + s * 18432) * 2;
        uint32_t stV = stK + 9216 * 2;

        // ---- S = Q K^T (3-pass hi/lo) ----
        float sacc[8][4];
        #pragma unroll
        for (int t2 = 0; t2 < 8; t2++)
            #pragma unroll
            for (int e = 0; e < 4; e++) sacc[t2][e] = 0.f;
        #pragma unroll
        for (int ks = 0; ks < 4; ks++) {
            uint32_t bK[2][4][4];
            #pragma unroll
            for (int p2 = 0; p2 < 4; p2++)
                #pragma unroll
                for (int hl = 0; hl < 2; hl++) {
                    uint32_t addr = stK + (hl * 4608 +
                        (p2 * 16 + (lane & 7) + ((lane >> 4) & 1) * 8) * 72 +
                        ks * 16 + ((lane >> 3) & 1) * 8) * 2;
                    LDM4(bK[hl][p2], addr);
                }
            #pragma unroll
            for (int p2 = 0; p2 < 4; p2++)
                #pragma unroll
                for (int t = 0; t < 2; t++) {
                    int tile = 2 * p2 + t;
                    uint32_t bh0 = bK[0][p2][t * 2], bh1 = bK[0][p2][t * 2 + 1];
                    uint32_t bl0 = bK[1][p2][t * 2], bl1 = bK[1][p2][t * 2 + 1];
                    MMA_BF16(sacc[tile], qA[ks][0], bh0, bh1);
                    MMA_BF16(sacc[tile], qA[ks][0], bl0, bl1);
                    MMA_BF16(sacc[tile], qA[ks][1], bh0, bh1);
                }
        }

        // ---- mask (diagonal + leading window-clip tile) ----
        if (kt == qt || (q0 + 63 - kt * 64) >= win) {
            #pragma unroll
            for (int tile = 0; tile < 8; tile++)
                #pragma unroll
                for (int e = 0; e < 4; e++) {
                    int rowg = q0 + w * 16 + g + (e >> 1) * 8;
                    int colg = kt * 64 + tile * 8 + cc * 2 + (e & 1);
                    int diff = rowg - colg;
                    if (diff < 0 || diff >= win) sacc[tile][e] = -1e30f;
                }
        }

        // ---- online softmax ----
        float r0 = -1e30f, r1 = -1e30f;
        #pragma unroll
        for (int tile = 0; tile < 8; tile++) {
            r0 = fmaxf(r0, fmaxf(sacc[tile][0], sacc[tile][1]));
            r1 = fmaxf(r1, fmaxf(sacc[tile][2], sacc[tile][3]));
        }
        r0 = fmaxf(r0, __shfl_xor_sync(0xffffffffu, r0, 1));
        r0 = fmaxf(r0, __shfl_xor_sync(0xffffffffu, r0, 2));
        r1 = fmaxf(r1, __shfl_xor_sync(0xffffffffu, r1, 1));
        r1 = fmaxf(r1, __shfl_xor_sync(0xffffffffu, r1, 2));
        float mn0 = fmaxf(m0, r0), mn1 = fmaxf(m1, r1);
        float f0 = __expf(m0 - mn0), f1 = __expf(m1 - mn1);
        m0 = mn0; m1 = mn1;
        float s0 = 0.f, s1 = 0.f;
        #pragma unroll
        for (int tile = 0; tile < 8; tile++) {
            sacc[tile][0] = __expf(sacc[tile][0] - mn0);
            sacc[tile][1] = __expf(sacc[tile][1] - mn0);
            sacc[tile][2] = __expf(sacc[tile][2] - mn1);
            sacc[tile][3] = __expf(sacc[tile][3] - mn1);
            s0 += sacc[tile][0] + sacc[tile][1];
            s1 += sacc[tile][2] + sacc[tile][3];
        }
        s0 += __shfl_xor_sync(0xffffffffu, s0, 1);
        s0 += __shfl_xor_sync(0xffffffffu, s0, 2);
        s1 += __shfl_xor_sync(0xffffffffu, s1, 1);
        s1 += __shfl_xor_sync(0xffffffffu, s1, 2);
        l0 = l0 * f0 + s0;
        l1 = l1 * f1 + s1;
        #pragma unroll
        for (int tile = 0; tile < 8; tile++) {
            oacc[tile][0] *= f0; oacc[tile][1] *= f0;
            oacc[tile][2] *= f1; oacc[tile][3] *= f1;
        }

        // ---- P fragments (hi/lo) ----
        uint32_t pAh[4][4], pAl[4][4];
        #pragma unroll
        for (int ks = 0; ks < 4; ks++) {
            split_pack(sacc[2*ks][0],   sacc[2*ks][1],   pAh[ks][0], pAl[ks][0]);
            split_pack(sacc[2*ks][2],   sacc[2*ks][3],   pAh[ks][1], pAl[ks][1]);
            split_pack(sacc[2*ks+1][0], sacc[2*ks+1][1], pAh[ks][2], pAl[ks][2]);
            split_pack(sacc[2*ks+1][2], sacc[2*ks+1][3], pAh[ks][3], pAl[ks][3]);
        }

        // ---- O += P V (3-pass hi/lo) ----
        #pragma unroll
        for (int ks = 0; ks < 4; ks++) {
            uint32_t bV[2][4][4];
            #pragma unroll
            for (int p2 = 0; p2 < 4; p2++)
                #pragma unroll
                for (int hl = 0; hl < 2; hl++) {
                    uint32_t addr = stV + (hl * 4608 +
                        (p2 * 16 + (lane & 7) + ((lane >> 4) & 1) * 8) * 72 +
                        ks * 16 + ((lane >> 3) & 1) * 8) * 2;
                    LDM4(bV[hl][p2], addr);
                }
            #pragma unroll
            for (int p2 = 0; p2 < 4; p2++)
                #pragma unroll
                for (int t = 0; t < 2; t++) {
                    int tile = 2 * p2 + t;
                    uint32_t vh0 = bV[0][p2][t * 2], vh1 = bV[0][p2][t * 2 + 1];
                    uint32_t vl0 = bV[1][p2][t * 2], vl1 = bV[1][p2][t * 2 + 1];
                    MMA_BF16(oacc[tile], pAh[ks], vh0, vh1);
                    MMA_BF16(oacc[tile], pAh[ks], vl0, vl1);
                    MMA_BF16(oacc[tile], pAl[ks], vh0, vh1);
                }
        }

        __syncthreads();
        if (i + 2 < nkt) issue_kv(i + 2);
    }

    float inv0 = 1.f / l0, inv1 = 1.f / l1;
    long tok0 = (long)b * TT + q0 + w * 16 + g;
    long tok1 = tok0 + 8;
    #pragma unroll
    for (int tile = 0; tile < 8; tile++) {
        int col = h * HD_ + tile * 8 + cc * 2;
        uint32_t hi0, lo0, hi1, lo1;
        split_pack(oacc[tile][0] * inv0, oacc[tile][1] * inv0, hi0, lo0);
        split_pack(oacc[tile][2] * inv1, oacc[tile][3] * inv1, hi1, lo1);
        *(uint32_t*)&yh[tok0 * DD + col] = hi0;
        *(uint32_t*)&yl[tok0 * DD + col] = lo0;
        *(uint32_t*)&yh[tok1 * DD + col] = hi1;
        *(uint32_t*)&yl[tok1 * DD + col] = lo1;
    }
}

// ---------------- bf16-split tensor-core NT GEMM (3-pass) -------------------
template <int EPI>
__global__ __launch_bounds__(256, 1) void gemm_bb(
    const bf16* __restrict__ Ah, const bf16* __restrict__ Al,
    const bf16* __restrict__ Bh, const bf16* __restrict__ Bl,
    float* __restrict__ C, bf16* __restrict__ Ch, bf16* __restrict__ Cl,
    int M, int N, int K) {
    extern __shared__ bf16 sm[];
    const int tid = threadIdx.x;
    const int wid = tid >> 5, lane = tid & 31;
    const int wm = wid & 3, wn = wid >> 2;
    const int bm = blockIdx.y << 7, bn = blockIdx.x << 7;

    float acc[2][8][4];
    #pragma unroll
    for (int i = 0; i < 2; i++)
        #pragma unroll
        for (int j = 0; j < 8; j++)
            #pragma unroll
            for (int e = 0; e < 4; e++) acc[i][j][e] = 0.f;

    const int nc = K >> 5;

    auto issue = [&](int c, int s) {
        int k0 = c << 5;
        #pragma unroll
        for (int it = 0; it < 4; it++) {
            int t = tid + it * 256;
            int hl = t >> 9, rem = t & 511, row = rem >> 2, seg = rem & 3;
            const bf16* g = (hl ? Al : Ah) + (long)(bm + row) * K + k0 + seg * 8;
            uint32_t sa = (uint32_t)__cvta_generic_to_shared(sm + s * 20480 + hl * 5120 + row * 40 + seg * 8);
            CP16(sa, g);
        }
        #pragma unroll
        for (int it = 0; it < 4; it++) {
            int t = tid + it * 256;
            int hl = t >> 9, rem = t & 511, row = rem >> 2, seg = rem & 3;
            const bf16* g = (hl ? Bl : Bh) + (long)(bn + row) * K + k0 + seg * 8;
            uint32_t sa = (uint32_t)__cvta_generic_to_shared(sm + s * 20480 + 10240 + hl * 5120 + row * 40 + seg * 8);
            CP16(sa, g);
        }
        CP_COMMIT();
    };

    issue(0, 0);
    for (int c = 0; c < nc; c++) {
        int s = c & 1;
        if (c + 1 < nc) {
            issue(c + 1, s ^ 1);
            asm volatile("cp.async.wait_group 1;\n");
        } else {
            asm volatile("cp.async.wait_group 0;\n");
        }
        __syncthreads();

        const bf16* As = sm + s * 20480;
        const bf16* Bs = sm + s * 20480 + 10240;
        #pragma unroll
        for (int kk = 0; kk < 2; kk++) {
            uint32_t a[2][2][4];
            #pragma unroll
            for (int i = 0; i < 2; i++)
                #pragma unroll
                for (int hl = 0; hl < 2; hl++) {
                    uint32_t addr = (uint32_t)__cvta_generic_to_shared(
                        As + hl * 5120 + (wm * 32 + i * 16 + (lane & 15)) * 40 + kk * 16 + (lane >> 4) * 8);
                    LDM4(a[i][hl], addr);
                }
            uint32_t bfr[4][2][4];
            #pragma unroll
            for (int p2 = 0; p2 < 4; p2++)
                #pragma unroll
                for (int hl = 0; hl < 2; hl++) {
                    int row = wn * 64 + p2 * 16 + (lane & 7) + ((lane >> 4) & 1) * 8;
                    int col = kk * 16 + ((lane >> 3) & 1) * 8;
                    uint32_t addr = (uint32_t)__cvta_generic_to_shared(Bs + hl * 5120 + row * 40 + col);
                    LDM4(bfr[p2][hl], addr);
                }
            #pragma unroll
            for (int i = 0; i < 2; i++)
                #pragma unroll
                for (int j = 0; j < 8; j++) {
                    int p2 = j >> 1, half = j & 1;
                    uint32_t bh0 = bfr[p2][0][half * 2], bh1 = bfr[p2][0][half * 2 + 1];
                    uint32_t bl0 = bfr[p2][1][half * 2], bl1 = bfr[p2][1][half * 2 + 1];
                    MMA_BF16(acc[i][j], a[i][0], bh0, bh1);
                    MMA_BF16(acc[i][j], a[i][0], bl0, bl1);
                    MMA_BF16(acc[i][j], a[i][1], bh0, bh1);
                }
        }
        __syncthreads();
    }

    #pragma unroll
    for (int i = 0; i < 2; i++) {
        int r0 = bm + wm * 32 + i * 16 + (lane >> 2);
        #pragma unroll
        for (int j = 0; j < 8; j++) {
            int col = bn + wn * 64 + j * 8 + (lane & 3) * 2;
            #pragma unroll
            for (int e = 0; e < 4; e++) {
                int rr = r0 + (e >> 1) * 8;
                int cid = col + (e & 1);
                long id = (long)rr * N + cid;
                float val = acc[i][j][e];
                if (EPI == 0)      C[id] = val;
                else if (EPI == 1) C[id] += val;
                else if (EPI == 2) {
                    float r = fmaxf(val, 0.f); r = r * r;
                    bf16 hi = __float2bfloat16(r);
                    Ch[id] = hi;
                    Cl[id] = __float2bfloat16(r - __bfloat162float(hi));
                }
                else C[id] = 15.0f * tanhf(val * (1.0f / 15.0f));
            }
        }
    }
}

// ---------------- fp16 2-pass GEMM for lm_head (3-stage pipeline) -----------
__global__ __launch_bounds__(256, 1) void gemm_lm(
    const __half* __restrict__ Ah, const __half* __restrict__ Al,
    const __half* __restrict__ Bf,
    float* __restrict__ C, int M, int N, int K) {
    extern __shared__ __half smh[];
    const int tid = threadIdx.x;
    const int wid = tid >> 5, lane = tid & 31;
    const int wm = wid & 3, wn = wid >> 2;
    const int bm = blockIdx.y << 7, bn = blockIdx.x << 7;

    float acc[2][8][4];
    #pragma unroll
    for (int i = 0; i < 2; i++)
        #pragma unroll
        for (int j = 0; j < 8; j++)
            #pragma unroll
            for (int e = 0; e < 4; e++) acc[i][j][e] = 0.f;

    const int nc = K >> 5;

    auto issue = [&](int c, int s) {
        int k0 = c << 5;
        #pragma unroll
        for (int it = 0; it < 6; it++) {
            int t = tid + it * 256;
            uint32_t sa; const __half* g;
            if (t < 1024) {
                int hl = t >> 9, rem = t & 511, row = rem >> 2, seg = rem & 3;
                g = (hl ? Al : Ah) + (long)(bm + row) * K + k0 + seg * 8;
                sa = (uint32_t)__cvta_generic_to_shared(smh + s * 15360 + hl * 5120 + row * 40 + seg * 8);
            } else {
                int t2 = t - 1024;
                int row = t2 >> 2, seg = t2 & 3;
                g = Bf + (long)(bn + row) * K + k0 + seg * 8;
                sa = (uint32_t)__cvta_generic_to_shared(smh + s * 15360 + 10240 + row * 40 + seg * 8);
            }
            CP16(sa, g);
        }
        CP_COMMIT();
    };

    issue(0, 0);
    issue(1, 1);
    for (int c = 0; c < nc; c++) {
        int s = c % 3;
        if (c + 2 < nc) {
            issue(c + 2, (c + 2) % 3);
            asm volatile("cp.async.wait_group 2;\n");
        } else if (c + 1 < nc) {
            asm volatile("cp.async.wait_group 1;\n");
        } else {
            asm volatile("cp.async.wait_group 0;\n");
        }
        __syncthreads();

        const __half* As = smh + s * 15360;
        const __half* Bs = smh + s * 15360 + 10240;
        #pragma unroll
        for (int kk = 0; kk < 2; kk++) {
            uint32_t a[2][2][4];
            #pragma unroll
            for (int i = 0; i < 2; i++)
                #pragma unroll
                for (int hl = 0; hl < 2; hl++) {
                    uint32_t addr = (uint32_t)__cvta_generic_to_shared(
                        As + hl * 5120 + (wm * 32 + i * 16 + (lane & 15)) * 40 + kk * 16 + (lane >> 4) * 8);
                    LDM4(a[i][hl], addr);
                }
            uint32_t bfr[4][4];
            #pragma unroll
            for (int p2 = 0; p2 < 4; p2++) {
                int row = wn * 64 + p2 * 16 + (lane & 7) + ((lane >> 4) & 1) * 8;
                int col = kk * 16 + ((lane >> 3) & 1) * 8;
                uint32_t addr = (uint32_t)__cvta_generic_to_shared(Bs + row * 40 + col);
                LDM4(bfr[p2], addr);
            }
            #pragma unroll
            for (int i = 0; i < 2; i++)
                #pragma unroll
                for (int j = 0; j < 8; j++) {
                    int p2 = j >> 1, half = j & 1;
                    uint32_t b0 = bfr[p2][half * 2], b1 = bfr[p2][half * 2 + 1];
                    MMA_F16(acc[i][j], a[i][0], b0, b1);
                    MMA_F16(acc[i][j], a[i][1], b0, b1);
                }
        }
        __syncthreads();
    }

    #pragma unroll
    for (int i = 0; i < 2; i++) {
        int r0 = bm + wm * 32 + i * 16 + (lane >> 2);
        #pragma unroll
        for (int j = 0; j < 8; j++) {
            int col = bn + wn * 64 + j * 8 + (lane & 3) * 2;
            #pragma unroll
            for (int e = 0; e < 4; e++) {
                int rr = r0 + (e >> 1) * 8;
                int cid = col + (e & 1);
                C[(long)rr * N + cid] = 15.0f * tanhf(acc[i][j][e] * (1.0f / 15.0f));
            }
        }
    }
}

// ---------------- orchestration ---------------------------------------------
extern "C" void kernel_launch(void* const* d_in, const int* in_sizes, int n_in,
                              void* d_out, int out_size) {
    const int*   idx  = (const int*)  d_in[0];
    const float* wte  = (const float*)d_in[1];
    const float* Wq   = (const float*)d_in[2];
    const float* Wk   = (const float*)d_in[3];
    const float* Wv   = (const float*)d_in[4];
    const float* Wo   = (const float*)d_in[5];
    const float* Wfc  = (const float*)d_in[6];
    const float* Wpr  = (const float*)d_in[7];
    const float* veT  = (const float*)d_in[8];
    const float* veG  = (const float*)d_in[9];
    const float* rl   = (const float*)d_in[10];
    const float* xl   = (const float*)d_in[11];
    const float* lm   = (const float*)d_in[12];
    float* out = (float*)d_out;

    float *x, *x0, *qkv;
    bf16 *xnh, *xnl, *yh, *yl, *hh, *hl;
    bf16 *qa_h, *qa_l, *ka_h, *ka_l, *vt_h, *vt_l;
    __half *xnfh, *xnfl, *lmf;
    bf16 *wqkvh, *wqkvl, *woh, *wol, *wfch, *wfcl, *wprh, *wprl;
    cudaGetSymbolAddress((void**)&x,   g_x);
    cudaGetSymbolAddress((void**)&x0,  g_x0);
    cudaGetSymbolAddress((void**)&qkv, g_qkv);
    cudaGetSymbolAddress((void**)&xnh, g_xn_h);  cudaGetSymbolAddress((void**)&xnl, g_xn_l);
    cudaGetSymbolAddress((void**)&yh,  g_y_h);   cudaGetSymbolAddress((void**)&yl,  g_y_l);
    cudaGetSymbolAddress((void**)&hh,  g_h_h);   cudaGetSymbolAddress((void**)&hl,  g_h_l);
    cudaGetSymbolAddress((void**)&qa_h, g_qah);  cudaGetSymbolAddress((void**)&qa_l, g_qal);
    cudaGetSymbolAddress((void**)&ka_h, g_kah);  cudaGetSymbolAddress((void**)&ka_l, g_kal);
    cudaGetSymbolAddress((void**)&vt_h, g_vth);  cudaGetSymbolAddress((void**)&vt_l, g_vtl);
    cudaGetSymbolAddress((void**)&xnfh, g_xn_fh); cudaGetSymbolAddress((void**)&xnfl, g_xn_fl);
    cudaGetSymbolAddress((void**)&wqkvh, g_wqkv_h); cudaGetSymbolAddress((void**)&wqkvl, g_wqkv_l);
    cudaGetSymbolAddress((void**)&woh, g_wo_h);  cudaGetSymbolAddress((void**)&wol, g_wo_l);
    cudaGetSymbolAddress((void**)&wfch, g_wfc_h); cudaGetSymbolAddress((void**)&wfcl, g_wfc_l);
    cudaGetSymbolAddress((void**)&wprh, g_wpr_h); cudaGetSymbolAddress((void**)&wprl, g_wpr_l);
    cudaGetSymbolAddress((void**)&lmf, g_lm_f);

    const int GEMM_SMEM = 81920;
    cudaFuncSetAttribute(gemm_bb<0>, cudaFuncAttributeMaxDynamicSharedMemorySize, GEMM_SMEM);
    cudaFuncSetAttribute(gemm_bb<1>, cudaFuncAttributeMaxDynamicSharedMemorySize, GEMM_SMEM);
    cudaFuncSetAttribute(gemm_bb<2>, cudaFuncAttributeMaxDynamicSharedMemorySize, GEMM_SMEM);
    const int LM_SMEM = 3 * 15360 * 2;  // 92160 bytes
    cudaFuncSetAttribute(gemm_lm, cudaFuncAttributeMaxDynamicSharedMemorySize, LM_SMEM);
    cudaFuncSetAttribute(attn_mma, cudaFuncAttributeMaxDynamicSharedMemorySize, ATT_SMEM);

    // weight conversions
    {
        long n = (long)LL * QKVD * DD;
        cvt_qkv_kernel<<<(int)((n + 255) / 256), 256>>>(Wq, Wk, Wv, wqkvh, wqkvl);
        long n4 = (long)LL * DD * DD / 4;
        cvt4_kernel<<<(int)((n4 + 255) / 256), 256>>>((const float4*)Wo,
            (__nv_bfloat162*)woh, (__nv_bfloat162*)wol, n4);
        n4 = (long)LL * FF * DD / 4;
        cvt4_kernel<<<(int)((n4 + 255) / 256), 256>>>((const float4*)Wfc,
            (__nv_bfloat162*)wfch, (__nv_bfloat162*)wfcl, n4);
        cvt4_kernel<<<(int)((n4 + 255) / 256), 256>>>((const float4*)Wpr,
            (__nv_bfloat162*)wprh, (__nv_bfloat162*)wprl, n4);
        n4 = (long)VV * DD / 4;
        cvt_half4_kernel<<<(int)((n4 + 255) / 256), 256>>>((const float4*)lm, (__half2*)lmf, n4);
    }

    embed_norm_kernel<<<BT, 256>>>(wte, idx, x, x0);

    for (int i = 0; i < LL; i++) {
        resid_norm_kernel<<<BT, 256>>>(x, x0, rl, xl, i, xnh, xnl);

        gemm_bb<0><<<dim3(QKVD / 128, BT / 128), 256, GEMM_SMEM>>>(
            xnh, xnl, wqkvh + (long)i * QKVD * DD, wqkvl + (long)i * QKVD * DD,
            qkv, nullptr, nullptr, BT, QKVD, DD);

        int j = (i == 1) ? 0 : (i == 3) ? 1 : (i == 5) ? 2 : -1;
        if (j >= 0)
            ve_kernel<<<BT, 128>>>(xnh, xnl, qkv, idx,
                                   veT + (long)j * VV * 256, veG + j * KVH_ * 32);

        ropenorm_kernel<<<BT * 16, HD_>>>(qkv, qa_h, qa_l, ka_h, ka_l);
        vcvt_kernel<<<dim3(TT / 32, 2, BB * KVH_), dim3(32, 8)>>>(qkv, vt_h, vt_l);

        int win = (i % 2 == 0) ? (TT / 2) : TT;
        attn_mma<<<dim3(TT / 64, HH, BB), 128, ATT_SMEM>>>(
            qa_h, qa_l, ka_h, ka_l, vt_h, vt_l, yh, yl, win);

        gemm_bb<1><<<dim3(DD / 128, BT / 128), 256, GEMM_SMEM>>>(
            yh, yl, woh + (long)i * DD * DD, wol + (long)i * DD * DD,
            x, nullptr, nullptr, BT, DD, DD);

        rmsnorm_kernel<<<BT, 256>>>(x, xnh, xnl);
        gemm_bb<2><<<dim3(FF / 128, BT / 128), 256, GEMM_SMEM>>>(
            xnh, xnl, wfch + (long)i * FF * DD, wfcl + (long)i * FF * DD,
            nullptr, hh, hl, BT, FF, DD);
        gemm_bb<1><<<dim3(DD / 128, BT / 128), 256, GEMM_SMEM>>>(
            hh, hl, wprh + (long)i * DD * FF, wprl + (long)i * DD * FF,
            x, nullptr, nullptr, BT, DD, FF);
    }

    rmsnorm_h_kernel<<<BT, 256>>>(x, xnfh, xnfl);
    gemm_lm<<<dim3(VV / 128, BT / 128), 256, LM_SMEM>>>(
        xnfh, xnfl, lmf, out, BT, VV, DD);
}

// round 9
// speedup vs baseline: 4.0995x; 1.0578x over previous
#include <cuda_runtime.h>
#include <cuda_bf16.h>
#include <cuda_fp16.h>
#include <stdint.h>
#include <math.h>

#define VV   32000
#define DD   768
#define HH   12
#define KVH_ 4
#define LL   6
#define TT   1024
#define HD_  64
#define BB   2
#define BT   2048
#define FF   3072
#define QKVD 1280   // 768 q + 256 k + 256 v

typedef __nv_bfloat16 bf16;

#define CP16(dst, src)    asm volatile("cp.async.cg.shared.global [%0],[%1],16;\n" :: "r"(dst), "l"(src))
#define CP_COMMIT()       asm volatile("cp.async.commit_group;\n")
#define LDM4(r, addr) \
    asm volatile("ldmatrix.sync.aligned.m8n8.x4.shared.b16 {%0,%1,%2,%3},[%4];\n" \
        : "=r"((r)[0]), "=r"((r)[1]), "=r"((r)[2]), "=r"((r)[3]) : "r"(addr))

#define MMA_BF16(d, a, b0,b1) \
  asm volatile("mma.sync.aligned.m16n8k16.row.col.f32.bf16.bf16.f32 " \
    "{%0,%1,%2,%3},{%4,%5,%6,%7},{%8,%9},{%0,%1,%2,%3};\n" \
    : "+f"((d)[0]),"+f"((d)[1]),"+f"((d)[2]),"+f"((d)[3]) \
    : "r"((a)[0]),"r"((a)[1]),"r"((a)[2]),"r"((a)[3]),"r"(b0),"r"(b1))

#define MMA_F16(d, a, b0,b1) \
  asm volatile("mma.sync.aligned.m16n8k16.row.col.f32.f16.f16.f32 " \
    "{%0,%1,%2,%3},{%4,%5,%6,%7},{%8,%9},{%0,%1,%2,%3};\n" \
    : "+f"((d)[0]),"+f"((d)[1]),"+f"((d)[2]),"+f"((d)[3]) \
    : "r"((a)[0]),"r"((a)[1]),"r"((a)[2]),"r"((a)[3]),"r"(b0),"r"(b1))

// ---------------- device-global scratch -------------------------------------
__device__ float g_x  [BT*DD];
__device__ float g_x0 [BT*DD];
__device__ float g_qkv[BT*QKVD];

__device__ bf16 g_xn_h[BT*DD], g_xn_l[BT*DD];
__device__ bf16 g_y_h [BT*DD], g_y_l [BT*DD];
__device__ bf16 g_h_h [BT*FF], g_h_l [BT*FF];
__device__ __half g_xn_f[BT*DD];

__device__ bf16 g_qah[BB*HH*TT*HD_],  g_qal[BB*HH*TT*HD_];
__device__ bf16 g_kah[BB*KVH_*TT*HD_], g_kal[BB*KVH_*TT*HD_];
__device__ bf16 g_vth[BB*KVH_*HD_*TT], g_vtl[BB*KVH_*HD_*TT];

__device__ bf16 g_wqkv_h[LL*QKVD*DD], g_wqkv_l[LL*QKVD*DD];
__device__ bf16 g_wo_h  [LL*DD*DD],   g_wo_l  [LL*DD*DD];
__device__ bf16 g_wfc_h [LL*FF*DD],   g_wfc_l [LL*FF*DD];
__device__ bf16 g_wpr_h [LL*DD*FF],   g_wpr_l [LL*DD*FF];
__device__ __half g_lm_f[(long)VV*DD];

// ---------------- fp32 -> bf16 hi/lo conversion (vectorized) -----------------
__global__ void cvt4_kernel(const float4* __restrict__ in, __nv_bfloat162* __restrict__ h2,
                            __nv_bfloat162* __restrict__ l2, long n4) {
    long i = (long)blockIdx.x * 256 + threadIdx.x;
    if (i >= n4) return;
    float4 v = in[i];
    bf16 h0 = __float2bfloat16(v.x), h1 = __float2bfloat16(v.y);
    bf16 h2v = __float2bfloat16(v.z), h3 = __float2bfloat16(v.w);
    __nv_bfloat162 ha; ha.x = h0; ha.y = h1;
    __nv_bfloat162 hb; hb.x = h2v; hb.y = h3;
    h2[i * 2]     = ha;
    h2[i * 2 + 1] = hb;
    __nv_bfloat162 la, lb;
    la.x = __float2bfloat16(v.x - __bfloat162float(h0));
    la.y = __float2bfloat16(v.y - __bfloat162float(h1));
    lb.x = __float2bfloat16(v.z - __bfloat162float(h2v));
    lb.y = __float2bfloat16(v.w - __bfloat162float(h3));
    l2[i * 2]     = la;
    l2[i * 2 + 1] = lb;
}

// per-layer block remap: dst4 = layer*dstStride4 + dstOff4 + rem
__global__ void cvt4_off_kernel(const float4* __restrict__ in, __nv_bfloat162* __restrict__ h2,
                                __nv_bfloat162* __restrict__ l2, long n4,
                                long per4, long dstStride4, long dstOff4) {
    long i = (long)blockIdx.x * 256 + threadIdx.x;
    if (i >= n4) return;
    long layer = i / per4, rem = i % per4;
    long d = layer * dstStride4 + dstOff4 + rem;
    float4 v = in[i];
    bf16 h0 = __float2bfloat16(v.x), h1 = __float2bfloat16(v.y);
    bf16 h2v = __float2bfloat16(v.z), h3 = __float2bfloat16(v.w);
    __nv_bfloat162 ha; ha.x = h0; ha.y = h1;
    __nv_bfloat162 hb; hb.x = h2v; hb.y = h3;
    h2[d * 2]     = ha;
    h2[d * 2 + 1] = hb;
    __nv_bfloat162 la, lb;
    la.x = __float2bfloat16(v.x - __bfloat162float(h0));
    la.y = __float2bfloat16(v.y - __bfloat162float(h1));
    lb.x = __float2bfloat16(v.z - __bfloat162float(h2v));
    lb.y = __float2bfloat16(v.w - __bfloat162float(h3));
    l2[d * 2]     = la;
    l2[d * 2 + 1] = lb;
}

__global__ void cvt_half4_kernel(const float4* __restrict__ in, __half2* __restrict__ o2, long n4) {
    long i = (long)blockIdx.x * 256 + threadIdx.x;
    if (i >= n4) return;
    float4 v = in[i];
    __half2 a; a.x = __float2half_rn(v.x); a.y = __float2half_rn(v.y);
    __half2 b; b.x = __float2half_rn(v.z); b.y = __float2half_rn(v.w);
    o2[i * 2]     = a;
    o2[i * 2 + 1] = b;
}

// ---------------- fused embedding + rmsnorm ---------------------------------
__global__ void embed_norm_kernel(const float* __restrict__ wte,
                                  const int* __restrict__ idx,
                                  float* __restrict__ x, float* __restrict__ x0) {
    int t = blockIdx.x;
    const float* row = wte + (long)idx[t] * DD;
    int tid = threadIdx.x;
    float v[3]; float s = 0.f;
    #pragma unroll
    for (int j = 0; j < 3; j++) { v[j] = row[tid + j * 256]; s += v[j] * v[j]; }
    __shared__ float red[256];
    red[tid] = s; __syncthreads();
    for (int o = 128; o; o >>= 1) { if (tid < o) red[tid] += red[tid + o]; __syncthreads(); }
    float inv = rsqrtf(red[0] * (1.0f / DD) + 1e-6f);
    #pragma unroll
    for (int j = 0; j < 3; j++) {
        float w = v[j] * inv;
        x[(long)t * DD + tid + j * 256]  = w;
        x0[(long)t * DD + tid + j * 256] = w;
    }
}

// ---------------- fused resid-lambda + rmsnorm ------------------------------
__global__ void resid_norm_kernel(float* __restrict__ x, const float* __restrict__ x0,
                                  const float* __restrict__ rl, const float* __restrict__ xl,
                                  int layer, bf16* __restrict__ oh, bf16* __restrict__ ol) {
    int t = blockIdx.x;
    int tid = threadIdx.x;
    float a = rl[layer], b = xl[layer];
    float v[3]; float s = 0.f;
    #pragma unroll
    for (int j = 0; j < 3; j++) {
        long id = (long)t * DD + tid + j * 256;
        float xv = a * x[id] + b * x0[id];
        v[j] = xv; s += xv * xv;
    }
    __shared__ float red[256];
    red[tid] = s; __syncthreads();
    for (int o = 128; o; o >>= 1) { if (tid < o) red[tid] += red[tid + o]; __syncthreads(); }
    float inv = rsqrtf(red[0] * (1.0f / DD) + 1e-6f);
    #pragma unroll
    for (int j = 0; j < 3; j++) {
        long id = (long)t * DD + tid + j * 256;
        x[id] = v[j];
        float w = v[j] * inv;
        bf16 hi = __float2bfloat16(w);
        oh[id] = hi;
        ol[id] = __float2bfloat16(w - __bfloat162float(hi));
    }
}

// ---------------- rmsnorm (bf16 hi/lo out) ----------------------------------
__global__ void rmsnorm_kernel(const float* __restrict__ src,
                               bf16* __restrict__ oh, bf16* __restrict__ ol) {
    int t = blockIdx.x;
    const float* xp = src + (long)t * DD;
    int tid = threadIdx.x;
    float v[3]; float s = 0.f;
    #pragma unroll
    for (int j = 0; j < 3; j++) { v[j] = xp[tid + j * 256]; s += v[j] * v[j]; }
    __shared__ float red[256];
    red[tid] = s; __syncthreads();
    for (int o = 128; o; o >>= 1) { if (tid < o) red[tid] += red[tid + o]; __syncthreads(); }
    float inv = rsqrtf(red[0] * (1.0f / DD) + 1e-6f);
    #pragma unroll
    for (int j = 0; j < 3; j++) {
        float w = v[j] * inv;
        long id = (long)t * DD + tid + j * 256;
        bf16 hi = __float2bfloat16(w);
        oh[id] = hi;
        ol[id] = __float2bfloat16(w - __bfloat162float(hi));
    }
}

// ---------------- rmsnorm (single fp16 out, for lm_head) --------------------
__global__ void rmsnorm_h_kernel(const float* __restrict__ src, __half* __restrict__ oh) {
    int t = blockIdx.x;
    const float* xp = src + (long)t * DD;
    int tid = threadIdx.x;
    float v[3]; float s = 0.f;
    #pragma unroll
    for (int j = 0; j < 3; j++) { v[j] = xp[tid + j * 256]; s += v[j] * v[j]; }
    __shared__ float red[256];
    red[tid] = s; __syncthreads();
    for (int o = 128; o; o >>= 1) { if (tid < o) red[tid] += red[tid + o]; __syncthreads(); }
    float inv = rsqrtf(red[0] * (1.0f / DD) + 1e-6f);
    #pragma unroll
    for (int j = 0; j < 3; j++)
        oh[(long)t * DD + tid + j * 256] = __float2half_rn(v[j] * inv);
}

// ---------------- value-embedding gate add (v slice of qkv) ------------------
__global__ void ve_kernel(const bf16* __restrict__ xnh, const bf16* __restrict__ xnl,
                          float* __restrict__ qkv,
                          const int* __restrict__ idx,
                          const float* __restrict__ ve_table,
                          const float* __restrict__ ve_gate) {
    int tok  = blockIdx.x;
    int tid  = threadIdx.x;           // 128
    int warp = tid >> 5, lane = tid & 31;
    __shared__ float gates[KVH_];
    float xv = __bfloat162float(xnh[(long)tok * DD + lane]) +
               __bfloat162float(xnl[(long)tok * DD + lane]);
    float g = xv * ve_gate[warp * 32 + lane];
    #pragma unroll
    for (int o = 16; o; o >>= 1) g += __shfl_down_sync(0xffffffffu, g, o);
    if (lane == 0) gates[warp] = 2.0f / (1.0f + expf(-g));
    __syncthreads();
    const float* vt = ve_table + (long)idx[tok] * 256;
    float* v = qkv + (long)tok * QKVD + 1024;
    for (int i = tid; i < 256; i += 128)
        v[i] += gates[i >> 6] * vt[i];
}

// ---------------- rope + per-head rmsnorm -> bf16 hi/lo q/k -----------------
__global__ void ropenorm_kernel(const float* __restrict__ qkv,
                                bf16* __restrict__ qah, bf16* __restrict__ qal,
                                bf16* __restrict__ kah, bf16* __restrict__ kal) {
    int bid = blockIdx.x;
    int hh  = bid & 15;               // 0..11 q heads, 12..15 k heads
    int tok = bid >> 4;
    int t   = tok % TT;
    int b   = tok / TT;
    const float* ptr = qkv + (long)tok * QKVD + (hh < HH ? hh * HD_ : DD + (hh - HH) * HD_);
    int d = threadIdx.x;              // 64
    __shared__ float sv[HD_];
    __shared__ float red[HD_];
    sv[d] = ptr[d];
    __syncthreads();
    int j = d & 31;
    float invf = 1.0f / powf(10000.0f, (float)(2 * j) * (1.0f / 64.0f));
    float ang  = (float)t * invf;
    float cv = cosf(ang), sn = sinf(ang);
    float x1 = sv[j], x2 = sv[j + 32];
    float r = (d < 32) ? (x1 * cv + x2 * sn) : (x2 * cv - x1 * sn);
    red[d] = r * r; __syncthreads();
    for (int o = 32; o; o >>= 1) { if (d < o) red[d] += red[d + o]; __syncthreads(); }
    float inv = rsqrtf(red[0] * (1.0f / HD_) + 1e-6f);
    float val = r * inv;
    if (hh < HH) {
        val *= 0.125f;  // fold 1/sqrt(hd) into q
        long id = (((long)b * HH + hh) * TT + t) * HD_ + d;
        bf16 hi = __float2bfloat16(val);
        qah[id] = hi;
        qal[id] = __float2bfloat16(val - __bfloat162float(hi));
    } else {
        long id = (((long)b * KVH_ + (hh - HH)) * TT + t) * HD_ + d;
        bf16 hi = __float2bfloat16(val);
        kah[id] = hi;
        kal[id] = __float2bfloat16(val - __bfloat162float(hi));
    }
}

// ---------------- v slice: convert + transpose to [b][kvh][hd][T] -----------
__global__ void vcvt_kernel(const float* __restrict__ qkv,
                            bf16* __restrict__ vth, bf16* __restrict__ vtl) {
    __shared__ float tile[32][33];
    int t0 = blockIdx.x * 32, d0 = blockIdx.y * 32;
    int bk = blockIdx.z; int b = bk / KVH_, kv = bk % KVH_;
    int tx = threadIdx.x, ty = threadIdx.y;    // (32, 8)
    #pragma unroll
    for (int j = 0; j < 4; j++) {
        int t = t0 + ty + j * 8;
        tile[ty + j * 8][tx] = qkv[(long)(b * TT + t) * QKVD + 1024 + kv * HD_ + d0 + tx];
    }
    __syncthreads();
    #pragma unroll
    for (int j = 0; j < 4; j++) {
        int d = d0 + ty + j * 8;
        float v = tile[tx][ty + j * 8];
        bf16 hi = __float2bfloat16(v);
        long o = (((long)b * KVH_ + kv) * HD_ + d) * TT + t0 + tx;
        vth[o] = hi;
        vtl[o] = __float2bfloat16(v - __bfloat162float(hi));
    }
}

// ---------------- mma flash attention ---------------------------------------
// grid (T/64, H, B), 128 threads (4 warps, warp w = q rows w*16..+16).
// smem elems: Qh[0,4608) Ql[4608,9216); stage s @9216+s*18432: Kh,Kl,Vh,Vl each 4608 (64x72).
#define ATT_SMEM (46080 * 2)
__device__ __forceinline__ void split_pack(float a, float b, uint32_t& hi, uint32_t& lo) {
    __nv_bfloat162 h2, l2;
    h2.x = __float2bfloat16(a); h2.y = __float2bfloat16(b);
    l2.x = __float2bfloat16(a - __bfloat162float(h2.x));
    l2.y = __float2bfloat16(b - __bfloat162float(h2.y));
    hi = *(uint32_t*)&h2; lo = *(uint32_t*)&l2;
}

__global__ __launch_bounds__(128) void attn_mma(
    const bf16* __restrict__ qah, const bf16* __restrict__ qal,
    const bf16* __restrict__ kah, const bf16* __restrict__ kal,
    const bf16* __restrict__ vth, const bf16* __restrict__ vtl,
    bf16* __restrict__ yh, bf16* __restrict__ yl, int win) {
    extern __shared__ bf16 smA[];
    const int qt = blockIdx.x, h = blockIdx.y, b = blockIdx.z;
    const int kvh = h / (HH / KVH_);
    const int tid = threadIdx.x, w = tid >> 5, lane = tid & 31;
    const int g = lane >> 2, cc = lane & 3;
    const int q0 = qt * 64;
    uint32_t sb = (uint32_t)__cvta_generic_to_shared(smA);

    // load Q (hi+lo), group 1
    const bf16* Qh_g = qah + (((long)b * HH + h) * TT + q0) * HD_;
    const bf16* Ql_g = qal + (((long)b * HH + h) * TT + q0) * HD_;
    #pragma unroll
    for (int it = 0; it < 8; it++) {
        int id = tid + it * 128;
        int mat = id >> 9, rem = id & 511, row = rem >> 3, seg = rem & 7;
        const bf16* src = (mat ? Ql_g : Qh_g) + row * HD_ + seg * 8;
        CP16(sb + (mat * 4608 + row * 72 + seg * 8) * 2, src);
    }
    CP_COMMIT();

    int lo_ = q0 - win + 1;
    int kt0 = lo_ > 0 ? (lo_ >> 6) : 0;
    int nkt = qt - kt0 + 1;

    const bf16* Kh_g = kah + (((long)b * KVH_ + kvh) * TT) * HD_;
    const bf16* Kl_g = kal + (((long)b * KVH_ + kvh) * TT) * HD_;
    const bf16* Vh_g = vth + ((long)b * KVH_ + kvh) * HD_ * TT;
    const bf16* Vl_g = vtl + ((long)b * KVH_ + kvh) * HD_ * TT;

    auto issue_kv = [&](int i) {
        int kt = kt0 + i, s = i & 1;
        uint32_t st = sb + (9216 + s * 18432) * 2;
        #pragma unroll
        for (int it = 0; it < 16; it++) {
            int id = tid + it * 128;
            int mat = id >> 9, rem = id & 511, row = rem >> 3, seg = rem & 7;
            const bf16* src;
            if (mat == 0)      src = Kh_g + (long)(kt * 64 + row) * HD_ + seg * 8;
            else if (mat == 1) src = Kl_g + (long)(kt * 64 + row) * HD_ + seg * 8;
            else if (mat == 2) src = Vh_g + (long)row * TT + kt * 64 + seg * 8;
            else               src = Vl_g + (long)row * TT + kt * 64 + seg * 8;
            CP16(st + (mat * 4608 + row * 72 + seg * 8) * 2, src);
        }
        CP_COMMIT();
    };

    issue_kv(0);
    if (nkt > 1) {
        issue_kv(1);
        asm volatile("cp.async.wait_group 1;\n");   // Q + kv0 complete, kv1 pending
    } else {
        asm volatile("cp.async.wait_group 0;\n");
    }
    __syncthreads();

    // Q fragments (resident for whole block)
    uint32_t qA[4][2][4];
    #pragma unroll
    for (int ks = 0; ks < 4; ks++)
        #pragma unroll
        for (int hl = 0; hl < 2; hl++) {
            uint32_t addr = sb + (hl * 4608 + (w * 16 + (lane & 15)) * 72 + ks * 16 + (lane >> 4) * 8) * 2;
            LDM4(qA[ks][hl], addr);
        }

    float oacc[8][4];
    #pragma unroll
    for (int t2 = 0; t2 < 8; t2++)
        #pragma unroll
        for (int e = 0; e < 4; e++) oacc[t2][e] = 0.f;
    float m0 = -1e30f, m1 = -1e30f, l0 = 0.f, l1 = 0.f;

    for (int i = 0; i < nkt; i++) {
        int kt = kt0 + i, s = i & 1;
        if (i > 0) {
            if (i + 1 < nkt) asm volatile("cp.async.wait_group 1;\n");
            else             asm volatile("cp.async.wait_group 0;\n");
            __syncthreads();
        }
        uint32_t stK = sb + (9216 + s * 18432) * 2;
        uint32_t stV = stK + 9216 * 2;

        // ---- S = Q K^T (3-pass hi/lo) ----
        float sacc[8][4];
        #pragma unroll
        for (int t2 = 0; t2 < 8; t2++)
            #pragma unroll
            for (int e = 0; e < 4; e++) sacc[t2][e] = 0.f;
        #pragma unroll
        for (int ks = 0; ks < 4; ks++) {
            uint32_t bK[2][4][4];
            #pragma unroll
            for (int p2 = 0; p2 < 4; p2++)
                #pragma unroll
                for (int hl = 0; hl < 2; hl++) {
                    uint32_t addr = stK + (hl * 4608 +
                        (p2 * 16 + (lane & 7) + ((lane >> 4) & 1) * 8) * 72 +
                        ks * 16 + ((lane >> 3) & 1) * 8) * 2;
                    LDM4(bK[hl][p2], addr);
                }
            #pragma unroll
            for (int p2 = 0; p2 < 4; p2++)
                #pragma unroll
                for (int t = 0; t < 2; t++) {
                    int tile = 2 * p2 + t;
                    uint32_t bh0 = bK[0][p2][t * 2], bh1 = bK[0][p2][t * 2 + 1];
                    uint32_t bl0 = bK[1][p2][t * 2], bl1 = bK[1][p2][t * 2 + 1];
                    MMA_BF16(sacc[tile], qA[ks][0], bh0, bh1);
                    MMA_BF16(sacc[tile], qA[ks][0], bl0, bl1);
                    MMA_BF16(sacc[tile], qA[ks][1], bh0, bh1);
                }
        }

        // ---- mask (diagonal + leading window-clip tile) ----
        if (kt == qt || (q0 + 63 - kt * 64) >= win) {
            #pragma unroll
            for (int tile = 0; tile < 8; tile++)
                #pragma unroll
                for (int e = 0; e < 4; e++) {
                    int rowg = q0 + w * 16 + g + (e >> 1) * 8;
                    int colg = kt * 64 + tile * 8 + cc * 2 + (e & 1);
                    int diff = rowg - colg;
                    if (diff < 0 || diff >= win) sacc[tile][e] = -1e30f;
                }
        }

        // ---- online softmax ----
        float r0 = -1e30f, r1 = -1e30f;
        #pragma unroll
        for (int tile = 0; tile < 8; tile++) {
            r0 = fmaxf(r0, fmaxf(sacc[tile][0], sacc[tile][1]));
            r1 = fmaxf(r1, fmaxf(sacc[tile][2], sacc[tile][3]));
        }
        r0 = fmaxf(r0, __shfl_xor_sync(0xffffffffu, r0, 1));
        r0 = fmaxf(r0, __shfl_xor_sync(0xffffffffu, r0, 2));
        r1 = fmaxf(r1, __shfl_xor_sync(0xffffffffu, r1, 1));
        r1 = fmaxf(r1, __shfl_xor_sync(0xffffffffu, r1, 2));
        float mn0 = fmaxf(m0, r0), mn1 = fmaxf(m1, r1);
        float f0 = __expf(m0 - mn0), f1 = __expf(m1 - mn1);
        m0 = mn0; m1 = mn1;
        float s0 = 0.f, s1 = 0.f;
        #pragma unroll
        for (int tile = 0; tile < 8; tile++) {
            sacc[tile][0] = __expf(sacc[tile][0] - mn0);
            sacc[tile][1] = __expf(sacc[tile][1] - mn0);
            sacc[tile][2] = __expf(sacc[tile][2] - mn1);
            sacc[tile][3] = __expf(sacc[tile][3] - mn1);
            s0 += sacc[tile][0] + sacc[tile][1];
            s1 += sacc[tile][2] + sacc[tile][3];
        }
        s0 += __shfl_xor_sync(0xffffffffu, s0, 1);
        s0 += __shfl_xor_sync(0xffffffffu, s0, 2);
        s1 += __shfl_xor_sync(0xffffffffu, s1, 1);
        s1 += __shfl_xor_sync(0xffffffffu, s1, 2);
        l0 = l0 * f0 + s0;
        l1 = l1 * f1 + s1;
        #pragma unroll
        for (int tile = 0; tile < 8; tile++) {
            oacc[tile][0] *= f0; oacc[tile][1] *= f0;
            oacc[tile][2] *= f1; oacc[tile][3] *= f1;
        }

        // ---- P fragments (hi/lo) ----
        uint32_t pAh[4][4], pAl[4][4];
        #pragma unroll
        for (int ks = 0; ks < 4; ks++) {
            split_pack(sacc[2*ks][0],   sacc[2*ks][1],   pAh[ks][0], pAl[ks][0]);
            split_pack(sacc[2*ks][2],   sacc[2*ks][3],   pAh[ks][1], pAl[ks][1]);
            split_pack(sacc[2*ks+1][0], sacc[2*ks+1][1], pAh[ks][2], pAl[ks][2]);
            split_pack(sacc[2*ks+1][2], sacc[2*ks+1][3], pAh[ks][3], pAl[ks][3]);
        }

        // ---- O += P V (3-pass hi/lo) ----
        #pragma unroll
        for (int ks = 0; ks < 4; ks++) {
            uint32_t bV[2][4][4];
            #pragma unroll
            for (int p2 = 0; p2 < 4; p2++)
                #pragma unroll
                for (int hl = 0; hl < 2; hl++) {
                    uint32_t addr = stV + (hl * 4608 +
                        (p2 * 16 + (lane & 7) + ((lane >> 4) & 1) * 8) * 72 +
                        ks * 16 + ((lane >> 3) & 1) * 8) * 2;
                    LDM4(bV[hl][p2], addr);
                }
            #pragma unroll
            for (int p2 = 0; p2 < 4; p2++)
                #pragma unroll
                for (int t = 0; t < 2; t++) {
                    int tile = 2 * p2 + t;
                    uint32_t vh0 = bV[0][p2][t * 2], vh1 = bV[0][p2][t * 2 + 1];
                    uint32_t vl0 = bV[1][p2][t * 2], vl1 = bV[1][p2][t * 2 + 1];
                    MMA_BF16(oacc[tile], pAh[ks], vh0, vh1);
                    MMA_BF16(oacc[tile], pAh[ks], vl0, vl1);
                    MMA_BF16(oacc[tile], pAl[ks], vh0, vh1);
                }
        }

        __syncthreads();
        if (i + 2 < nkt) issue_kv(i + 2);
    }

    float inv0 = 1.f / l0, inv1 = 1.f / l1;
    long tok0 = (long)b * TT + q0 + w * 16 + g;
    long tok1 = tok0 + 8;
    #pragma unroll
    for (int tile = 0; tile < 8; tile++) {
        int col = h * HD_ + tile * 8 + cc * 2;
        uint32_t hi0, lo0, hi1, lo1;
        split_pack(oacc[tile][0] * inv0, oacc[tile][1] * inv0, hi0, lo0);
        split_pack(oacc[tile][2] * inv1, oacc[tile][3] * inv1, hi1, lo1);
        *(uint32_t*)&yh[tok0 * DD + col] = hi0;
        *(uint32_t*)&yl[tok0 * DD + col] = lo0;
        *(uint32_t*)&yh[tok1 * DD + col] = hi1;
        *(uint32_t*)&yl[tok1 * DD + col] = lo1;
    }
}

// ---------------- bf16-split tensor-core NT GEMM (3-pass, 3-stage) ----------
template <int EPI>
__global__ __launch_bounds__(256, 1) void gemm_bb(
    const bf16* __restrict__ Ah, const bf16* __restrict__ Al,
    const bf16* __restrict__ Bh, const bf16* __restrict__ Bl,
    float* __restrict__ C, bf16* __restrict__ Ch, bf16* __restrict__ Cl,
    int M, int N, int K) {
    extern __shared__ bf16 sm[];
    const int tid = threadIdx.x;
    const int wid = tid >> 5, lane = tid & 31;
    const int wm = wid & 3, wn = wid >> 2;
    const int bm = blockIdx.y << 7, bn = blockIdx.x << 7;

    float acc[2][8][4];
    #pragma unroll
    for (int i = 0; i < 2; i++)
        #pragma unroll
        for (int j = 0; j < 8; j++)
            #pragma unroll
            for (int e = 0; e < 4; e++) acc[i][j][e] = 0.f;

    const int nc = K >> 5;

    auto issue = [&](int c, int s) {
        int k0 = c << 5;
        #pragma unroll
        for (int it = 0; it < 4; it++) {
            int t = tid + it * 256;
            int hl = t >> 9, rem = t & 511, row = rem >> 2, seg = rem & 3;
            const bf16* g = (hl ? Al : Ah) + (long)(bm + row) * K + k0 + seg * 8;
            uint32_t sa = (uint32_t)__cvta_generic_to_shared(sm + s * 20480 + hl * 5120 + row * 40 + seg * 8);
            CP16(sa, g);
        }
        #pragma unroll
        for (int it = 0; it < 4; it++) {
            int t = tid + it * 256;
            int hl = t >> 9, rem = t & 511, row = rem >> 2, seg = rem & 3;
            const bf16* g = (hl ? Bl : Bh) + (long)(bn + row) * K + k0 + seg * 8;
            uint32_t sa = (uint32_t)__cvta_generic_to_shared(sm + s * 20480 + 10240 + hl * 5120 + row * 40 + seg * 8);
            CP16(sa, g);
        }
        CP_COMMIT();
    };

    issue(0, 0);
    issue(1, 1);
    for (int c = 0; c < nc; c++) {
        int s = c % 3;
        if (c + 2 < nc) {
            issue(c + 2, (c + 2) % 3);
            asm volatile("cp.async.wait_group 2;\n");
        } else if (c + 1 < nc) {
            asm volatile("cp.async.wait_group 1;\n");
        } else {
            asm volatile("cp.async.wait_group 0;\n");
        }
        __syncthreads();

        const bf16* As = sm + s * 20480;
        const bf16* Bs = sm + s * 20480 + 10240;
        #pragma unroll
        for (int kk = 0; kk < 2; kk++) {
            uint32_t a[2][2][4];
            #pragma unroll
            for (int i = 0; i < 2; i++)
                #pragma unroll
                for (int hl = 0; hl < 2; hl++) {
                    uint32_t addr = (uint32_t)__cvta_generic_to_shared(
                        As + hl * 5120 + (wm * 32 + i * 16 + (lane & 15)) * 40 + kk * 16 + (lane >> 4) * 8);
                    LDM4(a[i][hl], addr);
                }
            uint32_t bfr[4][2][4];
            #pragma unroll
            for (int p2 = 0; p2 < 4; p2++)
                #pragma unroll
                for (int hl = 0; hl < 2; hl++) {
                    int row = wn * 64 + p2 * 16 + (lane & 7) + ((lane >> 4) & 1) * 8;
                    int col = kk * 16 + ((lane >> 3) & 1) * 8;
                    uint32_t addr = (uint32_t)__cvta_generic_to_shared(Bs + hl * 5120 + row * 40 + col);
                    LDM4(bfr[p2][hl], addr);
                }
            #pragma unroll
            for (int i = 0; i < 2; i++)
                #pragma unroll
                for (int j = 0; j < 8; j++) {
                    int p2 = j >> 1, half = j & 1;
                    uint32_t bh0 = bfr[p2][0][half * 2], bh1 = bfr[p2][0][half * 2 + 1];
                    uint32_t bl0 = bfr[p2][1][half * 2], bl1 = bfr[p2][1][half * 2 + 1];
                    MMA_BF16(acc[i][j], a[i][0], bh0, bh1);
                    MMA_BF16(acc[i][j], a[i][0], bl0, bl1);
                    MMA_BF16(acc[i][j], a[i][1], bh0, bh1);
                }
        }
        __syncthreads();
    }

    #pragma unroll
    for (int i = 0; i < 2; i++) {
        int r0 = bm + wm * 32 + i * 16 + (lane >> 2);
        #pragma unroll
        for (int j = 0; j < 8; j++) {
            int col = bn + wn * 64 + j * 8 + (lane & 3) * 2;
            #pragma unroll
            for (int e = 0; e < 4; e++) {
                int rr = r0 + (e >> 1) * 8;
                int cid = col + (e & 1);
                long id = (long)rr * N + cid;
                float val = acc[i][j][e];
                if (EPI == 0)      C[id] = val;
                else if (EPI == 1) C[id] += val;
                else if (EPI == 2) {
                    float r = fmaxf(val, 0.f); r = r * r;
                    bf16 hi = __float2bfloat16(r);
                    Ch[id] = hi;
                    Cl[id] = __float2bfloat16(r - __bfloat162float(hi));
                }
                else C[id] = 15.0f * tanhf(val * (1.0f / 15.0f));
            }
        }
    }
}

// ---------------- fp16 1-pass GEMM for lm_head (3-stage pipeline) -----------
// stage (halves): A[0,5120) B[5120,10240); stride 10240
__global__ __launch_bounds__(256, 1) void gemm_lm(
    const __half* __restrict__ Af, const __half* __restrict__ Bf,
    float* __restrict__ C, int M, int N, int K) {
    extern __shared__ __half smh[];
    const int tid = threadIdx.x;
    const int wid = tid >> 5, lane = tid & 31;
    const int wm = wid & 3, wn = wid >> 2;
    const int bm = blockIdx.y << 7, bn = blockIdx.x << 7;

    float acc[2][8][4];
    #pragma unroll
    for (int i = 0; i < 2; i++)
        #pragma unroll
        for (int j = 0; j < 8; j++)
            #pragma unroll
            for (int e = 0; e < 4; e++) acc[i][j][e] = 0.f;

    const int nc = K >> 5;

    auto issue = [&](int c, int s) {
        int k0 = c << 5;
        #pragma unroll
        for (int it = 0; it < 4; it++) {
            int t = tid + it * 256;
            int mat = t >> 9, rem = t & 511, row = rem >> 2, seg = rem & 3;
            const __half* g = (mat ? Bf + (long)(bn + row) * K : Af + (long)(bm + row) * K)
                              + k0 + seg * 8;
            uint32_t sa = (uint32_t)__cvta_generic_to_shared(
                smh + s * 10240 + mat * 5120 + row * 40 + seg * 8);
            CP16(sa, g);
        }
        CP_COMMIT();
    };

    issue(0, 0);
    issue(1, 1);
    for (int c = 0; c < nc; c++) {
        int s = c % 3;
        if (c + 2 < nc) {
            issue(c + 2, (c + 2) % 3);
            asm volatile("cp.async.wait_group 2;\n");
        } else if (c + 1 < nc) {
            asm volatile("cp.async.wait_group 1;\n");
        } else {
            asm volatile("cp.async.wait_group 0;\n");
        }
        __syncthreads();

        const __half* As = smh + s * 10240;
        const __half* Bs = smh + s * 10240 + 5120;
        #pragma unroll
        for (int kk = 0; kk < 2; kk++) {
            uint32_t a[2][4];
            #pragma unroll
            for (int i = 0; i < 2; i++) {
                uint32_t addr = (uint32_t)__cvta_generic_to_shared(
                    As + (wm * 32 + i * 16 + (lane & 15)) * 40 + kk * 16 + (lane >> 4) * 8);
                LDM4(a[i], addr);
            }
            uint32_t bfr[4][4];
            #pragma unroll
            for (int p2 = 0; p2 < 4; p2++) {
                int row = wn * 64 + p2 * 16 + (lane & 7) + ((lane >> 4) & 1) * 8;
                int col = kk * 16 + ((lane >> 3) & 1) * 8;
                uint32_t addr = (uint32_t)__cvta_generic_to_shared(Bs + row * 40 + col);
                LDM4(bfr[p2], addr);
            }
            #pragma unroll
            for (int i = 0; i < 2; i++)
                #pragma unroll
                for (int j = 0; j < 8; j++) {
                    int p2 = j >> 1, half = j & 1;
                    MMA_F16(acc[i][j], a[i], bfr[p2][half * 2], bfr[p2][half * 2 + 1]);
                }
        }
        __syncthreads();
    }

    #pragma unroll
    for (int i = 0; i < 2; i++) {
        int r0 = bm + wm * 32 + i * 16 + (lane >> 2);
        #pragma unroll
        for (int j = 0; j < 8; j++) {
            int col = bn + wn * 64 + j * 8 + (lane & 3) * 2;
            #pragma unroll
            for (int e = 0; e < 4; e++) {
                int rr = r0 + (e >> 1) * 8;
                int cid = col + (e & 1);
                C[(long)rr * N + cid] = 15.0f * tanhf(acc[i][j][e] * (1.0f / 15.0f));
            }
        }
    }
}

// ---------------- orchestration ---------------------------------------------
extern "C" void kernel_launch(void* const* d_in, const int* in_sizes, int n_in,
                              void* d_out, int out_size) {
    const int*   idx  = (const int*)  d_in[0];
    const float* wte  = (const float*)d_in[1];
    const float* Wq   = (const float*)d_in[2];
    const float* Wk   = (const float*)d_in[3];
    const float* Wv   = (const float*)d_in[4];
    const float* Wo   = (const float*)d_in[5];
    const float* Wfc  = (const float*)d_in[6];
    const float* Wpr  = (const float*)d_in[7];
    const float* veT  = (const float*)d_in[8];
    const float* veG  = (const float*)d_in[9];
    const float* rl   = (const float*)d_in[10];
    const float* xl   = (const float*)d_in[11];
    const float* lm   = (const float*)d_in[12];
    float* out = (float*)d_out;

    float *x, *x0, *qkv;
    bf16 *xnh, *xnl, *yh, *yl, *hh, *hl;
    bf16 *qa_h, *qa_l, *ka_h, *ka_l, *vt_h, *vt_l;
    __half *xnf, *lmf;
    bf16 *wqkvh, *wqkvl, *woh, *wol, *wfch, *wfcl, *wprh, *wprl;
    cudaGetSymbolAddress((void**)&x,   g_x);
    cudaGetSymbolAddress((void**)&x0,  g_x0);
    cudaGetSymbolAddress((void**)&qkv, g_qkv);
    cudaGetSymbolAddress((void**)&xnh, g_xn_h);  cudaGetSymbolAddress((void**)&xnl, g_xn_l);
    cudaGetSymbolAddress((void**)&yh,  g_y_h);   cudaGetSymbolAddress((void**)&yl,  g_y_l);
    cudaGetSymbolAddress((void**)&hh,  g_h_h);   cudaGetSymbolAddress((void**)&hl,  g_h_l);
    cudaGetSymbolAddress((void**)&qa_h, g_qah);  cudaGetSymbolAddress((void**)&qa_l, g_qal);
    cudaGetSymbolAddress((void**)&ka_h, g_kah);  cudaGetSymbolAddress((void**)&ka_l, g_kal);
    cudaGetSymbolAddress((void**)&vt_h, g_vth);  cudaGetSymbolAddress((void**)&vt_l, g_vtl);
    cudaGetSymbolAddress((void**)&xnf, g_xn_f);
    cudaGetSymbolAddress((void**)&wqkvh, g_wqkv_h); cudaGetSymbolAddress((void**)&wqkvl, g_wqkv_l);
    cudaGetSymbolAddress((void**)&woh, g_wo_h);  cudaGetSymbolAddress((void**)&wol, g_wo_l);
    cudaGetSymbolAddress((void**)&wfch, g_wfc_h); cudaGetSymbolAddress((void**)&wfcl, g_wfc_l);
    cudaGetSymbolAddress((void**)&wprh, g_wpr_h); cudaGetSymbolAddress((void**)&wprl, g_wpr_l);
    cudaGetSymbolAddress((void**)&lmf, g_lm_f);

    const int GEMM_SMEM = 3 * 20480 * 2;   // 122880 bytes, 3 stages
    cudaFuncSetAttribute(gemm_bb<0>, cudaFuncAttributeMaxDynamicSharedMemorySize, GEMM_SMEM);
    cudaFuncSetAttribute(gemm_bb<1>, cudaFuncAttributeMaxDynamicSharedMemorySize, GEMM_SMEM);
    cudaFuncSetAttribute(gemm_bb<2>, cudaFuncAttributeMaxDynamicSharedMemorySize, GEMM_SMEM);
    const int LM_SMEM = 3 * 10240 * 2;     // 61440 bytes, 3 stages
    cudaFuncSetAttribute(gemm_lm, cudaFuncAttributeMaxDynamicSharedMemorySize, LM_SMEM);
    cudaFuncSetAttribute(attn_mma, cudaFuncAttributeMaxDynamicSharedMemorySize, ATT_SMEM);

    // weight conversions (all vectorized)
    {
        long n4;
        // qkv packed: per-layer [q 768 | k 256 | v 256] rows, contiguous blocks
        n4 = (long)LL * DD * DD / 4;       // Wq
        cvt4_off_kernel<<<(int)((n4 + 255) / 256), 256>>>((const float4*)Wq,
            (__nv_bfloat162*)wqkvh, (__nv_bfloat162*)wqkvl, n4,
            (long)DD * DD / 4, (long)QKVD * DD / 4, 0);
        n4 = (long)LL * 256 * DD / 4;      // Wk
        cvt4_off_kernel<<<(int)((n4 + 255) / 256), 256>>>((const float4*)Wk,
            (__nv_bfloat162*)wqkvh, (__nv_bfloat162*)wqkvl, n4,
            (long)256 * DD / 4, (long)QKVD * DD / 4, (long)DD * DD / 4);
        cvt4_off_kernel<<<(int)((n4 + 255) / 256), 256>>>((const float4*)Wv,
            (__nv_bfloat162*)wqkvh, (__nv_bfloat162*)wqkvl, n4,
            (long)256 * DD / 4, (long)QKVD * DD / 4, (long)(DD + 256) * DD / 4);
        n4 = (long)LL * DD * DD / 4;
        cvt4_kernel<<<(int)((n4 + 255) / 256), 256>>>((const float4*)Wo,
            (__nv_bfloat162*)woh, (__nv_bfloat162*)wol, n4);
        n4 = (long)LL * FF * DD / 4;
        cvt4_kernel<<<(int)((n4 + 255) / 256), 256>>>((const float4*)Wfc,
            (__nv_bfloat162*)wfch, (__nv_bfloat162*)wfcl, n4);
        cvt4_kernel<<<(int)((n4 + 255) / 256), 256>>>((const float4*)Wpr,
            (__nv_bfloat162*)wprh, (__nv_bfloat162*)wprl, n4);
        n4 = (long)VV * DD / 4;
        cvt_half4_kernel<<<(int)((n4 + 255) / 256), 256>>>((const float4*)lm, (__half2*)lmf, n4);
    }

    embed_norm_kernel<<<BT, 256>>>(wte, idx, x, x0);

    for (int i = 0; i < LL; i++) {
        resid_norm_kernel<<<BT, 256>>>(x, x0, rl, xl, i, xnh, xnl);

        gemm_bb<0><<<dim3(QKVD / 128, BT / 128), 256, GEMM_SMEM>>>(
            xnh, xnl, wqkvh + (long)i * QKVD * DD, wqkvl + (long)i * QKVD * DD,
            qkv, nullptr, nullptr, BT, QKVD, DD);

        int j = (i == 1) ? 0 : (i == 3) ? 1 : (i == 5) ? 2 : -1;
        if (j >= 0)
            ve_kernel<<<BT, 128>>>(xnh, xnl, qkv, idx,
                                   veT + (long)j * VV * 256, veG + j * KVH_ * 32);

        ropenorm_kernel<<<BT * 16, HD_>>>(qkv, qa_h, qa_l, ka_h, ka_l);
        vcvt_kernel<<<dim3(TT / 32, 2, BB * KVH_), dim3(32, 8)>>>(qkv, vt_h, vt_l);

        int win = (i % 2 == 0) ? (TT / 2) : TT;
        attn_mma<<<dim3(TT / 64, HH, BB), 128, ATT_SMEM>>>(
            qa_h, qa_l, ka_h, ka_l, vt_h, vt_l, yh, yl, win);

        gemm_bb<1><<<dim3(DD / 128, BT / 128), 256, GEMM_SMEM>>>(
            yh, yl, woh + (long)i * DD * DD, wol + (long)i * DD * DD,
            x, nullptr, nullptr, BT, DD, DD);

        rmsnorm_kernel<<<BT, 256>>>(x, xnh, xnl);
        gemm_bb<2><<<dim3(FF / 128, BT / 128), 256, GEMM_SMEM>>>(
            xnh, xnl, wfch + (long)i * FF * DD, wfcl + (long)i * FF * DD,
            nullptr, hh, hl, BT, FF, DD);
        gemm_bb<1><<<dim3(DD / 128, BT / 128), 256, GEMM_SMEM>>>(
            hh, hl, wprh + (long)i * DD * FF, wprl + (long)i * DD * FF,
            x, nullptr, nullptr, BT, DD, FF);
    }

    rmsnorm_h_kernel<<<BT, 256>>>(x, xnf);
    gemm_lm<<<dim3(VV / 128, BT / 128), 256, LM_SMEM>>>(
        xnf, lmf, out, BT, VV, DD);
}

// round 10
// speedup vs baseline: 5.0220x; 1.2250x over previous
#include <cuda_runtime.h>
#include <cuda_bf16.h>
#include <cuda_fp16.h>
#include <stdint.h>
#include <math.h>

#define VV   32000
#define DD   768
#define HH   12
#define KVH_ 4
#define LL   6
#define TT   1024
#define HD_  64
#define BB   2
#define BT   2048
#define FF   3072
#define QKVD 1280   // 768 q + 256 k + 256 v

typedef __nv_bfloat16 bf16;

#define CP16(dst, src)    asm volatile("cp.async.cg.shared.global [%0],[%1],16;\n" :: "r"(dst), "l"(src))
#define CP_COMMIT()       asm volatile("cp.async.commit_group;\n")
#define LDM4(r, addr) \
    asm volatile("ldmatrix.sync.aligned.m8n8.x4.shared.b16 {%0,%1,%2,%3},[%4];\n" \
        : "=r"((r)[0]), "=r"((r)[1]), "=r"((r)[2]), "=r"((r)[3]) : "r"(addr))

#define MMA_BF16(d, a, b0,b1) \
  asm volatile("mma.sync.aligned.m16n8k16.row.col.f32.bf16.bf16.f32 " \
    "{%0,%1,%2,%3},{%4,%5,%6,%7},{%8,%9},{%0,%1,%2,%3};\n" \
    : "+f"((d)[0]),"+f"((d)[1]),"+f"((d)[2]),"+f"((d)[3]) \
    : "r"((a)[0]),"r"((a)[1]),"r"((a)[2]),"r"((a)[3]),"r"(b0),"r"(b1))

#define MMA_F16(d, a, b0,b1) \
  asm volatile("mma.sync.aligned.m16n8k16.row.col.f32.f16.f16.f32 " \
    "{%0,%1,%2,%3},{%4,%5,%6,%7},{%8,%9},{%0,%1,%2,%3};\n" \
    : "+f"((d)[0]),"+f"((d)[1]),"+f"((d)[2]),"+f"((d)[3]) \
    : "r"((a)[0]),"r"((a)[1]),"r"((a)[2]),"r"((a)[3]),"r"(b0),"r"(b1))

// ---------------- device-global scratch -------------------------------------
__device__ float g_x  [BT*DD];
__device__ float g_x0 [BT*DD];
__device__ float g_qkv[BT*QKVD];

__device__ __half g_xn_h[BT*DD], g_xn_l[BT*DD];
__device__ __half g_y_h [BT*DD], g_y_l [BT*DD];
__device__ __half g_h_h [BT*FF], g_h_l [BT*FF];
__device__ __half g_xn_f[BT*DD];

__device__ bf16 g_qah[BB*HH*TT*HD_],  g_qal[BB*HH*TT*HD_];
__device__ bf16 g_kah[BB*KVH_*TT*HD_], g_kal[BB*KVH_*TT*HD_];
__device__ bf16 g_vth[BB*KVH_*HD_*TT], g_vtl[BB*KVH_*HD_*TT];

__device__ __half g_wqkv_f[LL*QKVD*DD];
__device__ __half g_wo_f  [LL*DD*DD];
__device__ __half g_wfc_f [LL*FF*DD];
__device__ __half g_wpr_f [LL*DD*FF];
__device__ __half g_lm_f[(long)VV*DD];

// ---------------- fp32 -> fp16 conversion (vectorized) ----------------------
__global__ void cvt_half4_kernel(const float4* __restrict__ in, __half2* __restrict__ o2, long n4) {
    long i = (long)blockIdx.x * 256 + threadIdx.x;
    if (i >= n4) return;
    float4 v = in[i];
    __half2 a; a.x = __float2half_rn(v.x); a.y = __float2half_rn(v.y);
    __half2 b; b.x = __float2half_rn(v.z); b.y = __float2half_rn(v.w);
    o2[i * 2]     = a;
    o2[i * 2 + 1] = b;
}

// per-layer block remap: dst4 = layer*dstStride4 + dstOff4 + rem
__global__ void cvt_half4_off_kernel(const float4* __restrict__ in, __half2* __restrict__ o2,
                                     long n4, long per4, long dstStride4, long dstOff4) {
    long i = (long)blockIdx.x * 256 + threadIdx.x;
    if (i >= n4) return;
    long layer = i / per4, rem = i % per4;
    long d = layer * dstStride4 + dstOff4 + rem;
    float4 v = in[i];
    __half2 a; a.x = __float2half_rn(v.x); a.y = __float2half_rn(v.y);
    __half2 b; b.x = __float2half_rn(v.z); b.y = __float2half_rn(v.w);
    o2[d * 2]     = a;
    o2[d * 2 + 1] = b;
}

// ---------------- fused embedding + rmsnorm ---------------------------------
__global__ void embed_norm_kernel(const float* __restrict__ wte,
                                  const int* __restrict__ idx,
                                  float* __restrict__ x, float* __restrict__ x0) {
    int t = blockIdx.x;
    const float* row = wte + (long)idx[t] * DD;
    int tid = threadIdx.x;
    float v[3]; float s = 0.f;
    #pragma unroll
    for (int j = 0; j < 3; j++) { v[j] = row[tid + j * 256]; s += v[j] * v[j]; }
    __shared__ float red[256];
    red[tid] = s; __syncthreads();
    for (int o = 128; o; o >>= 1) { if (tid < o) red[tid] += red[tid + o]; __syncthreads(); }
    float inv = rsqrtf(red[0] * (1.0f / DD) + 1e-6f);
    #pragma unroll
    for (int j = 0; j < 3; j++) {
        float w = v[j] * inv;
        x[(long)t * DD + tid + j * 256]  = w;
        x0[(long)t * DD + tid + j * 256] = w;
    }
}

// ---------------- fused resid-lambda + rmsnorm (fp16 hi/lo out) -------------
__global__ void resid_norm_kernel(float* __restrict__ x, const float* __restrict__ x0,
                                  const float* __restrict__ rl, const float* __restrict__ xl,
                                  int layer, __half* __restrict__ oh, __half* __restrict__ ol) {
    int t = blockIdx.x;
    int tid = threadIdx.x;
    float a = rl[layer], b = xl[layer];
    float v[3]; float s = 0.f;
    #pragma unroll
    for (int j = 0; j < 3; j++) {
        long id = (long)t * DD + tid + j * 256;
        float xv = a * x[id] + b * x0[id];
        v[j] = xv; s += xv * xv;
    }
    __shared__ float red[256];
    red[tid] = s; __syncthreads();
    for (int o = 128; o; o >>= 1) { if (tid < o) red[tid] += red[tid + o]; __syncthreads(); }
    float inv = rsqrtf(red[0] * (1.0f / DD) + 1e-6f);
    #pragma unroll
    for (int j = 0; j < 3; j++) {
        long id = (long)t * DD + tid + j * 256;
        x[id] = v[j];
        float w = v[j] * inv;
        __half hi = __float2half_rn(w);
        oh[id] = hi;
        ol[id] = __float2half_rn(w - __half2float(hi));
    }
}

// ---------------- rmsnorm (fp16 hi/lo out) ----------------------------------
__global__ void rmsnorm_kernel(const float* __restrict__ src,
                               __half* __restrict__ oh, __half* __restrict__ ol) {
    int t = blockIdx.x;
    const float* xp = src + (long)t * DD;
    int tid = threadIdx.x;
    float v[3]; float s = 0.f;
    #pragma unroll
    for (int j = 0; j < 3; j++) { v[j] = xp[tid + j * 256]; s += v[j] * v[j]; }
    __shared__ float red[256];
    red[tid] = s; __syncthreads();
    for (int o = 128; o; o >>= 1) { if (tid < o) red[tid] += red[tid + o]; __syncthreads(); }
    float inv = rsqrtf(red[0] * (1.0f / DD) + 1e-6f);
    #pragma unroll
    for (int j = 0; j < 3; j++) {
        float w = v[j] * inv;
        long id = (long)t * DD + tid + j * 256;
        __half hi = __float2half_rn(w);
        oh[id] = hi;
        ol[id] = __float2half_rn(w - __half2float(hi));
    }
}

// ---------------- rmsnorm (single fp16 out, for lm_head) --------------------
__global__ void rmsnorm_h_kernel(const float* __restrict__ src, __half* __restrict__ oh) {
    int t = blockIdx.x;
    const float* xp = src + (long)t * DD;
    int tid = threadIdx.x;
    float v[3]; float s = 0.f;
    #pragma unroll
    for (int j = 0; j < 3; j++) { v[j] = xp[tid + j * 256]; s += v[j] * v[j]; }
    __shared__ float red[256];
    red[tid] = s; __syncthreads();
    for (int o = 128; o; o >>= 1) { if (tid < o) red[tid] += red[tid + o]; __syncthreads(); }
    float inv = rsqrtf(red[0] * (1.0f / DD) + 1e-6f);
    #pragma unroll
    for (int j = 0; j < 3; j++)
        oh[(long)t * DD + tid + j * 256] = __float2half_rn(v[j] * inv);
}

// ---------------- value-embedding gate add (v slice of qkv) ------------------
__global__ void ve_kernel(const __half* __restrict__ xnh, const __half* __restrict__ xnl,
                          float* __restrict__ qkv,
                          const int* __restrict__ idx,
                          const float* __restrict__ ve_table,
                          const float* __restrict__ ve_gate) {
    int tok  = blockIdx.x;
    int tid  = threadIdx.x;           // 128
    int warp = tid >> 5, lane = tid & 31;
    __shared__ float gates[KVH_];
    float xv = __half2float(xnh[(long)tok * DD + lane]) +
               __half2float(xnl[(long)tok * DD + lane]);
    float g = xv * ve_gate[warp * 32 + lane];
    #pragma unroll
    for (int o = 16; o; o >>= 1) g += __shfl_down_sync(0xffffffffu, g, o);
    if (lane == 0) gates[warp] = 2.0f / (1.0f + expf(-g));
    __syncthreads();
    const float* vt = ve_table + (long)idx[tok] * 256;
    float* v = qkv + (long)tok * QKVD + 1024;
    for (int i = tid; i < 256; i += 128)
        v[i] += gates[i >> 6] * vt[i];
}

// ---------------- rope + per-head rmsnorm -> bf16 hi/lo q/k -----------------
__global__ void ropenorm_kernel(const float* __restrict__ qkv,
                                bf16* __restrict__ qah, bf16* __restrict__ qal,
                                bf16* __restrict__ kah, bf16* __restrict__ kal) {
    int bid = blockIdx.x;
    int hh  = bid & 15;               // 0..11 q heads, 12..15 k heads
    int tok = bid >> 4;
    int t   = tok % TT;
    int b   = tok / TT;
    const float* ptr = qkv + (long)tok * QKVD + (hh < HH ? hh * HD_ : DD + (hh - HH) * HD_);
    int d = threadIdx.x;              // 64
    __shared__ float sv[HD_];
    __shared__ float red[HD_];
    sv[d] = ptr[d];
    __syncthreads();
    int j = d & 31;
    float invf = 1.0f / powf(10000.0f, (float)(2 * j) * (1.0f / 64.0f));
    float ang  = (float)t * invf;
    float cv = cosf(ang), sn = sinf(ang);
    float x1 = sv[j], x2 = sv[j + 32];
    float r = (d < 32) ? (x1 * cv + x2 * sn) : (x2 * cv - x1 * sn);
    red[d] = r * r; __syncthreads();
    for (int o = 32; o; o >>= 1) { if (d < o) red[d] += red[d + o]; __syncthreads(); }
    float inv = rsqrtf(red[0] * (1.0f / HD_) + 1e-6f);
    float val = r * inv;
    if (hh < HH) {
        val *= 0.125f;  // fold 1/sqrt(hd) into q
        long id = (((long)b * HH + hh) * TT + t) * HD_ + d;
        bf16 hi = __float2bfloat16(val);
        qah[id] = hi;
        qal[id] = __float2bfloat16(val - __bfloat162float(hi));
    } else {
        long id = (((long)b * KVH_ + (hh - HH)) * TT + t) * HD_ + d;
        bf16 hi = __float2bfloat16(val);
        kah[id] = hi;
        kal[id] = __float2bfloat16(val - __bfloat162float(hi));
    }
}

// ---------------- v slice: convert + transpose to [b][kvh][hd][T] -----------
__global__ void vcvt_kernel(const float* __restrict__ qkv,
                            bf16* __restrict__ vth, bf16* __restrict__ vtl) {
    __shared__ float tile[32][33];
    int t0 = blockIdx.x * 32, d0 = blockIdx.y * 32;
    int bk = blockIdx.z; int b = bk / KVH_, kv = bk % KVH_;
    int tx = threadIdx.x, ty = threadIdx.y;    // (32, 8)
    #pragma unroll
    for (int j = 0; j < 4; j++) {
        int t = t0 + ty + j * 8;
        tile[ty + j * 8][tx] = qkv[(long)(b * TT + t) * QKVD + 1024 + kv * HD_ + d0 + tx];
    }
    __syncthreads();
    #pragma unroll
    for (int j = 0; j < 4; j++) {
        int d = d0 + ty + j * 8;
        float v = tile[tx][ty + j * 8];
        bf16 hi = __float2bfloat16(v);
        long o = (((long)b * KVH_ + kv) * HD_ + d) * TT + t0 + tx;
        vth[o] = hi;
        vtl[o] = __float2bfloat16(v - __bfloat162float(hi));
    }
}

// ---------------- mma flash attention ---------------------------------------
// grid (T/64, H, B), 128 threads (4 warps, warp w = q rows w*16..+16).
// smem elems: Qh[0,4608) Ql[4608,9216); stage s @9216+s*18432: Kh,Kl,Vh,Vl each 4608 (64x72).
#define ATT_SMEM (46080 * 2)
__device__ __forceinline__ void split_pack(float a, float b, uint32_t& hi, uint32_t& lo) {
    __nv_bfloat162 h2, l2;
    h2.x = __float2bfloat16(a); h2.y = __float2bfloat16(b);
    l2.x = __float2bfloat16(a - __bfloat162float(h2.x));
    l2.y = __float2bfloat16(b - __bfloat162float(h2.y));
    hi = *(uint32_t*)&h2; lo = *(uint32_t*)&l2;
}
__device__ __forceinline__ void split_pack_h(float a, float b, uint32_t& hi, uint32_t& lo) {
    __half2 h2, l2;
    h2.x = __float2half_rn(a); h2.y = __float2half_rn(b);
    l2.x = __float2half_rn(a - __half2float(h2.x));
    l2.y = __float2half_rn(b - __half2float(h2.y));
    hi = *(uint32_t*)&h2; lo = *(uint32_t*)&l2;
}

__global__ __launch_bounds__(128) void attn_mma(
    const bf16* __restrict__ qah, const bf16* __restrict__ qal,
    const bf16* __restrict__ kah, const bf16* __restrict__ kal,
    const bf16* __restrict__ vth, const bf16* __restrict__ vtl,
    __half* __restrict__ yh, __half* __restrict__ yl, int win) {
    extern __shared__ bf16 smA[];
    const int qt = blockIdx.x, h = blockIdx.y, b = blockIdx.z;
    const int kvh = h / (HH / KVH_);
    const int tid = threadIdx.x, w = tid >> 5, lane = tid & 31;
    const int g = lane >> 2, cc = lane & 3;
    const int q0 = qt * 64;
    uint32_t sb = (uint32_t)__cvta_generic_to_shared(smA);

    const bf16* Qh_g = qah + (((long)b * HH + h) * TT + q0) * HD_;
    const bf16* Ql_g = qal + (((long)b * HH + h) * TT + q0) * HD_;
    #pragma unroll
    for (int it = 0; it < 8; it++) {
        int id = tid + it * 128;
        int mat = id >> 9, rem = id & 511, row = rem >> 3, seg = rem & 7;
        const bf16* src = (mat ? Ql_g : Qh_g) + row * HD_ + seg * 8;
        CP16(sb + (mat * 4608 + row * 72 + seg * 8) * 2, src);
    }
    CP_COMMIT();

    int lo_ = q0 - win + 1;
    int kt0 = lo_ > 0 ? (lo_ >> 6) : 0;
    int nkt = qt - kt0 + 1;

    const bf16* Kh_g = kah + (((long)b * KVH_ + kvh) * TT) * HD_;
    const bf16* Kl_g = kal + (((long)b * KVH_ + kvh) * TT) * HD_;
    const bf16* Vh_g = vth + ((long)b * KVH_ + kvh) * HD_ * TT;
    const bf16* Vl_g = vtl + ((long)b * KVH_ + kvh) * HD_ * TT;

    auto issue_kv = [&](int i) {
        int kt = kt0 + i, s = i & 1;
        uint32_t st = sb + (9216 + s * 18432) * 2;
        #pragma unroll
        for (int it = 0; it < 16; it++) {
            int id = tid + it * 128;
            int mat = id >> 9, rem = id & 511, row = rem >> 3, seg = rem & 7;
            const bf16* src;
            if (mat == 0)      src = Kh_g + (long)(kt * 64 + row) * HD_ + seg * 8;
            else if (mat == 1) src = Kl_g + (long)(kt * 64 + row) * HD_ + seg * 8;
            else if (mat == 2) src = Vh_g + (long)row * TT + kt * 64 + seg * 8;
            else               src = Vl_g + (long)row * TT + kt * 64 + seg * 8;
            CP16(st + (mat * 4608 + row * 72 + seg * 8) * 2, src);
        }
        CP_COMMIT();
    };

    issue_kv(0);
    if (nkt > 1) {
        issue_kv(1);
        asm volatile("cp.async.wait_group 1;\n");   // Q + kv0 complete, kv1 pending
    } else {
        asm volatile("cp.async.wait_group 0;\n");
    }
    __syncthreads();

    uint32_t qA[4][2][4];
    #pragma unroll
    for (int ks = 0; ks < 4; ks++)
        #pragma unroll
        for (int hl = 0; hl < 2; hl++) {
            uint32_t addr = sb + (hl * 4608 + (w * 16 + (lane & 15)) * 72 + ks * 16 + (lane >> 4) * 8) * 2;
            LDM4(qA[ks][hl], addr);
        }

    float oacc[8][4];
    #pragma unroll
    for (int t2 = 0; t2 < 8; t2++)
        #pragma unroll
        for (int e = 0; e < 4; e++) oacc[t2][e] = 0.f;
    float m0 = -1e30f, m1 = -1e30f, l0 = 0.f, l1 = 0.f;

    for (int i = 0; i < nkt; i++) {
        int kt = kt0 + i, s = i & 1;
        if (i > 0) {
            if (i + 1 < nkt) asm volatile("cp.async.wait_group 1;\n");
            else             asm volatile("cp.async.wait_group 0;\n");
            __syncthreads();
        }
        uint32_t stK = sb + (9216 + s * 18432) * 2;
        uint32_t stV = stK + 9216 * 2;

        float sacc[8][4];
        #pragma unroll
        for (int t2 = 0; t2 < 8; t2++)
            #pragma unroll
            for (int e = 0; e < 4; e++) sacc[t2][e] = 0.f;
        #pragma unroll
        for (int ks = 0; ks < 4; ks++) {
            uint32_t bK[2][4][4];
            #pragma unroll
            for (int p2 = 0; p2 < 4; p2++)
                #pragma unroll
                for (int hl = 0; hl < 2; hl++) {
                    uint32_t addr = stK + (hl * 4608 +
                        (p2 * 16 + (lane & 7) + ((lane >> 4) & 1) * 8) * 72 +
                        ks * 16 + ((lane >> 3) & 1) * 8) * 2;
                    LDM4(bK[hl][p2], addr);
                }
            #pragma unroll
            for (int p2 = 0; p2 < 4; p2++)
                #pragma unroll
                for (int t = 0; t < 2; t++) {
                    int tile = 2 * p2 + t;
                    uint32_t bh0 = bK[0][p2][t * 2], bh1 = bK[0][p2][t * 2 + 1];
                    uint32_t bl0 = bK[1][p2][t * 2], bl1 = bK[1][p2][t * 2 + 1];
                    MMA_BF16(sacc[tile], qA[ks][0], bh0, bh1);
                    MMA_BF16(sacc[tile], qA[ks][0], bl0, bl1);
                    MMA_BF16(sacc[tile], qA[ks][1], bh0, bh1);
                }
        }

        if (kt == qt || (q0 + 63 - kt * 64) >= win) {
            #pragma unroll
            for (int tile = 0; tile < 8; tile++)
                #pragma unroll
                for (int e = 0; e < 4; e++) {
                    int rowg = q0 + w * 16 + g + (e >> 1) * 8;
                    int colg = kt * 64 + tile * 8 + cc * 2 + (e & 1);
                    int diff = rowg - colg;
                    if (diff < 0 || diff >= win) sacc[tile][e] = -1e30f;
                }
        }

        float r0 = -1e30f, r1 = -1e30f;
        #pragma unroll
        for (int tile = 0; tile < 8; tile++) {
            r0 = fmaxf(r0, fmaxf(sacc[tile][0], sacc[tile][1]));
            r1 = fmaxf(r1, fmaxf(sacc[tile][2], sacc[tile][3]));
        }
        r0 = fmaxf(r0, __shfl_xor_sync(0xffffffffu, r0, 1));
        r0 = fmaxf(r0, __shfl_xor_sync(0xffffffffu, r0, 2));
        r1 = fmaxf(r1, __shfl_xor_sync(0xffffffffu, r1, 1));
        r1 = fmaxf(r1, __shfl_xor_sync(0xffffffffu, r1, 2));
        float mn0 = fmaxf(m0, r0), mn1 = fmaxf(m1, r1);
        float f0 = __expf(m0 - mn0), f1 = __expf(m1 - mn1);
        m0 = mn0; m1 = mn1;
        float s0 = 0.f, s1 = 0.f;
        #pragma unroll
        for (int tile = 0; tile < 8; tile++) {
            sacc[tile][0] = __expf(sacc[tile][0] - mn0);
            sacc[tile][1] = __expf(sacc[tile][1] - mn0);
            sacc[tile][2] = __expf(sacc[tile][2] - mn1);
            sacc[tile][3] = __expf(sacc[tile][3] - mn1);
            s0 += sacc[tile][0] + sacc[tile][1];
            s1 += sacc[tile][2] + sacc[tile][3];
        }
        s0 += __shfl_xor_sync(0xffffffffu, s0, 1);
        s0 += __shfl_xor_sync(0xffffffffu, s0, 2);
        s1 += __shfl_xor_sync(0xffffffffu, s1, 1);
        s1 += __shfl_xor_sync(0xffffffffu, s1, 2);
        l0 = l0 * f0 + s0;
        l1 = l1 * f1 + s1;
        #pragma unroll
        for (int tile = 0; tile < 8; tile++) {
            oacc[tile][0] *= f0; oacc[tile][1] *= f0;
            oacc[tile][2] *= f1; oacc[tile][3] *= f1;
        }

        uint32_t pAh[4][4], pAl[4][4];
        #pragma unroll
        for (int ks = 0; ks < 4; ks++) {
            split_pack(sacc[2*ks][0],   sacc[2*ks][1],   pAh[ks][0], pAl[ks][0]);
            split_pack(sacc[2*ks][2],   sacc[2*ks][3],   pAh[ks][1], pAl[ks][1]);
            split_pack(sacc[2*ks+1][0], sacc[2*ks+1][1], pAh[ks][2], pAl[ks][2]);
            split_pack(sacc[2*ks+1][2], sacc[2*ks+1][3], pAh[ks][3], pAl[ks][3]);
        }

        #pragma unroll
        for (int ks = 0; ks < 4; ks++) {
            uint32_t bV[2][4][4];
            #pragma unroll
            for (int p2 = 0; p2 < 4; p2++)
                #pragma unroll
                for (int hl = 0; hl < 2; hl++) {
                    uint32_t addr = stV + (hl * 4608 +
                        (p2 * 16 + (lane & 7) + ((lane >> 4) & 1) * 8) * 72 +
                        ks * 16 + ((lane >> 3) & 1) * 8) * 2;
                    LDM4(bV[hl][p2], addr);
                }
            #pragma unroll
            for (int p2 = 0; p2 < 4; p2++)
                #pragma unroll
                for (int t = 0; t < 2; t++) {
                    int tile = 2 * p2 + t;
                    uint32_t vh0 = bV[0][p2][t * 2], vh1 = bV[0][p2][t * 2 + 1];
                    uint32_t vl0 = bV[1][p2][t * 2], vl1 = bV[1][p2][t * 2 + 1];
                    MMA_BF16(oacc[tile], pAh[ks], vh0, vh1);
                    MMA_BF16(oacc[tile], pAh[ks], vl0, vl1);
                    MMA_BF16(oacc[tile], pAl[ks], vh0, vh1);
                }
        }

        __syncthreads();
        if (i + 2 < nkt) issue_kv(i + 2);
    }

    float inv0 = 1.f / l0, inv1 = 1.f / l1;
    long tok0 = (long)b * TT + q0 + w * 16 + g;
    long tok1 = tok0 + 8;
    #pragma unroll
    for (int tile = 0; tile < 8; tile++) {
        int col = h * HD_ + tile * 8 + cc * 2;
        uint32_t hi0, lo0, hi1, lo1;
        split_pack_h(oacc[tile][0] * inv0, oacc[tile][1] * inv0, hi0, lo0);
        split_pack_h(oacc[tile][2] * inv1, oacc[tile][3] * inv1, hi1, lo1);
        *(uint32_t*)&yh[tok0 * DD + col] = hi0;
        *(uint32_t*)&yl[tok0 * DD + col] = lo0;
        *(uint32_t*)&yh[tok1 * DD + col] = hi1;
        *(uint32_t*)&yl[tok1 * DD + col] = lo1;
    }
}

// ---------------- fp16 2-pass NT GEMM (A hi/lo split, B single, 3-stage) ----
// EPI: 0=store f32  1=accumulate f32  2=relu^2 -> fp16 hi/lo
// stage (halves): Ah[0,5120) Al[5120,10240) B[10240,15360); stride 15360.
template <int EPI>
__global__ __launch_bounds__(256, 1) void gemm_hf(
    const __half* __restrict__ Ah, const __half* __restrict__ Al,
    const __half* __restrict__ Bf,
    float* __restrict__ C, __half* __restrict__ Ch, __half* __restrict__ Cl,
    int M, int N, int K) {
    extern __shared__ __half smh[];
    const int tid = threadIdx.x;
    const int wid = tid >> 5, lane = tid & 31;
    const int wm = wid & 3, wn = wid >> 2;
    const int bm = blockIdx.y << 7, bn = blockIdx.x << 7;

    float acc[2][8][4];
    #pragma unroll
    for (int i = 0; i < 2; i++)
        #pragma unroll
        for (int j = 0; j < 8; j++)
            #pragma unroll
            for (int e = 0; e < 4; e++) acc[i][j][e] = 0.f;

    const int nc = K >> 5;

    auto issue = [&](int c, int s) {
        int k0 = c << 5;
        #pragma unroll
        for (int it = 0; it < 6; it++) {
            int t = tid + it * 256;
            int mat = t >> 9, rem = t & 511, row = rem >> 2, seg = rem & 3;
            const __half* g;
            if (mat == 0)      g = Ah + (long)(bm + row) * K + k0 + seg * 8;
            else if (mat == 1) g = Al + (long)(bm + row) * K + k0 + seg * 8;
            else               g = Bf + (long)(bn + row) * K + k0 + seg * 8;
            uint32_t sa = (uint32_t)__cvta_generic_to_shared(
                smh + s * 15360 + mat * 5120 + row * 40 + seg * 8);
            CP16(sa, g);
        }
        CP_COMMIT();
    };

    issue(0, 0);
    issue(1, 1);
    for (int c = 0; c < nc; c++) {
        int s = c % 3;
        if (c + 2 < nc) {
            issue(c + 2, (c + 2) % 3);
            asm volatile("cp.async.wait_group 2;\n");
        } else if (c + 1 < nc) {
            asm volatile("cp.async.wait_group 1;\n");
        } else {
            asm volatile("cp.async.wait_group 0;\n");
        }
        __syncthreads();

        const __half* As = smh + s * 15360;
        const __half* Bs = smh + s * 15360 + 10240;
        #pragma unroll
        for (int kk = 0; kk < 2; kk++) {
            uint32_t a[2][2][4];
            #pragma unroll
            for (int i = 0; i < 2; i++)
                #pragma unroll
                for (int hl = 0; hl < 2; hl++) {
                    uint32_t addr = (uint32_t)__cvta_generic_to_shared(
                        As + hl * 5120 + (wm * 32 + i * 16 + (lane & 15)) * 40 + kk * 16 + (lane >> 4) * 8);
                    LDM4(a[i][hl], addr);
                }
            uint32_t bfr[4][4];
            #pragma unroll
            for (int p2 = 0; p2 < 4; p2++) {
                int row = wn * 64 + p2 * 16 + (lane & 7) + ((lane >> 4) & 1) * 8;
                int col = kk * 16 + ((lane >> 3) & 1) * 8;
                uint32_t addr = (uint32_t)__cvta_generic_to_shared(Bs + row * 40 + col);
                LDM4(bfr[p2], addr);
            }
            #pragma unroll
            for (int i = 0; i < 2; i++)
                #pragma unroll
                for (int j = 0; j < 8; j++) {
                    int p2 = j >> 1, half = j & 1;
                    uint32_t b0 = bfr[p2][half * 2], b1 = bfr[p2][half * 2 + 1];
                    MMA_F16(acc[i][j], a[i][0], b0, b1);
                    MMA_F16(acc[i][j], a[i][1], b0, b1);
                }
        }
        __syncthreads();
    }

    #pragma unroll
    for (int i = 0; i < 2; i++) {
        int r0 = bm + wm * 32 + i * 16 + (lane >> 2);
        #pragma unroll
        for (int j = 0; j < 8; j++) {
            int col = bn + wn * 64 + j * 8 + (lane & 3) * 2;
            #pragma unroll
            for (int e = 0; e < 4; e++) {
                int rr = r0 + (e >> 1) * 8;
                int cid = col + (e & 1);
                long id = (long)rr * N + cid;
                float val = acc[i][j][e];
                if (EPI == 0)      C[id] = val;
                else if (EPI == 1) C[id] += val;
                else {
                    float r = fmaxf(val, 0.f); r = r * r;
                    __half hi = __float2half_rn(r);
                    Ch[id] = hi;
                    Cl[id] = __float2half_rn(r - __half2float(hi));
                }
            }
        }
    }
}

// ---------------- fp16 1-pass GEMM for lm_head (3-stage pipeline) -----------
// stage (halves): A[0,5120) B[5120,10240); stride 10240
__global__ __launch_bounds__(256, 1) void gemm_lm(
    const __half* __restrict__ Af, const __half* __restrict__ Bf,
    float* __restrict__ C, int M, int N, int K) {
    extern __shared__ __half smh[];
    const int tid = threadIdx.x;
    const int wid = tid >> 5, lane = tid & 31;
    const int wm = wid & 3, wn = wid >> 2;
    const int bm = blockIdx.y << 7, bn = blockIdx.x << 7;

    float acc[2][8][4];
    #pragma unroll
    for (int i = 0; i < 2; i++)
        #pragma unroll
        for (int j = 0; j < 8; j++)
            #pragma unroll
            for (int e = 0; e < 4; e++) acc[i][j][e] = 0.f;

    const int nc = K >> 5;

    auto issue = [&](int c, int s) {
        int k0 = c << 5;
        #pragma unroll
        for (int it = 0; it < 4; it++) {
            int t = tid + it * 256;
            int mat = t >> 9, rem = t & 511, row = rem >> 2, seg = rem & 3;
            const __half* g = (mat ? Bf + (long)(bn + row) * K : Af + (long)(bm + row) * K)
                              + k0 + seg * 8;
            uint32_t sa = (uint32_t)__cvta_generic_to_shared(
                smh + s * 10240 + mat * 5120 + row * 40 + seg * 8);
            CP16(sa, g);
        }
        CP_COMMIT();
    };

    issue(0, 0);
    issue(1, 1);
    for (int c = 0; c < nc; c++) {
        int s = c % 3;
        if (c + 2 < nc) {
            issue(c + 2, (c + 2) % 3);
            asm volatile("cp.async.wait_group 2;\n");
        } else if (c + 1 < nc) {
            asm volatile("cp.async.wait_group 1;\n");
        } else {
            asm volatile("cp.async.wait_group 0;\n");
        }
        __syncthreads();

        const __half* As = smh + s * 10240;
        const __half* Bs = smh + s * 10240 + 5120;
        #pragma unroll
        for (int kk = 0; kk < 2; kk++) {
            uint32_t a[2][4];
            #pragma unroll
            for (int i = 0; i < 2; i++) {
                uint32_t addr = (uint32_t)__cvta_generic_to_shared(
                    As + (wm * 32 + i * 16 + (lane & 15)) * 40 + kk * 16 + (lane >> 4) * 8);
                LDM4(a[i], addr);
            }
            uint32_t bfr[4][4];
            #pragma unroll
            for (int p2 = 0; p2 < 4; p2++) {
                int row = wn * 64 + p2 * 16 + (lane & 7) + ((lane >> 4) & 1) * 8;
                int col = kk * 16 + ((lane >> 3) & 1) * 8;
                uint32_t addr = (uint32_t)__cvta_generic_to_shared(Bs + row * 40 + col);
                LDM4(bfr[p2], addr);
            }
            #pragma unroll
            for (int i = 0; i < 2; i++)
                #pragma unroll
                for (int j = 0; j < 8; j++) {
                    int p2 = j >> 1, half = j & 1;
                    MMA_F16(acc[i][j], a[i], bfr[p2][half * 2], bfr[p2][half * 2 + 1]);
                }
        }
        __syncthreads();
    }

    #pragma unroll
    for (int i = 0; i < 2; i++) {
        int r0 = bm + wm * 32 + i * 16 + (lane >> 2);
        #pragma unroll
        for (int j = 0; j < 8; j++) {
            int col = bn + wn * 64 + j * 8 + (lane & 3) * 2;
            #pragma unroll
            for (int e = 0; e < 4; e++) {
                int rr = r0 + (e >> 1) * 8;
                int cid = col + (e & 1);
                C[(long)rr * N + cid] = 15.0f * tanhf(acc[i][j][e] * (1.0f / 15.0f));
            }
        }
    }
}

// ---------------- orchestration ---------------------------------------------
extern "C" void kernel_launch(void* const* d_in, const int* in_sizes, int n_in,
                              void* d_out, int out_size) {
    const int*   idx  = (const int*)  d_in[0];
    const float* wte  = (const float*)d_in[1];
    const float* Wq   = (const float*)d_in[2];
    const float* Wk   = (const float*)d_in[3];
    const float* Wv   = (const float*)d_in[4];
    const float* Wo   = (const float*)d_in[5];
    const float* Wfc  = (const float*)d_in[6];
    const float* Wpr  = (const float*)d_in[7];
    const float* veT  = (const float*)d_in[8];
    const float* veG  = (const float*)d_in[9];
    const float* rl   = (const float*)d_in[10];
    const float* xl   = (const float*)d_in[11];
    const float* lm   = (const float*)d_in[12];
    float* out = (float*)d_out;

    float *x, *x0, *qkv;
    __half *xnh, *xnl, *yh, *yl, *hh, *hl, *xnf;
    bf16 *qa_h, *qa_l, *ka_h, *ka_l, *vt_h, *vt_l;
    __half *wqkvf, *wof, *wfcf, *wprf, *lmf;
    cudaGetSymbolAddress((void**)&x,   g_x);
    cudaGetSymbolAddress((void**)&x0,  g_x0);
    cudaGetSymbolAddress((void**)&qkv, g_qkv);
    cudaGetSymbolAddress((void**)&xnh, g_xn_h);  cudaGetSymbolAddress((void**)&xnl, g_xn_l);
    cudaGetSymbolAddress((void**)&yh,  g_y_h);   cudaGetSymbolAddress((void**)&yl,  g_y_l);
    cudaGetSymbolAddress((void**)&hh,  g_h_h);   cudaGetSymbolAddress((void**)&hl,  g_h_l);
    cudaGetSymbolAddress((void**)&qa_h, g_qah);  cudaGetSymbolAddress((void**)&qa_l, g_qal);
    cudaGetSymbolAddress((void**)&ka_h, g_kah);  cudaGetSymbolAddress((void**)&ka_l, g_kal);
    cudaGetSymbolAddress((void**)&vt_h, g_vth);  cudaGetSymbolAddress((void**)&vt_l, g_vtl);
    cudaGetSymbolAddress((void**)&xnf, g_xn_f);
    cudaGetSymbolAddress((void**)&wqkvf, g_wqkv_f);
    cudaGetSymbolAddress((void**)&wof, g_wo_f);
    cudaGetSymbolAddress((void**)&wfcf, g_wfc_f);
    cudaGetSymbolAddress((void**)&wprf, g_wpr_f);
    cudaGetSymbolAddress((void**)&lmf, g_lm_f);

    const int GEMM_SMEM = 3 * 15360 * 2;   // 92160 bytes, 3 stages
    cudaFuncSetAttribute(gemm_hf<0>, cudaFuncAttributeMaxDynamicSharedMemorySize, GEMM_SMEM);
    cudaFuncSetAttribute(gemm_hf<1>, cudaFuncAttributeMaxDynamicSharedMemorySize, GEMM_SMEM);
    cudaFuncSetAttribute(gemm_hf<2>, cudaFuncAttributeMaxDynamicSharedMemorySize, GEMM_SMEM);
    const int LM_SMEM = 3 * 10240 * 2;     // 61440 bytes, 3 stages
    cudaFuncSetAttribute(gemm_lm, cudaFuncAttributeMaxDynamicSharedMemorySize, LM_SMEM);
    cudaFuncSetAttribute(attn_mma, cudaFuncAttributeMaxDynamicSharedMemorySize, ATT_SMEM);

    // weight conversions (all fp16 single, vectorized)
    {
        long n4;
        n4 = (long)LL * DD * DD / 4;       // Wq
        cvt_half4_off_kernel<<<(int)((n4 + 255) / 256), 256>>>((const float4*)Wq,
            (__half2*)wqkvf, n4, (long)DD * DD / 4, (long)QKVD * DD / 4, 0);
        n4 = (long)LL * 256 * DD / 4;      // Wk
        cvt_half4_off_kernel<<<(int)((n4 + 255) / 256), 256>>>((const float4*)Wk,
            (__half2*)wqkvf, n4, (long)256 * DD / 4, (long)QKVD * DD / 4, (long)DD * DD / 4);
        cvt_half4_off_kernel<<<(int)((n4 + 255) / 256), 256>>>((const float4*)Wv,
            (__half2*)wqkvf, n4, (long)256 * DD / 4, (long)QKVD * DD / 4, (long)(DD + 256) * DD / 4);
        n4 = (long)LL * DD * DD / 4;
        cvt_half4_kernel<<<(int)((n4 + 255) / 256), 256>>>((const float4*)Wo, (__half2*)wof, n4);
        n4 = (long)LL * FF * DD / 4;
        cvt_half4_kernel<<<(int)((n4 + 255) / 256), 256>>>((const float4*)Wfc, (__half2*)wfcf, n4);
        cvt_half4_kernel<<<(int)((n4 + 255) / 256), 256>>>((const float4*)Wpr, (__half2*)wprf, n4);
        n4 = (long)VV * DD / 4;
        cvt_half4_kernel<<<(int)((n4 + 255) / 256), 256>>>((const float4*)lm, (__half2*)lmf, n4);
    }

    embed_norm_kernel<<<BT, 256>>>(wte, idx, x, x0);

    for (int i = 0; i < LL; i++) {
        resid_norm_kernel<<<BT, 256>>>(x, x0, rl, xl, i, xnh, xnl);

        gemm_hf<0><<<dim3(QKVD / 128, BT / 128), 256, GEMM_SMEM>>>(
            xnh, xnl, wqkvf + (long)i * QKVD * DD,
            qkv, nullptr, nullptr, BT, QKVD, DD);

        int j = (i == 1) ? 0 : (i == 3) ? 1 : (i == 5) ? 2 : -1;
        if (j >= 0)
            ve_kernel<<<BT, 128>>>(xnh, xnl, qkv, idx,
                                   veT + (long)j * VV * 256, veG + j * KVH_ * 32);

        ropenorm_kernel<<<BT * 16, HD_>>>(qkv, qa_h, qa_l, ka_h, ka_l);
        vcvt_kernel<<<dim3(TT / 32, 2, BB * KVH_), dim3(32, 8)>>>(qkv, vt_h, vt_l);

        int win = (i % 2 == 0) ? (TT / 2) : TT;
        attn_mma<<<dim3(TT / 64, HH, BB), 128, ATT_SMEM>>>(
            qa_h, qa_l, ka_h, ka_l, vt_h, vt_l, yh, yl, win);

        gemm_hf<1><<<dim3(DD / 128, BT / 128), 256, GEMM_SMEM>>>(
            yh, yl, wof + (long)i * DD * DD,
            x, nullptr, nullptr, BT, DD, DD);

        rmsnorm_kernel<<<BT, 256>>>(x, xnh, xnl);
        gemm_hf<2><<<dim3(FF / 128, BT / 128), 256, GEMM_SMEM>>>(
            xnh, xnl, wfcf + (long)i * FF * DD,
            nullptr, hh, hl, BT, FF, DD);
        gemm_hf<1><<<dim3(DD / 128, BT / 128), 256, GEMM_SMEM>>>(
            hh, hl, wprf + (long)i * DD * FF,
            x, nullptr, nullptr, BT, DD, FF);
    }

    rmsnorm_h_kernel<<<BT, 256>>>(x, xnf);
    gemm_lm<<<dim3(VV / 128, BT / 128), 256, LM_SMEM>>>(
        xnf, lmf, out, BT, VV, DD);
}

// round 14
// speedup vs baseline: 7.9082x; 1.5747x over previous
#include <cuda_runtime.h>
#include <cuda_fp16.h>
#include <stdint.h>
#include <math.h>

#define VV   32000
#define DD   768
#define HH   12
#define KVH_ 4
#define LL   6
#define TT   1024
#define HD_  64
#define BB   2
#define BT   2048
#define FF   3072
#define QKVD 1280   // 768 q + 256 k + 256 v

#define CP16(dst, src)    asm volatile("cp.async.cg.shared.global [%0],[%1],16;\n" :: "r"(dst), "l"(src))
#define CP_COMMIT()       asm volatile("cp.async.commit_group;\n")
#define LDM4(r, addr) \
    asm volatile("ldmatrix.sync.aligned.m8n8.x4.shared.b16 {%0,%1,%2,%3},[%4];\n" \
        : "=r"((r)[0]), "=r"((r)[1]), "=r"((r)[2]), "=r"((r)[3]) : "r"(addr))

#define MMA_F16(d, a, b0,b1) \
  asm volatile("mma.sync.aligned.m16n8k16.row.col.f32.f16.f16.f32 " \
    "{%0,%1,%2,%3},{%4,%5,%6,%7},{%8,%9},{%0,%1,%2,%3};\n" \
    : "+f"((d)[0]),"+f"((d)[1]),"+f"((d)[2]),"+f"((d)[3]) \
    : "r"((a)[0]),"r"((a)[1]),"r"((a)[2]),"r"((a)[3]),"r"(b0),"r"(b1))

// ---------------- device-global scratch -------------------------------------
__device__ float g_x  [BT*DD];
__device__ float g_x0 [BT*DD];
__device__ float g_qkv[BT*QKVD];

__device__ __half g_xn[BT*DD];
__device__ __half g_y [BT*DD];
__device__ __half g_h [BT*FF];

__device__ __half g_qa[BB*HH*TT*HD_];
__device__ __half g_ka[BB*KVH_*TT*HD_];
__device__ __half g_vt[BB*KVH_*HD_*TT];

__device__ __half g_wqkv_f[LL*QKVD*DD];
__device__ __half g_wo_f  [LL*DD*DD];
__device__ __half g_wfc_f [LL*FF*DD];
__device__ __half g_wpr_f [LL*DD*FF];
__device__ __half g_lm_f[(long)VV*DD];

// ---------------- fp32 -> fp16 conversion (vectorized) ----------------------
__global__ void cvt_half4_kernel(const float4* __restrict__ in, __half2* __restrict__ o2, long n4) {
    long i = (long)blockIdx.x * 256 + threadIdx.x;
    if (i >= n4) return;
    float4 v = in[i];
    __half2 a; a.x = __float2half_rn(v.x); a.y = __float2half_rn(v.y);
    __half2 b; b.x = __float2half_rn(v.z); b.y = __float2half_rn(v.w);
    o2[i * 2]     = a;
    o2[i * 2 + 1] = b;
}

__global__ void cvt_half4_off_kernel(const float4* __restrict__ in, __half2* __restrict__ o2,
                                     long n4, long per4, long dstStride4, long dstOff4) {
    long i = (long)blockIdx.x * 256 + threadIdx.x;
    if (i >= n4) return;
    long layer = i / per4, rem = i % per4;
    long d = layer * dstStride4 + dstOff4 + rem;
    float4 v = in[i];
    __half2 a; a.x = __float2half_rn(v.x); a.y = __float2half_rn(v.y);
    __half2 b; b.x = __float2half_rn(v.z); b.y = __float2half_rn(v.w);
    o2[d * 2]     = a;
    o2[d * 2 + 1] = b;
}

// ---------------- fused embedding + rmsnorm ---------------------------------
__global__ void embed_norm_kernel(const float* __restrict__ wte,
                                  const int* __restrict__ idx,
                                  float* __restrict__ x, float* __restrict__ x0) {
    int t = blockIdx.x;
    const float* row = wte + (long)idx[t] * DD;
    int tid = threadIdx.x;
    float v[3]; float s = 0.f;
    #pragma unroll
    for (int j = 0; j < 3; j++) { v[j] = row[tid + j * 256]; s += v[j] * v[j]; }
    __shared__ float red[256];
    red[tid] = s; __syncthreads();
    for (int o = 128; o; o >>= 1) { if (tid < o) red[tid] += red[tid + o]; __syncthreads(); }
    float inv = rsqrtf(red[0] * (1.0f / DD) + 1e-6f);
    #pragma unroll
    for (int j = 0; j < 3; j++) {
        float w = v[j] * inv;
        x[(long)t * DD + tid + j * 256]  = w;
        x0[(long)t * DD + tid + j * 256] = w;
    }
}

// ---------------- fused resid-lambda + rmsnorm (fp16 out) -------------------
__global__ void resid_norm_kernel(float* __restrict__ x, const float* __restrict__ x0,
                                  const float* __restrict__ rl, const float* __restrict__ xl,
                                  int layer, __half* __restrict__ oh) {
    int t = blockIdx.x;
    int tid = threadIdx.x;
    float a = rl[layer], b = xl[layer];
    float v[3]; float s = 0.f;
    #pragma unroll
    for (int j = 0; j < 3; j++) {
        long id = (long)t * DD + tid + j * 256;
        float xv = a * x[id] + b * x0[id];
        v[j] = xv; s += xv * xv;
    }
    __shared__ float red[256];
    red[tid] = s; __syncthreads();
    for (int o = 128; o; o >>= 1) { if (tid < o) red[tid] += red[tid + o]; __syncthreads(); }
    float inv = rsqrtf(red[0] * (1.0f / DD) + 1e-6f);
    #pragma unroll
    for (int j = 0; j < 3; j++) {
        long id = (long)t * DD + tid + j * 256;
        x[id] = v[j];
        oh[id] = __float2half_rn(v[j] * inv);
    }
}

// ---------------- rmsnorm (fp16 out) ----------------------------------------
__global__ void rmsnorm_kernel(const float* __restrict__ src, __half* __restrict__ oh) {
    int t = blockIdx.x;
    const float* xp = src + (long)t * DD;
    int tid = threadIdx.x;
    float v[3]; float s = 0.f;
    #pragma unroll
    for (int j = 0; j < 3; j++) { v[j] = xp[tid + j * 256]; s += v[j] * v[j]; }
    __shared__ float red[256];
    red[tid] = s; __syncthreads();
    for (int o = 128; o; o >>= 1) { if (tid < o) red[tid] += red[tid + o]; __syncthreads(); }
    float inv = rsqrtf(red[0] * (1.0f / DD) + 1e-6f);
    #pragma unroll
    for (int j = 0; j < 3; j++)
        oh[(long)t * DD + tid + j * 256] = __float2half_rn(v[j] * inv);
}

// ---------------- value-embedding gate add (v slice of qkv) ------------------
__global__ void ve_kernel(const __half* __restrict__ xn,
                          float* __restrict__ qkv,
                          const int* __restrict__ idx,
                          const float* __restrict__ ve_table,
                          const float* __restrict__ ve_gate) {
    int tok  = blockIdx.x;
    int tid  = threadIdx.x;           // 128
    int warp = tid >> 5, lane = tid & 31;
    __shared__ float gates[KVH_];
    float xv = __half2float(xn[(long)tok * DD + lane]);
    float g = xv * ve_gate[warp * 32 + lane];
    #pragma unroll
    for (int o = 16; o; o >>= 1) g += __shfl_down_sync(0xffffffffu, g, o);
    if (lane == 0) gates[warp] = 2.0f / (1.0f + expf(-g));
    __syncthreads();
    const float* vt = ve_table + (long)idx[tok] * 256;
    float* v = qkv + (long)tok * QKVD + 1024;
    for (int i = tid; i < 256; i += 128)
        v[i] += gates[i >> 6] * vt[i];
}

// ---------------- rope + per-head rmsnorm -> fp16 q/k -----------------------
__global__ void ropenorm_kernel(const float* __restrict__ qkv,
                                __half* __restrict__ qa, __half* __restrict__ ka) {
    int bid = blockIdx.x;
    int hh  = bid & 15;               // 0..11 q heads, 12..15 k heads
    int tok = bid >> 4;
    int t   = tok % TT;
    int b   = tok / TT;
    const float* ptr = qkv + (long)tok * QKVD + (hh < HH ? hh * HD_ : DD + (hh - HH) * HD_);
    int d = threadIdx.x;              // 64
    __shared__ float sv[HD_];
    __shared__ float red[HD_];
    sv[d] = ptr[d];
    __syncthreads();
    int j = d & 31;
    float invf = 1.0f / powf(10000.0f, (float)(2 * j) * (1.0f / 64.0f));
    float ang  = (float)t * invf;
    float cv = cosf(ang), sn = sinf(ang);
    float x1 = sv[j], x2 = sv[j + 32];
    float r = (d < 32) ? (x1 * cv + x2 * sn) : (x2 * cv - x1 * sn);
    red[d] = r * r; __syncthreads();
    for (int o = 32; o; o >>= 1) { if (d < o) red[d] += red[d + o]; __syncthreads(); }
    float inv = rsqrtf(red[0] * (1.0f / HD_) + 1e-6f);
    float val = r * inv;
    if (hh < HH) {
        val *= 0.125f;  // fold 1/sqrt(hd) into q
        qa[(((long)b * HH + hh) * TT + t) * HD_ + d] = __float2half_rn(val);
    } else {
        ka[(((long)b * KVH_ + (hh - HH)) * TT + t) * HD_ + d] = __float2half_rn(val);
    }
}

// ---------------- v slice: convert + transpose to [b][kvh][hd][T] -----------
__global__ void vcvt_kernel(const float* __restrict__ qkv, __half* __restrict__ vt_) {
    __shared__ float tile[32][33];
    int t0 = blockIdx.x * 32, d0 = blockIdx.y * 32;
    int bk = blockIdx.z; int b = bk / KVH_, kv = bk % KVH_;
    int tx = threadIdx.x, ty = threadIdx.y;    // (32, 8)
    #pragma unroll
    for (int j = 0; j < 4; j++) {
        int t = t0 + ty + j * 8;
        tile[ty + j * 8][tx] = qkv[(long)(b * TT + t) * QKVD + 1024 + kv * HD_ + d0 + tx];
    }
    __syncthreads();
    #pragma unroll
    for (int j = 0; j < 4; j++) {
        int d = d0 + ty + j * 8;
        vt_[(((long)b * KVH_ + kv) * HD_ + d) * TT + t0 + tx] =
            __float2half_rn(tile[tx][ty + j * 8]);
    }
}

// ---------------- mma flash attention (fp16 1-pass) --------------------------
// grid (T/64, H, B), 128 threads (4 warps, warp w = q rows w*16..+16).
// smem (halves): Q[0,4608); stage s @4608+s*9216: K 4608, V 4608 (64x72 each).
#define ATT_SMEM ((4608 + 2 * 9216) * 2)
__device__ __forceinline__ uint32_t pack_h(float a, float b) {
    __half2 h2; h2.x = __float2half_rn(a); h2.y = __float2half_rn(b);
    return *(uint32_t*)&h2;
}

__global__ __launch_bounds__(128) void attn_mma(
    const __half* __restrict__ qa, const __half* __restrict__ ka,
    const __half* __restrict__ vt_,
    __half* __restrict__ y, int win) {
    extern __shared__ __half smA[];
    const int qt = blockIdx.x, h = blockIdx.y, b = blockIdx.z;
    const int kvh = h / (HH / KVH_);
    const int tid = threadIdx.x, w = tid >> 5, lane = tid & 31;
    const int g = lane >> 2, cc = lane & 3;
    const int q0 = qt * 64;
    uint32_t sb = (uint32_t)__cvta_generic_to_shared(smA);

    const __half* Q_g = qa + (((long)b * HH + h) * TT + q0) * HD_;
    #pragma unroll
    for (int it = 0; it < 4; it++) {
        int id = tid + it * 128;
        int row = id >> 3, seg = id & 7;
        CP16(sb + (row * 72 + seg * 8) * 2, Q_g + row * HD_ + seg * 8);
    }
    CP_COMMIT();

    int lo_ = q0 - win + 1;
    int kt0 = lo_ > 0 ? (lo_ >> 6) : 0;
    int nkt = qt - kt0 + 1;

    const __half* K_g = ka + (((long)b * KVH_ + kvh) * TT) * HD_;
    const __half* V_g = vt_ + ((long)b * KVH_ + kvh) * HD_ * TT;

    auto issue_kv = [&](int i) {
        int kt = kt0 + i, s = i & 1;
        uint32_t st = sb + (4608 + s * 9216) * 2;
        #pragma unroll
        for (int it = 0; it < 8; it++) {
            int id = tid + it * 128;
            int mat = id >> 9, rem = id & 511, row = rem >> 3, seg = rem & 7;
            const __half* src = mat ? V_g + (long)row * TT + kt * 64 + seg * 8
                                    : K_g + (long)(kt * 64 + row) * HD_ + seg * 8;
            CP16(st + (mat * 4608 + row * 72 + seg * 8) * 2, src);
        }
        CP_COMMIT();
    };

    issue_kv(0);
    if (nkt > 1) {
        issue_kv(1);
        asm volatile("cp.async.wait_group 1;\n");   // Q + kv0 complete, kv1 pending
    } else {
        asm volatile("cp.async.wait_group 0;\n");
    }
    __syncthreads();

    uint32_t qA[4][4];
    #pragma unroll
    for (int ks = 0; ks < 4; ks++) {
        uint32_t addr = sb + ((w * 16 + (lane & 15)) * 72 + ks * 16 + (lane >> 4) * 8) * 2;
        LDM4(qA[ks], addr);
    }

    float oacc[8][4];
    #pragma unroll
    for (int t2 = 0; t2 < 8; t2++)
        #pragma unroll
        for (int e = 0; e < 4; e++) oacc[t2][e] = 0.f;
    float m0 = -1e30f, m1 = -1e30f, l0 = 0.f, l1 = 0.f;

    for (int i = 0; i < nkt; i++) {
        int kt = kt0 + i, s = i & 1;
        if (i > 0) {
            if (i + 1 < nkt) asm volatile("cp.async.wait_group 1;\n");
            else             asm volatile("cp.async.wait_group 0;\n");
            __syncthreads();
        }
        uint32_t stK = sb + (4608 + s * 9216) * 2;
        uint32_t stV = stK + 4608 * 2;

        float sacc[8][4];
        #pragma unroll
        for (int t2 = 0; t2 < 8; t2++)
            #pragma unroll
            for (int e = 0; e < 4; e++) sacc[t2][e] = 0.f;
        #pragma unroll
        for (int ks = 0; ks < 4; ks++) {
            uint32_t bK[4][4];
            #pragma unroll
            for (int p2 = 0; p2 < 4; p2++) {
                uint32_t addr = stK + (
                    (p2 * 16 + (lane & 7) + ((lane >> 4) & 1) * 8) * 72 +
                    ks * 16 + ((lane >> 3) & 1) * 8) * 2;
                LDM4(bK[p2], addr);
            }
            #pragma unroll
            for (int p2 = 0; p2 < 4; p2++)
                #pragma unroll
                for (int t = 0; t < 2; t++)
                    MMA_F16(sacc[2 * p2 + t], qA[ks], bK[p2][t * 2], bK[p2][t * 2 + 1]);
        }

        if (kt == qt || (q0 + 63 - kt * 64) >= win) {
            #pragma unroll
            for (int tile = 0; tile < 8; tile++)
                #pragma unroll
                for (int e = 0; e < 4; e++) {
                    int rowg = q0 + w * 16 + g + (e >> 1) * 8;
                    int colg = kt * 64 + tile * 8 + cc * 2 + (e & 1);
                    int diff = rowg - colg;
                    if (diff < 0 || diff >= win) sacc[tile][e] = -1e30f;
                }
        }

        float r0 = -1e30f, r1 = -1e30f;
        #pragma unroll
        for (int tile = 0; tile < 8; tile++) {
            r0 = fmaxf(r0, fmaxf(sacc[tile][0], sacc[tile][1]));
            r1 = fmaxf(r1, fmaxf(sacc[tile][2], sacc[tile][3]));
        }
        r0 = fmaxf(r0, __shfl_xor_sync(0xffffffffu, r0, 1));
        r0 = fmaxf(r0, __shfl_xor_sync(0xffffffffu, r0, 2));
        r1 = fmaxf(r1, __shfl_xor_sync(0xffffffffu, r1, 1));
        r1 = fmaxf(r1, __shfl_xor_sync(0xffffffffu, r1, 2));
        float mn0 = fmaxf(m0, r0), mn1 = fmaxf(m1, r1);
        float f0 = __expf(m0 - mn0), f1 = __expf(m1 - mn1);
        m0 = mn0; m1 = mn1;
        float s0 = 0.f, s1 = 0.f;
        #pragma unroll
        for (int tile = 0; tile < 8; tile++) {
            sacc[tile][0] = __expf(sacc[tile][0] - mn0);
            sacc[tile][1] = __expf(sacc[tile][1] - mn0);
            sacc[tile][2] = __expf(sacc[tile][2] - mn1);
            sacc[tile][3] = __expf(sacc[tile][3] - mn1);
            s0 += sacc[tile][0] + sacc[tile][1];
            s1 += sacc[tile][2] + sacc[tile][3];
        }
        s0 += __shfl_xor_sync(0xffffffffu, s0, 1);
        s0 += __shfl_xor_sync(0xffffffffu, s0, 2);
        s1 += __shfl_xor_sync(0xffffffffu, s1, 1);
        s1 += __shfl_xor_sync(0xffffffffu, s1, 2);
        l0 = l0 * f0 + s0;
        l1 = l1 * f1 + s1;
        #pragma unroll
        for (int tile = 0; tile < 8; tile++) {
            oacc[tile][0] *= f0; oacc[tile][1] *= f0;
            oacc[tile][2] *= f1; oacc[tile][3] *= f1;
        }

        uint32_t pA[4][4];
        #pragma unroll
        for (int ks = 0; ks < 4; ks++) {
            pA[ks][0] = pack_h(sacc[2*ks][0],   sacc[2*ks][1]);
            pA[ks][1] = pack_h(sacc[2*ks][2],   sacc[2*ks][3]);
            pA[ks][2] = pack_h(sacc[2*ks+1][0], sacc[2*ks+1][1]);
            pA[ks][3] = pack_h(sacc[2*ks+1][2], sacc[2*ks+1][3]);
        }

        #pragma unroll
        for (int ks = 0; ks < 4; ks++) {
            uint32_t bV[4][4];
            #pragma unroll
            for (int p2 = 0; p2 < 4; p2++) {
                uint32_t addr = stV + (
                    (p2 * 16 + (lane & 7) + ((lane >> 4) & 1) * 8) * 72 +
                    ks * 16 + ((lane >> 3) & 1) * 8) * 2;
                LDM4(bV[p2], addr);
            }
            #pragma unroll
            for (int p2 = 0; p2 < 4; p2++)
                #pragma unroll
                for (int t = 0; t < 2; t++)
                    MMA_F16(oacc[2 * p2 + t], pA[ks], bV[p2][t * 2], bV[p2][t * 2 + 1]);
        }

        __syncthreads();
        if (i + 2 < nkt) issue_kv(i + 2);
    }

    float inv0 = 1.f / l0, inv1 = 1.f / l1;
    long tok0 = (long)b * TT + q0 + w * 16 + g;
    long tok1 = tok0 + 8;
    #pragma unroll
    for (int tile = 0; tile < 8; tile++) {
        int col = h * HD_ + tile * 8 + cc * 2;
        *(uint32_t*)&y[tok0 * DD + col] = pack_h(oacc[tile][0] * inv0, oacc[tile][1] * inv0);
        *(uint32_t*)&y[tok1 * DD + col] = pack_h(oacc[tile][2] * inv1, oacc[tile][3] * inv1);
    }
}

// ---------------- unified fp16 1-pass NT GEMM (3-stage) ---------------------
// EPI: 0=store f32  1=accumulate f32  2=relu^2 -> fp16  3=softcap f32
// stage (halves): A[0,5120) B[5120,10240); stride 10240
template <int EPI>
__global__ __launch_bounds__(256, 2) void gemm_hf(
    const __half* __restrict__ Af, const __half* __restrict__ Bf,
    float* __restrict__ C, __half* __restrict__ Ch,
    int M, int N, int K) {
    extern __shared__ __half smh[];
    const int tid = threadIdx.x;
    const int wid = tid >> 5, lane = tid & 31;
    const int wm = wid & 3, wn = wid >> 2;
    const int bm = blockIdx.y << 7, bn = blockIdx.x << 7;

    float acc[2][8][4];
    #pragma unroll
    for (int i = 0; i < 2; i++)
        #pragma unroll
        for (int j = 0; j < 8; j++)
            #pragma unroll
            for (int e = 0; e < 4; e++) acc[i][j][e] = 0.f;

    const int nc = K >> 5;

    auto issue = [&](int c, int s) {
        int k0 = c << 5;
        #pragma unroll
        for (int it = 0; it < 4; it++) {
            int t = tid + it * 256;
            int mat = t >> 9, rem = t & 511, row = rem >> 2, seg = rem & 3;
            const __half* g = (mat ? Bf + (long)(bn + row) * K : Af + (long)(bm + row) * K)
                              + k0 + seg * 8;
            uint32_t sa = (uint32_t)__cvta_generic_to_shared(
                smh + s * 10240 + mat * 5120 + row * 40 + seg * 8);
            CP16(sa, g);
        }
        CP_COMMIT();
    };

    issue(0, 0);
    issue(1, 1);
    for (int c = 0; c < nc; c++) {
        int s = c % 3;
        if (c + 2 < nc) {
            issue(c + 2, (c + 2) % 3);
            asm volatile("cp.async.wait_group 2;\n");
        } else if (c + 1 < nc) {
            asm volatile("cp.async.wait_group 1;\n");
        } else {
            asm volatile("cp.async.wait_group 0;\n");
        }
        __syncthreads();

        const __half* As = smh + s * 10240;
        const __half* Bs = smh + s * 10240 + 5120;
        #pragma unroll
        for (int kk = 0; kk < 2; kk++) {
            uint32_t a[2][4];
            #pragma unroll
            for (int i = 0; i < 2; i++) {
                uint32_t addr = (uint32_t)__cvta_generic_to_shared(
                    As + (wm * 32 + i * 16 + (lane & 15)) * 40 + kk * 16 + (lane >> 4) * 8);
                LDM4(a[i], addr);
            }
            uint32_t bfr[4][4];
            #pragma unroll
            for (int p2 = 0; p2 < 4; p2++) {
                int row = wn * 64 + p2 * 16 + (lane & 7) + ((lane >> 4) & 1) * 8;
                int col = kk * 16 + ((lane >> 3) & 1) * 8;
                uint32_t addr = (uint32_t)__cvta_generic_to_shared(Bs + row * 40 + col);
                LDM4(bfr[p2], addr);
            }
            #pragma unroll
            for (int i = 0; i < 2; i++)
                #pragma unroll
                for (int j = 0; j < 8; j++) {
                    int p2 = j >> 1, half = j & 1;
                    MMA_F16(acc[i][j], a[i], bfr[p2][half * 2], bfr[p2][half * 2 + 1]);
                }
        }
        __syncthreads();
    }

    #pragma unroll
    for (int i = 0; i < 2; i++) {
        int r0 = bm + wm * 32 + i * 16 + (lane >> 2);
        #pragma unroll
        for (int j = 0; j < 8; j++) {
            int col = bn + wn * 64 + j * 8 + (lane & 3) * 2;
            #pragma unroll
            for (int e = 0; e < 4; e++) {
                int rr = r0 + (e >> 1) * 8;
                int cid = col + (e & 1);
                long id = (long)rr * N + cid;
                float val = acc[i][j][e];
                if (EPI == 0)      C[id] = val;
                else if (EPI == 1) C[id] += val;
                else if (EPI == 2) {
                    float r = fmaxf(val, 0.f);
                    Ch[id] = __float2half_rn(r * r);
                }
                else C[id] = 15.0f * tanhf(val * (1.0f / 15.0f));
            }
        }
    }
}

// ---------------- orchestration ---------------------------------------------
extern "C" void kernel_launch(void* const* d_in, const int* in_sizes, int n_in,
                              void* d_out, int out_size) {
    const int*   idx  = (const int*)  d_in[0];
    const float* wte  = (const float*)d_in[1];
    const float* Wq   = (const float*)d_in[2];
    const float* Wk   = (const float*)d_in[3];
    const float* Wv   = (const float*)d_in[4];
    const float* Wo   = (const float*)d_in[5];
    const float* Wfc  = (const float*)d_in[6];
    const float* Wpr  = (const float*)d_in[7];
    const float* veT  = (const float*)d_in[8];
    const float* veG  = (const float*)d_in[9];
    const float* rl   = (const float*)d_in[10];
    const float* xl   = (const float*)d_in[11];
    const float* lm   = (const float*)d_in[12];
    float* out = (float*)d_out;

    float *x, *x0, *qkv;
    __half *xn, *y, *h, *qa, *ka, *vt;
    __half *wqkvf, *wof, *wfcf, *wprf, *lmf;
    cudaGetSymbolAddress((void**)&x,   g_x);
    cudaGetSymbolAddress((void**)&x0,  g_x0);
    cudaGetSymbolAddress((void**)&qkv, g_qkv);
    cudaGetSymbolAddress((void**)&xn,  g_xn);
    cudaGetSymbolAddress((void**)&y,   g_y);
    cudaGetSymbolAddress((void**)&h,   g_h);
    cudaGetSymbolAddress((void**)&qa,  g_qa);
    cudaGetSymbolAddress((void**)&ka,  g_ka);
    cudaGetSymbolAddress((void**)&vt,  g_vt);
    cudaGetSymbolAddress((void**)&wqkvf, g_wqkv_f);
    cudaGetSymbolAddress((void**)&wof, g_wo_f);
    cudaGetSymbolAddress((void**)&wfcf, g_wfc_f);
    cudaGetSymbolAddress((void**)&wprf, g_wpr_f);
    cudaGetSymbolAddress((void**)&lmf, g_lm_f);

    const int GEMM_SMEM = 3 * 10240 * 2;   // 61440 bytes, 3 stages
    cudaFuncSetAttribute(gemm_hf<0>, cudaFuncAttributeMaxDynamicSharedMemorySize, GEMM_SMEM);
    cudaFuncSetAttribute(gemm_hf<1>, cudaFuncAttributeMaxDynamicSharedMemorySize, GEMM_SMEM);
    cudaFuncSetAttribute(gemm_hf<2>, cudaFuncAttributeMaxDynamicSharedMemorySize, GEMM_SMEM);
    cudaFuncSetAttribute(gemm_hf<3>, cudaFuncAttributeMaxDynamicSharedMemorySize, GEMM_SMEM);
    cudaFuncSetAttribute(attn_mma, cudaFuncAttributeMaxDynamicSharedMemorySize, ATT_SMEM);

    // weight conversions
    {
        long n4;
        n4 = (long)LL * DD * DD / 4;       // Wq
        cvt_half4_off_kernel<<<(int)((n4 + 255) / 256), 256>>>((const float4*)Wq,
            (__half2*)wqkvf, n4, (long)DD * DD / 4, (long)QKVD * DD / 4, 0);
        n4 = (long)LL * 256 * DD / 4;      // Wk
        cvt_half4_off_kernel<<<(int)((n4 + 255) / 256), 256>>>((const float4*)Wk,
            (__half2*)wqkvf, n4, (long)256 * DD / 4, (long)QKVD * DD / 4, (long)DD * DD / 4);
        cvt_half4_off_kernel<<<(int)((n4 + 255) / 256), 256>>>((const float4*)Wv,
            (__half2*)wqkvf, n4, (long)256 * DD / 4, (long)QKVD * DD / 4, (long)(DD + 256) * DD / 4);
        n4 = (long)LL * DD * DD / 4;
        cvt_half4_kernel<<<(int)((n4 + 255) / 256), 256>>>((const float4*)Wo, (__half2*)wof, n4);
        n4 = (long)LL * FF * DD / 4;
        cvt_half4_kernel<<<(int)((n4 + 255) / 256), 256>>>((const float4*)Wfc, (__half2*)wfcf, n4);
        cvt_half4_kernel<<<(int)((n4 + 255) / 256), 256>>>((const float4*)Wpr, (__half2*)wprf, n4);
        n4 = (long)VV * DD / 4;
        cvt_half4_kernel<<<(int)((n4 + 255) / 256), 256>>>((const float4*)lm, (__half2*)lmf, n4);
    }

    embed_norm_kernel<<<BT, 256>>>(wte, idx, x, x0);

    for (int i = 0; i < LL; i++) {
        resid_norm_kernel<<<BT, 256>>>(x, x0, rl, xl, i, xn);

        gemm_hf<0><<<dim3(QKVD / 128, BT / 128), 256, GEMM_SMEM>>>(
            xn, wqkvf + (long)i * QKVD * DD, qkv, nullptr, BT, QKVD, DD);

        int j = (i == 1) ? 0 : (i == 3) ? 1 : (i == 5) ? 2 : -1;
        if (j >= 0)
            ve_kernel<<<BT, 128>>>(xn, qkv, idx,
                                   veT + (long)j * VV * 256, veG + j * KVH_ * 32);

        ropenorm_kernel<<<BT * 16, HD_>>>(qkv, qa, ka);
        vcvt_kernel<<<dim3(TT / 32, 2, BB * KVH_), dim3(32, 8)>>>(qkv, vt);

        int win = (i % 2 == 0) ? (TT / 2) : TT;
        attn_mma<<<dim3(TT / 64, HH, BB), 128, ATT_SMEM>>>(qa, ka, vt, y, win);

        gemm_hf<1><<<dim3(DD / 128, BT / 128), 256, GEMM_SMEM>>>(
            y, wof + (long)i * DD * DD, x, nullptr, BT, DD, DD);

        rmsnorm_kernel<<<BT, 256>>>(x, xn);
        gemm_hf<2><<<dim3(FF / 128, BT / 128), 256, GEMM_SMEM>>>(
            xn, wfcf + (long)i * FF * DD, nullptr, h, BT, FF, DD);
        gemm_hf<1><<<dim3(DD / 128, BT / 128), 256, GEMM_SMEM>>>(
            h, wprf + (long)i * DD * FF, x, nullptr, BT, DD, FF);
    }

    rmsnorm_kernel<<<BT, 256>>>(x, xn);
    gemm_hf<3><<<dim3(VV / 128, BT / 128), 256, GEMM_SMEM>>>(
        xn, lmf, out, nullptr, BT, VV, DD);
}

// round 16
// speedup vs baseline: 8.1413x; 1.0295x over previous
#include <cuda_runtime.h>
#include <cuda_fp16.h>
#include <stdint.h>
#include <math.h>

#define VV   32000
#define DD   768
#define HH   12
#define KVH_ 4
#define LL   6
#define TT   1024
#define HD_  64
#define BB   2
#define BT   2048
#define FF   3072
#define QKVD 1280   // 768 q + 256 k + 256 v

#define CP16(dst, src)    asm volatile("cp.async.cg.shared.global [%0],[%1],16;\n" :: "r"(dst), "l"(src))
#define CP_COMMIT()       asm volatile("cp.async.commit_group;\n")
#define LDM4(r, addr) \
    asm volatile("ldmatrix.sync.aligned.m8n8.x4.shared.b16 {%0,%1,%2,%3},[%4];\n" \
        : "=r"((r)[0]), "=r"((r)[1]), "=r"((r)[2]), "=r"((r)[3]) : "r"(addr))

#define MMA_F16(d, a, b0,b1) \
  asm volatile("mma.sync.aligned.m16n8k16.row.col.f32.f16.f16.f32 " \
    "{%0,%1,%2,%3},{%4,%5,%6,%7},{%8,%9},{%0,%1,%2,%3};\n" \
    : "+f"((d)[0]),"+f"((d)[1]),"+f"((d)[2]),"+f"((d)[3]) \
    : "r"((a)[0]),"r"((a)[1]),"r"((a)[2]),"r"((a)[3]),"r"(b0),"r"(b1))

// ---------------- device-global scratch -------------------------------------
__device__ float g_x  [BT*DD];
__device__ float g_x0 [BT*DD];
__device__ float g_qkv[BT*QKVD];

__device__ __half g_xn[BT*DD];
__device__ __half g_y [BT*DD];
__device__ __half g_h [BT*FF];

__device__ __half g_qa[BB*HH*TT*HD_];
__device__ __half g_ka[BB*KVH_*TT*HD_];
__device__ __half g_vt[BB*KVH_*HD_*TT];

__device__ float g_rcos[TT*32], g_rsin[TT*32];

__device__ __half g_wqkv_f[LL*QKVD*DD];
__device__ __half g_wo_f  [LL*DD*DD];
__device__ __half g_wfc_f [LL*FF*DD];
__device__ __half g_wpr_f [LL*DD*FF];
__device__ __half g_lm_f[(long)VV*DD];

// ---------------- rope tables (computed once per call) ----------------------
__global__ void rope_table_kernel(float* __restrict__ rc, float* __restrict__ rs) {
    int t = blockIdx.x, j = threadIdx.x;      // (TT, 32)
    float invf = 1.0f / powf(10000.0f, (float)(2 * j) * (1.0f / 64.0f));
    float ang = (float)t * invf;
    rc[t * 32 + j] = cosf(ang);
    rs[t * 32 + j] = sinf(ang);
}

// ---------------- fp32 -> fp16 conversion (vectorized, 8B store) ------------
__global__ void cvt_half4_kernel(const float4* __restrict__ in, uint2* __restrict__ o, long n4) {
    long i = (long)blockIdx.x * 256 + threadIdx.x;
    if (i >= n4) return;
    float4 v = in[i];
    __half2 a; a.x = __float2half_rn(v.x); a.y = __float2half_rn(v.y);
    __half2 b; b.x = __float2half_rn(v.z); b.y = __float2half_rn(v.w);
    uint2 st; st.x = *(uint32_t*)&a; st.y = *(uint32_t*)&b;
    o[i] = st;
}

__global__ void cvt_half4_off_kernel(const float4* __restrict__ in, uint2* __restrict__ o,
                                     long n4, long per4, long dstStride4, long dstOff4) {
    long i = (long)blockIdx.x * 256 + threadIdx.x;
    if (i >= n4) return;
    long layer = i / per4, rem = i % per4;
    long d = layer * dstStride4 + dstOff4 + rem;
    float4 v = in[i];
    __half2 a; a.x = __float2half_rn(v.x); a.y = __float2half_rn(v.y);
    __half2 b; b.x = __float2half_rn(v.z); b.y = __float2half_rn(v.w);
    uint2 st; st.x = *(uint32_t*)&a; st.y = *(uint32_t*)&b;
    o[d] = st;
}

// ---------------- fused embedding + rmsnorm ---------------------------------
__global__ void embed_norm_kernel(const float* __restrict__ wte,
                                  const int* __restrict__ idx,
                                  float* __restrict__ x, float* __restrict__ x0) {
    int t = blockIdx.x;
    const float* row = wte + (long)idx[t] * DD;
    int tid = threadIdx.x;
    float v[3]; float s = 0.f;
    #pragma unroll
    for (int j = 0; j < 3; j++) { v[j] = row[tid + j * 256]; s += v[j] * v[j]; }
    __shared__ float red[256];
    red[tid] = s; __syncthreads();
    for (int o = 128; o; o >>= 1) { if (tid < o) red[tid] += red[tid + o]; __syncthreads(); }
    float inv = rsqrtf(red[0] * (1.0f / DD) + 1e-6f);
    #pragma unroll
    for (int j = 0; j < 3; j++) {
        float w = v[j] * inv;
        x[(long)t * DD + tid + j * 256]  = w;
        x0[(long)t * DD + tid + j * 256] = w;
    }
}

// ---------------- fused resid-lambda + rmsnorm (fp16 out) -------------------
__global__ void resid_norm_kernel(float* __restrict__ x, const float* __restrict__ x0,
                                  const float* __restrict__ rl, const float* __restrict__ xl,
                                  int layer, __half* __restrict__ oh) {
    int t = blockIdx.x;
    int tid = threadIdx.x;
    float a = rl[layer], b = xl[layer];
    float v[3]; float s = 0.f;
    #pragma unroll
    for (int j = 0; j < 3; j++) {
        long id = (long)t * DD + tid + j * 256;
        float xv = a * x[id] + b * x0[id];
        v[j] = xv; s += xv * xv;
    }
    __shared__ float red[256];
    red[tid] = s; __syncthreads();
    for (int o = 128; o; o >>= 1) { if (tid < o) red[tid] += red[tid + o]; __syncthreads(); }
    float inv = rsqrtf(red[0] * (1.0f / DD) + 1e-6f);
    #pragma unroll
    for (int j = 0; j < 3; j++) {
        long id = (long)t * DD + tid + j * 256;
        x[id] = v[j];
        oh[id] = __float2half_rn(v[j] * inv);
    }
}

// ---------------- rmsnorm (fp16 out) ----------------------------------------
__global__ void rmsnorm_kernel(const float* __restrict__ src, __half* __restrict__ oh) {
    int t = blockIdx.x;
    const float* xp = src + (long)t * DD;
    int tid = threadIdx.x;
    float v[3]; float s = 0.f;
    #pragma unroll
    for (int j = 0; j < 3; j++) { v[j] = xp[tid + j * 256]; s += v[j] * v[j]; }
    __shared__ float red[256];
    red[tid] = s; __syncthreads();
    for (int o = 128; o; o >>= 1) { if (tid < o) red[tid] += red[tid + o]; __syncthreads(); }
    float inv = rsqrtf(red[0] * (1.0f / DD) + 1e-6f);
    #pragma unroll
    for (int j = 0; j < 3; j++)
        oh[(long)t * DD + tid + j * 256] = __float2half_rn(v[j] * inv);
}

// ---------------- value-embedding gate add (v slice of qkv) ------------------
__global__ void ve_kernel(const __half* __restrict__ xn,
                          float* __restrict__ qkv,
                          const int* __restrict__ idx,
                          const float* __restrict__ ve_table,
                          const float* __restrict__ ve_gate) {
    int tok  = blockIdx.x;
    int tid  = threadIdx.x;           // 128
    int warp = tid >> 5, lane = tid & 31;
    __shared__ float gates[KVH_];
    float xv = __half2float(xn[(long)tok * DD + lane]);
    float g = xv * ve_gate[warp * 32 + lane];
    #pragma unroll
    for (int o = 16; o; o >>= 1) g += __shfl_down_sync(0xffffffffu, g, o);
    if (lane == 0) gates[warp] = 2.0f / (1.0f + expf(-g));
    __syncthreads();
    const float* vt = ve_table + (long)idx[tok] * 256;
    float* v = qkv + (long)tok * QKVD + 1024;
    for (int i = tid; i < 256; i += 128)
        v[i] += gates[i >> 6] * vt[i];
}

// ---------------- rope + per-head rmsnorm -> fp16 q/k (table-based) ---------
// block (64, 4): 4 (tok,head) units per block
__global__ void ropenorm_kernel(const float* __restrict__ qkv,
                                const float* __restrict__ rc, const float* __restrict__ rs,
                                __half* __restrict__ qa, __half* __restrict__ ka) {
    int unit = blockIdx.x * 4 + threadIdx.y;
    int hh  = unit & 15;
    int tok = unit >> 4;
    int t   = tok % TT;
    int b   = tok / TT;
    const float* ptr = qkv + (long)tok * QKVD + (hh < HH ? hh * HD_ : DD + (hh - HH) * HD_);
    int d = threadIdx.x;              // 64
    int ty = threadIdx.y;
    __shared__ float sv[4][HD_];
    __shared__ float red[4][HD_];
    sv[ty][d] = ptr[d];
    __syncthreads();
    int j = d & 31;
    float cv = rc[t * 32 + j], sn = rs[t * 32 + j];
    float x1 = sv[ty][j], x2 = sv[ty][j + 32];
    float r = (d < 32) ? (x1 * cv + x2 * sn) : (x2 * cv - x1 * sn);
    red[ty][d] = r * r; __syncthreads();
    for (int o = 32; o; o >>= 1) { if (d < o) red[ty][d] += red[ty][d + o]; __syncthreads(); }
    float inv = rsqrtf(red[ty][0] * (1.0f / HD_) + 1e-6f);
    float val = r * inv;
    if (hh < HH) {
        val *= 0.125f;  // fold 1/sqrt(hd) into q
        qa[(((long)b * HH + hh) * TT + t) * HD_ + d] = __float2half_rn(val);
    } else {
        ka[(((long)b * KVH_ + (hh - HH)) * TT + t) * HD_ + d] = __float2half_rn(val);
    }
}

// ---------------- v slice: convert + transpose to [b][kvh][hd][T] -----------
__global__ void vcvt_kernel(const float* __restrict__ qkv, __half* __restrict__ vt_) {
    __shared__ float tile[32][33];
    int t0 = blockIdx.x * 32, d0 = blockIdx.y * 32;
    int bk = blockIdx.z; int b = bk / KVH_, kv = bk % KVH_;
    int tx = threadIdx.x, ty = threadIdx.y;    // (32, 8)
    #pragma unroll
    for (int j = 0; j < 4; j++) {
        int t = t0 + ty + j * 8;
        tile[ty + j * 8][tx] = qkv[(long)(b * TT + t) * QKVD + 1024 + kv * HD_ + d0 + tx];
    }
    __syncthreads();
    #pragma unroll
    for (int j = 0; j < 4; j++) {
        int d = d0 + ty + j * 8;
        vt_[(((long)b * KVH_ + kv) * HD_ + d) * TT + t0 + tx] =
            __float2half_rn(tile[tx][ty + j * 8]);
    }
}

// ---------------- mma flash attention (fp16 1-pass) --------------------------
#define ATT_SMEM ((4608 + 2 * 9216) * 2)
__device__ __forceinline__ uint32_t pack_h(float a, float b) {
    __half2 h2; h2.x = __float2half_rn(a); h2.y = __float2half_rn(b);
    return *(uint32_t*)&h2;
}

__global__ __launch_bounds__(128) void attn_mma(
    const __half* __restrict__ qa, const __half* __restrict__ ka,
    const __half* __restrict__ vt_,
    __half* __restrict__ y, int win) {
    extern __shared__ __half smA[];
    const int qt = blockIdx.x, h = blockIdx.y, b = blockIdx.z;
    const int kvh = h / (HH / KVH_);
    const int tid = threadIdx.x, w = tid >> 5, lane = tid & 31;
    const int g = lane >> 2, cc = lane & 3;
    const int q0 = qt * 64;
    uint32_t sb = (uint32_t)__cvta_generic_to_shared(smA);

    const __half* Q_g = qa + (((long)b * HH + h) * TT + q0) * HD_;
    #pragma unroll
    for (int it = 0; it < 4; it++) {
        int id = tid + it * 128;
        int row = id >> 3, seg = id & 7;
        CP16(sb + (row * 72 + seg * 8) * 2, Q_g + row * HD_ + seg * 8);
    }
    CP_COMMIT();

    int lo_ = q0 - win + 1;
    int kt0 = lo_ > 0 ? (lo_ >> 6) : 0;
    int nkt = qt - kt0 + 1;

    const __half* K_g = ka + (((long)b * KVH_ + kvh) * TT) * HD_;
    const __half* V_g = vt_ + ((long)b * KVH_ + kvh) * HD_ * TT;

    auto issue_kv = [&](int i) {
        int kt = kt0 + i, s = i & 1;
        uint32_t st = sb + (4608 + s * 9216) * 2;
        #pragma unroll
        for (int it = 0; it < 8; it++) {
            int id = tid + it * 128;
            int mat = id >> 9, rem = id & 511, row = rem >> 3, seg = rem & 7;
            const __half* src = mat ? V_g + (long)row * TT + kt * 64 + seg * 8
                                    : K_g + (long)(kt * 64 + row) * HD_ + seg * 8;
            CP16(st + (mat * 4608 + row * 72 + seg * 8) * 2, src);
        }
        CP_COMMIT();
    };

    issue_kv(0);
    if (nkt > 1) {
        issue_kv(1);
        asm volatile("cp.async.wait_group 1;\n");   // Q + kv0 complete, kv1 pending
    } else {
        asm volatile("cp.async.wait_group 0;\n");
    }
    __syncthreads();

    uint32_t qA[4][4];
    #pragma unroll
    for (int ks = 0; ks < 4; ks++) {
        uint32_t addr = sb + ((w * 16 + (lane & 15)) * 72 + ks * 16 + (lane >> 4) * 8) * 2;
        LDM4(qA[ks], addr);
    }

    float oacc[8][4];
    #pragma unroll
    for (int t2 = 0; t2 < 8; t2++)
        #pragma unroll
        for (int e = 0; e < 4; e++) oacc[t2][e] = 0.f;
    float m0 = -1e30f, m1 = -1e30f, l0 = 0.f, l1 = 0.f;

    for (int i = 0; i < nkt; i++) {
        int kt = kt0 + i, s = i & 1;
        if (i > 0) {
            if (i + 1 < nkt) asm volatile("cp.async.wait_group 1;\n");
            else             asm volatile("cp.async.wait_group 0;\n");
            __syncthreads();
        }
        uint32_t stK = sb + (4608 + s * 9216) * 2;
        uint32_t stV = stK + 4608 * 2;

        float sacc[8][4];
        #pragma unroll
        for (int t2 = 0; t2 < 8; t2++)
            #pragma unroll
            for (int e = 0; e < 4; e++) sacc[t2][e] = 0.f;
        #pragma unroll
        for (int ks = 0; ks < 4; ks++) {
            uint32_t bK[4][4];
            #pragma unroll
            for (int p2 = 0; p2 < 4; p2++) {
                uint32_t addr = stK + (
                    (p2 * 16 + (lane & 7) + ((lane >> 4) & 1) * 8) * 72 +
                    ks * 16 + ((lane >> 3) & 1) * 8) * 2;
                LDM4(bK[p2], addr);
            }
            #pragma unroll
            for (int p2 = 0; p2 < 4; p2++)
                #pragma unroll
                for (int t = 0; t < 2; t++)
                    MMA_F16(sacc[2 * p2 + t], qA[ks], bK[p2][t * 2], bK[p2][t * 2 + 1]);
        }

        if (kt == qt || (q0 + 63 - kt * 64) >= win) {
            #pragma unroll
            for (int tile = 0; tile < 8; tile++)
                #pragma unroll
                for (int e = 0; e < 4; e++) {
                    int rowg = q0 + w * 16 + g + (e >> 1) * 8;
                    int colg = kt * 64 + tile * 8 + cc * 2 + (e & 1);
                    int diff = rowg - colg;
                    if (diff < 0 || diff >= win) sacc[tile][e] = -1e30f;
                }
        }

        float r0 = -1e30f, r1 = -1e30f;
        #pragma unroll
        for (int tile = 0; tile < 8; tile++) {
            r0 = fmaxf(r0, fmaxf(sacc[tile][0], sacc[tile][1]));
            r1 = fmaxf(r1, fmaxf(sacc[tile][2], sacc[tile][3]));
        }
        r0 = fmaxf(r0, __shfl_xor_sync(0xffffffffu, r0, 1));
        r0 = fmaxf(r0, __shfl_xor_sync(0xffffffffu, r0, 2));
        r1 = fmaxf(r1, __shfl_xor_sync(0xffffffffu, r1, 1));
        r1 = fmaxf(r1, __shfl_xor_sync(0xffffffffu, r1, 2));
        float mn0 = fmaxf(m0, r0), mn1 = fmaxf(m1, r1);
        float f0 = __expf(m0 - mn0), f1 = __expf(m1 - mn1);
        m0 = mn0; m1 = mn1;
        float s0 = 0.f, s1 = 0.f;
        #pragma unroll
        for (int tile = 0; tile < 8; tile++) {
            sacc[tile][0] = __expf(sacc[tile][0] - mn0);
            sacc[tile][1] = __expf(sacc[tile][1] - mn0);
            sacc[tile][2] = __expf(sacc[tile][2] - mn1);
            sacc[tile][3] = __expf(sacc[tile][3] - mn1);
            s0 += sacc[tile][0] + sacc[tile][1];
            s1 += sacc[tile][2] + sacc[tile][3];
        }
        s0 += __shfl_xor_sync(0xffffffffu, s0, 1);
        s0 += __shfl_xor_sync(0xffffffffu, s0, 2);
        s1 += __shfl_xor_sync(0xffffffffu, s1, 1);
        s1 += __shfl_xor_sync(0xffffffffu, s1, 2);
        l0 = l0 * f0 + s0;
        l1 = l1 * f1 + s1;
        #pragma unroll
        for (int tile = 0; tile < 8; tile++) {
            oacc[tile][0] *= f0; oacc[tile][1] *= f0;
            oacc[tile][2] *= f1; oacc[tile][3] *= f1;
        }

        uint32_t pA[4][4];
        #pragma unroll
        for (int ks = 0; ks < 4; ks++) {
            pA[ks][0] = pack_h(sacc[2*ks][0],   sacc[2*ks][1]);
            pA[ks][1] = pack_h(sacc[2*ks][2],   sacc[2*ks][3]);
            pA[ks][2] = pack_h(sacc[2*ks+1][0], sacc[2*ks+1][1]);
            pA[ks][3] = pack_h(sacc[2*ks+1][2], sacc[2*ks+1][3]);
        }

        #pragma unroll
        for (int ks = 0; ks < 4; ks++) {
            uint32_t bV[4][4];
            #pragma unroll
            for (int p2 = 0; p2 < 4; p2++) {
                uint32_t addr = stV + (
                    (p2 * 16 + (lane & 7) + ((lane >> 4) & 1) * 8) * 72 +
                    ks * 16 + ((lane >> 3) & 1) * 8) * 2;
                LDM4(bV[p2], addr);
            }
            #pragma unroll
            for (int p2 = 0; p2 < 4; p2++)
                #pragma unroll
                for (int t = 0; t < 2; t++)
                    MMA_F16(oacc[2 * p2 + t], pA[ks], bV[p2][t * 2], bV[p2][t * 2 + 1]);
        }

        __syncthreads();
        if (i + 2 < nkt) issue_kv(i + 2);
    }

    float inv0 = 1.f / l0, inv1 = 1.f / l1;
    long tok0 = (long)b * TT + q0 + w * 16 + g;
    long tok1 = tok0 + 8;
    #pragma unroll
    for (int tile = 0; tile < 8; tile++) {
        int col = h * HD_ + tile * 8 + cc * 2;
        *(uint32_t*)&y[tok0 * DD + col] = pack_h(oacc[tile][0] * inv0, oacc[tile][1] * inv0);
        *(uint32_t*)&y[tok1 * DD + col] = pack_h(oacc[tile][2] * inv1, oacc[tile][3] * inv1);
    }
}

// ---------------- unified fp16 1-pass NT GEMM (3-stage, tiled BN) -----------
// EPI: 0=store f32  1=accumulate f32  2=relu^2 -> fp16  3=softcap f32
// BNT: 8-col tiles per warp-n group (8 -> BN=128, 4 -> BN=64)
// stage (halves): A[0,5120) B[5120,5120+BN*40)
template <int EPI, int BNT>
__global__ __launch_bounds__(256, 2) void gemm_hf(
    const __half* __restrict__ Af, const __half* __restrict__ Bf,
    float* __restrict__ C, __half* __restrict__ Ch,
    int M, int N, int K) {
    constexpr int BN = BNT * 16;
    constexpr int STAGE = 5120 + BN * 40;
    constexpr int NLOAD = (128 + BN) * 4 / 256;   // 16B loads per thread per chunk
    extern __shared__ __half smh[];
    const int tid = threadIdx.x;
    const int wid = tid >> 5, lane = tid & 31;
    const int wm = wid & 3, wn = wid >> 2;
    const int bm = blockIdx.y << 7, bn = blockIdx.x * BN;

    float acc[2][BNT][4];
    #pragma unroll
    for (int i = 0; i < 2; i++)
        #pragma unroll
        for (int j = 0; j < BNT; j++)
            #pragma unroll
            for (int e = 0; e < 4; e++) acc[i][j][e] = 0.f;

    const int nc = K >> 5;

    auto issue = [&](int c, int s) {
        int k0 = c << 5;
        #pragma unroll
        for (int it = 0; it < NLOAD; it++) {
            int t = tid + it * 256;
            const __half* g;
            uint32_t sa;
            if (t < 512) {
                int row = t >> 2, seg = t & 3;
                g = Af + (long)(bm + row) * K + k0 + seg * 8;
                sa = (uint32_t)__cvta_generic_to_shared(smh + s * STAGE + row * 40 + seg * 8);
            } else {
                int t2 = t - 512;
                int row = t2 >> 2, seg = t2 & 3;
                g = Bf + (long)(bn + row) * K + k0 + seg * 8;
                sa = (uint32_t)__cvta_generic_to_shared(smh + s * STAGE + 5120 + row * 40 + seg * 8);
            }
            CP16(sa, g);
        }
        CP_COMMIT();
    };

    issue(0, 0);
    issue(1, 1);
    for (int c = 0; c < nc; c++) {
        int s = c % 3;
        if (c + 2 < nc) {
            issue(c + 2, (c + 2) % 3);
            asm volatile("cp.async.wait_group 2;\n");
        } else if (c + 1 < nc) {
            asm volatile("cp.async.wait_group 1;\n");
        } else {
            asm volatile("cp.async.wait_group 0;\n");
        }
        __syncthreads();

        const __half* As = smh + s * STAGE;
        const __half* Bs = smh + s * STAGE + 5120;
        #pragma unroll
        for (int kk = 0; kk < 2; kk++) {
            uint32_t a[2][4];
            #pragma unroll
            for (int i = 0; i < 2; i++) {
                uint32_t addr = (uint32_t)__cvta_generic_to_shared(
                    As + (wm * 32 + i * 16 + (lane & 15)) * 40 + kk * 16 + (lane >> 4) * 8);
                LDM4(a[i], addr);
            }
            uint32_t bfr[BNT / 2][4];
            #pragma unroll
            for (int p2 = 0; p2 < BNT / 2; p2++) {
                int row = wn * (BNT * 8) + p2 * 16 + (lane & 7) + ((lane >> 4) & 1) * 8;
                int col = kk * 16 + ((lane >> 3) & 1) * 8;
                uint32_t addr = (uint32_t)__cvta_generic_to_shared(Bs + row * 40 + col);
                LDM4(bfr[p2], addr);
            }
            #pragma unroll
            for (int i = 0; i < 2; i++)
                #pragma unroll
                for (int j = 0; j < BNT; j++) {
                    int p2 = j >> 1, half = j & 1;
                    MMA_F16(acc[i][j], a[i], bfr[p2][half * 2], bfr[p2][half * 2 + 1]);
                }
        }
        __syncthreads();
    }

    #pragma unroll
    for (int i = 0; i < 2; i++) {
        int r0 = bm + wm * 32 + i * 16 + (lane >> 2);
        #pragma unroll
        for (int j = 0; j < BNT; j++) {
            int col = bn + wn * (BNT * 8) + j * 8 + (lane & 3) * 2;
            #pragma unroll
            for (int e = 0; e < 4; e++) {
                int rr = r0 + (e >> 1) * 8;
                int cid = col + (e & 1);
                long id = (long)rr * N + cid;
                float val = acc[i][j][e];
                if (EPI == 0)      C[id] = val;
                else if (EPI == 1) C[id] += val;
                else if (EPI == 2) {
                    float r = fmaxf(val, 0.f);
                    Ch[id] = __float2half_rn(r * r);
                }
                else C[id] = 15.0f * tanhf(val * (1.0f / 15.0f));
            }
        }
    }
}

// ---------------- orchestration ---------------------------------------------
extern "C" void kernel_launch(void* const* d_in, const int* in_sizes, int n_in,
                              void* d_out, int out_size) {
    const int*   idx  = (const int*)  d_in[0];
    const float* wte  = (const float*)d_in[1];
    const float* Wq   = (const float*)d_in[2];
    const float* Wk   = (const float*)d_in[3];
    const float* Wv   = (const float*)d_in[4];
    const float* Wo   = (const float*)d_in[5];
    const float* Wfc  = (const float*)d_in[6];
    const float* Wpr  = (const float*)d_in[7];
    const float* veT  = (const float*)d_in[8];
    const float* veG  = (const float*)d_in[9];
    const float* rl   = (const float*)d_in[10];
    const float* xl   = (const float*)d_in[11];
    const float* lm   = (const float*)d_in[12];
    float* out = (float*)d_out;

    float *x, *x0, *qkv, *rc, *rs;
    __half *xn, *y, *h, *qa, *ka, *vt;
    __half *wqkvf, *wof, *wfcf, *wprf, *lmf;
    cudaGetSymbolAddress((void**)&x,   g_x);
    cudaGetSymbolAddress((void**)&x0,  g_x0);
    cudaGetSymbolAddress((void**)&qkv, g_qkv);
    cudaGetSymbolAddress((void**)&xn,  g_xn);
    cudaGetSymbolAddress((void**)&y,   g_y);
    cudaGetSymbolAddress((void**)&h,   g_h);
    cudaGetSymbolAddress((void**)&qa,  g_qa);
    cudaGetSymbolAddress((void**)&ka,  g_ka);
    cudaGetSymbolAddress((void**)&vt,  g_vt);
    cudaGetSymbolAddress((void**)&rc,  g_rcos);
    cudaGetSymbolAddress((void**)&rs,  g_rsin);
    cudaGetSymbolAddress((void**)&wqkvf, g_wqkv_f);
    cudaGetSymbolAddress((void**)&wof, g_wo_f);
    cudaGetSymbolAddress((void**)&wfcf, g_wfc_f);
    cudaGetSymbolAddress((void**)&wprf, g_wpr_f);
    cudaGetSymbolAddress((void**)&lmf, g_lm_f);

    const int SMEM64  = 3 * (5120 + 64 * 40) * 2;    // 46080 bytes
    const int SMEM128 = 3 * (5120 + 128 * 40) * 2;   // 61440 bytes
    cudaFuncSetAttribute((const void*)gemm_hf<0,4>, cudaFuncAttributeMaxDynamicSharedMemorySize, SMEM64);
    cudaFuncSetAttribute((const void*)gemm_hf<1,4>, cudaFuncAttributeMaxDynamicSharedMemorySize, SMEM64);
    cudaFuncSetAttribute((const void*)gemm_hf<2,8>, cudaFuncAttributeMaxDynamicSharedMemorySize, SMEM128);
    cudaFuncSetAttribute((const void*)gemm_hf<3,8>, cudaFuncAttributeMaxDynamicSharedMemorySize, SMEM128);
    cudaFuncSetAttribute(attn_mma, cudaFuncAttributeMaxDynamicSharedMemorySize, ATT_SMEM);

    // rope tables + weight conversions
    rope_table_kernel<<<TT, 32>>>(rc, rs);
    {
        long n4;
        n4 = (long)LL * DD * DD / 4;       // Wq
        cvt_half4_off_kernel<<<(int)((n4 + 255) / 256), 256>>>((const float4*)Wq,
            (uint2*)wqkvf, n4, (long)DD * DD / 4, (long)QKVD * DD / 4, 0);
        n4 = (long)LL * 256 * DD / 4;      // Wk
        cvt_half4_off_kernel<<<(int)((n4 + 255) / 256), 256>>>((const float4*)Wk,
            (uint2*)wqkvf, n4, (long)256 * DD / 4, (long)QKVD * DD / 4, (long)DD * DD / 4);
        cvt_half4_off_kernel<<<(int)((n4 + 255) / 256), 256>>>((const float4*)Wv,
            (uint2*)wqkvf, n4, (long)256 * DD / 4, (long)QKVD * DD / 4, (long)(DD + 256) * DD / 4);
        n4 = (long)LL * DD * DD / 4;
        cvt_half4_kernel<<<(int)((n4 + 255) / 256), 256>>>((const float4*)Wo, (uint2*)wof, n4);
        n4 = (long)LL * FF * DD / 4;
        cvt_half4_kernel<<<(int)((n4 + 255) / 256), 256>>>((const float4*)Wfc, (uint2*)wfcf, n4);
        cvt_half4_kernel<<<(int)((n4 + 255) / 256), 256>>>((const float4*)Wpr, (uint2*)wprf, n4);
        n4 = (long)VV * DD / 4;
        cvt_half4_kernel<<<(int)((n4 + 255) / 256), 256>>>((const float4*)lm, (uint2*)lmf, n4);
    }

    embed_norm_kernel<<<BT, 256>>>(wte, idx, x, x0);

    for (int i = 0; i < LL; i++) {
        resid_norm_kernel<<<BT, 256>>>(x, x0, rl, xl, i, xn);

        gemm_hf<0,4><<<dim3(QKVD / 64, BT / 128), 256, SMEM64>>>(
            xn, wqkvf + (long)i * QKVD * DD, qkv, nullptr, BT, QKVD, DD);

        int j = (i == 1) ? 0 : (i == 3) ? 1 : (i == 5) ? 2 : -1;
        if (j >= 0)
            ve_kernel<<<BT, 128>>>(xn, qkv, idx,
                                   veT + (long)j * VV * 256, veG + j * KVH_ * 32);

        ropenorm_kernel<<<BT * 16 / 4, dim3(64, 4)>>>(qkv, rc, rs, qa, ka);
        vcvt_kernel<<<dim3(TT / 32, 2, BB * KVH_), dim3(32, 8)>>>(qkv, vt);

        int win = (i % 2 == 0) ? (TT / 2) : TT;
        attn_mma<<<dim3(TT / 64, HH, BB), 128, ATT_SMEM>>>(qa, ka, vt, y, win);

        gemm_hf<1,4><<<dim3(DD / 64, BT / 128), 256, SMEM64>>>(
            y, wof + (long)i * DD * DD, x, nullptr, BT, DD, DD);

        rmsnorm_kernel<<<BT, 256>>>(x, xn);
        gemm_hf<2,8><<<dim3(FF / 128, BT / 128), 256, SMEM128>>>(
            xn, wfcf + (long)i * FF * DD, nullptr, h, BT, FF, DD);
        gemm_hf<1,4><<<dim3(DD / 64, BT / 128), 256, SMEM64>>>(
            h, wprf + (long)i * DD * FF, x, nullptr, BT, DD, FF);
    }

    rmsnorm_kernel<<<BT, 256>>>(x, xn);
    gemm_hf<3,8><<<dim3(VV / 128, BT / 128), 256, SMEM128>>>(
        xn, lmf, out, nullptr, BT, VV, DD);
}